// round 1
// baseline (speedup 1.0000x reference)
#include <cuda_runtime.h>
#include <math.h>

#define NT 4096
#define CD 1024
#define NH 16
#define DH 64

// Scratch (allocation-free rule: __device__ globals)
__device__ float g_qkv[NT * 3 * CD];   // 48 MB: qkv activations
__device__ float g_h[NT * CD];         // 16 MB: attention output

// ---------------------------------------------------------------------------
// GEMM: C[M,Nc] = A[M,K] @ B[Nc,K]^T + bias[Nc]
// 64x64 block tile, BK=64, 256 threads, 4x4 micro-tile per thread.
// A kept natural in smem (scalar broadcast reads), B transposed (float4 reads).
// ---------------------------------------------------------------------------
__global__ __launch_bounds__(256)
void gemm_bt_kernel(const float* __restrict__ A, const float* __restrict__ B,
                    const float* __restrict__ bias, float* __restrict__ Cout,
                    int M, int Nc, int K)
{
    __shared__ float As[64][68];   // [row][k]  (stride 68: float4-aligned, low conflict)
    __shared__ float Bt[64][68];   // [k][col]

    const int tid = threadIdx.x;
    const int tx = tid & 15, ty = tid >> 4;
    const int n0 = blockIdx.x * 64, m0 = blockIdx.y * 64;

    float acc[4][4] = {};

    for (int kt = 0; kt < K; kt += 64) {
        #pragma unroll
        for (int p = 0; p < 4; p++) {
            int idx = tid + p * 256;          // 0..1023
            int row = idx >> 4, c4 = idx & 15;
            float4 av = *(const float4*)&A[(m0 + row) * K + kt + c4 * 4];
            *(float4*)&As[row][c4 * 4] = av;
            float4 bv = *(const float4*)&B[(n0 + row) * K + kt + c4 * 4];
            Bt[c4 * 4 + 0][row] = bv.x;
            Bt[c4 * 4 + 1][row] = bv.y;
            Bt[c4 * 4 + 2][row] = bv.z;
            Bt[c4 * 4 + 3][row] = bv.w;
        }
        __syncthreads();

        #pragma unroll 8
        for (int kk = 0; kk < 64; kk++) {
            float4 b = *(const float4*)&Bt[kk][tx * 4];
            float a[4];
            #pragma unroll
            for (int i = 0; i < 4; i++) a[i] = As[ty * 4 + i][kk];
            #pragma unroll
            for (int i = 0; i < 4; i++) {
                acc[i][0] += a[i] * b.x;
                acc[i][1] += a[i] * b.y;
                acc[i][2] += a[i] * b.z;
                acc[i][3] += a[i] * b.w;
            }
        }
        __syncthreads();
    }

    #pragma unroll
    for (int i = 0; i < 4; i++) {
        #pragma unroll
        for (int j = 0; j < 4; j++) {
            int cc = n0 + tx * 4 + j;
            Cout[(m0 + ty * 4 + i) * Nc + cc] = acc[i][j] + bias[cc];
        }
    }
}

// ---------------------------------------------------------------------------
// Per-head RMS norm of q and k, in place on g_qkv.
// One warp per (token, head, q|k) row of 64 elements.
// out = t / max(||t||2, 1e-12) * gamma * sqrt(D)
// ---------------------------------------------------------------------------
__global__ __launch_bounds__(256)
void rmsnorm_kernel(float* __restrict__ qkv,
                    const float* __restrict__ qg,
                    const float* __restrict__ kg)
{
    int w = (blockIdx.x * blockDim.x + threadIdx.x) >> 5;   // warp id, 0..131071
    int lane = threadIdx.x & 31;
    int n = w >> 5;          // token
    int rem = w & 31;
    int h = rem >> 1;        // head
    int which = rem & 1;     // 0 = q, 1 = k

    float* base = qkv + (size_t)n * (3 * CD) + which * CD + h * DH;
    const float* g = which ? kg : qg;

    float v0 = base[lane];
    float v1 = base[lane + 32];
    float ss = v0 * v0 + v1 * v1;
    #pragma unroll
    for (int off = 16; off >= 1; off >>= 1)
        ss += __shfl_xor_sync(0xffffffffu, ss, off);

    float norm = fmaxf(sqrtf(ss), 1e-12f);
    float sc = 8.0f / norm;   // sqrt(D)=8
    base[lane]      = v0 * sc * g[h * DH + lane];
    base[lane + 32] = v1 * sc * g[h * DH + lane + 32];
}

// ---------------------------------------------------------------------------
// Flash attention, one head x one 64-query block per CTA.
// BM=BN=64, D=64. 256 threads, 4x4 micro-tiles for both S=QK^T and O+=PV.
// Online softmax with running (m, l) per row.
// ---------------------------------------------------------------------------
__global__ __launch_bounds__(256, 2)
void flash_attn_kernel(const float* __restrict__ qkv, float* __restrict__ Hout)
{
    extern __shared__ float sm[];
    float (*Qs)[68] = (float(*)[68])(sm);            // [row][d]
    float (*Kt)[68] = (float(*)[68])(sm + 4352);     // [d][m]   (transposed)
    float (*Vs)[68] = (float(*)[68])(sm + 8704);     // [m][d]
    float (*Ps)[68] = (float(*)[68])(sm + 13056);    // [row][m]

    const int tid = threadIdx.x;
    const int tx = tid & 15, ty = tid >> 4;
    const int h = blockIdx.y;
    const int q0 = blockIdx.x * 64;

    const float* qb = qkv + h * DH;
    const float* kb = qkv + CD + h * DH;
    const float* vb = qkv + 2 * CD + h * DH;

    // Load Q tile once
    #pragma unroll
    for (int p = 0; p < 4; p++) {
        int idx = tid + p * 256;
        int row = idx >> 4, c4 = idx & 15;
        *(float4*)&Qs[row][c4 * 4] =
            *(const float4*)&qb[(size_t)(q0 + row) * (3 * CD) + c4 * 4];
    }

    float mi[4], li[4], O[4][4];
    #pragma unroll
    for (int i = 0; i < 4; i++) {
        mi[i] = -1e30f; li[i] = 0.f;
        #pragma unroll
        for (int j = 0; j < 4; j++) O[i][j] = 0.f;
    }

    for (int t = 0; t < NT / 64; t++) {
        const int k0 = t * 64;
        __syncthreads();   // prior PV GEMM done reading Vs/Ps; Qs visible on t=0

        #pragma unroll
        for (int p = 0; p < 4; p++) {
            int idx = tid + p * 256;
            int row = idx >> 4, c4 = idx & 15;
            float4 kv = *(const float4*)&kb[(size_t)(k0 + row) * (3 * CD) + c4 * 4];
            Kt[c4 * 4 + 0][row] = kv.x;
            Kt[c4 * 4 + 1][row] = kv.y;
            Kt[c4 * 4 + 2][row] = kv.z;
            Kt[c4 * 4 + 3][row] = kv.w;
            *(float4*)&Vs[row][c4 * 4] =
                *(const float4*)&vb[(size_t)(k0 + row) * (3 * CD) + c4 * 4];
        }
        __syncthreads();

        // S = Q @ K^T (reduction over d)
        float s[4][4] = {};
        #pragma unroll 8
        for (int kk = 0; kk < 64; kk++) {
            float4 b = *(const float4*)&Kt[kk][tx * 4];
            float a[4];
            #pragma unroll
            for (int i = 0; i < 4; i++) a[i] = Qs[ty * 4 + i][kk];
            #pragma unroll
            for (int i = 0; i < 4; i++) {
                s[i][0] += a[i] * b.x;
                s[i][1] += a[i] * b.y;
                s[i][2] += a[i] * b.z;
                s[i][3] += a[i] * b.w;
            }
        }

        // Online softmax: per row (distributed over 16 tx lanes, width-16 shuffles)
        #pragma unroll
        for (int i = 0; i < 4; i++) {
            float rmax = -1e30f;
            #pragma unroll
            for (int j = 0; j < 4; j++) {
                s[i][j] *= 0.125f;   // 1/sqrt(64)
                rmax = fmaxf(rmax, s[i][j]);
            }
            #pragma unroll
            for (int off = 8; off >= 1; off >>= 1)
                rmax = fmaxf(rmax, __shfl_xor_sync(0xffffffffu, rmax, off, 16));

            float mnew = fmaxf(mi[i], rmax);
            float corr = __expf(mi[i] - mnew);
            float rs = 0.f;
            #pragma unroll
            for (int j = 0; j < 4; j++) {
                float pv = __expf(s[i][j] - mnew);
                Ps[ty * 4 + i][tx * 4 + j] = pv;
                rs += pv;
            }
            #pragma unroll
            for (int off = 8; off >= 1; off >>= 1)
                rs += __shfl_xor_sync(0xffffffffu, rs, off, 16);

            li[i] = li[i] * corr + rs;
            mi[i] = mnew;
            #pragma unroll
            for (int j = 0; j < 4; j++) O[i][j] *= corr;
        }
        __syncthreads();

        // O += P @ V (reduction over m)
        #pragma unroll 8
        for (int mm = 0; mm < 64; mm++) {
            float4 b = *(const float4*)&Vs[mm][tx * 4];
            float a[4];
            #pragma unroll
            for (int i = 0; i < 4; i++) a[i] = Ps[ty * 4 + i][mm];
            #pragma unroll
            for (int i = 0; i < 4; i++) {
                O[i][0] += a[i] * b.x;
                O[i][1] += a[i] * b.y;
                O[i][2] += a[i] * b.z;
                O[i][3] += a[i] * b.w;
            }
        }
    }

    #pragma unroll
    for (int i = 0; i < 4; i++) {
        float inv = 1.0f / li[i];
        #pragma unroll
        for (int j = 0; j < 4; j++)
            Hout[(size_t)(q0 + ty * 4 + i) * CD + h * DH + tx * 4 + j] = O[i][j] * inv;
    }
}

// ---------------------------------------------------------------------------
// kernel_launch: 4 launches on the default stream (graph-capturable, no sync,
// no allocation; scratch via __device__ globals).
// Inputs (metadata order): x, Wqkv, bqkv, q_gamma, k_gamma, Wout, bout
// ---------------------------------------------------------------------------
extern "C" void kernel_launch(void* const* d_in, const int* in_sizes, int n_in,
                              void* d_out, int out_size)
{
    const float* x    = (const float*)d_in[0];
    const float* Wqkv = (const float*)d_in[1];
    const float* bqkv = (const float*)d_in[2];
    const float* qg   = (const float*)d_in[3];
    const float* kg   = (const float*)d_in[4];
    const float* Wout = (const float*)d_in[5];
    const float* bout = (const float*)d_in[6];
    float* out = (float*)d_out;

    void* qkv_p = 0; cudaGetSymbolAddress(&qkv_p, g_qkv);
    void* h_p   = 0; cudaGetSymbolAddress(&h_p,   g_h);
    float* qkv  = (float*)qkv_p;
    float* hbuf = (float*)h_p;

    cudaFuncSetAttribute(flash_attn_kernel,
                         cudaFuncAttributeMaxDynamicSharedMemorySize, 69632);

    // 1) qkv = x @ Wqkv^T + bqkv
    gemm_bt_kernel<<<dim3(3 * CD / 64, NT / 64), 256>>>(x, Wqkv, bqkv, qkv,
                                                        NT, 3 * CD, CD);
    // 2) per-head RMS norm on q and k (in place)
    rmsnorm_kernel<<<(NT * NH * 2 * 32) / 256, 256>>>(qkv, qg, kg);
    // 3) flash attention -> hbuf
    flash_attn_kernel<<<dim3(NT / 64, NH), 256, 69632>>>(qkv, hbuf);
    // 4) out = hbuf @ Wout^T + bout
    gemm_bt_kernel<<<dim3(CD / 64, NT / 64), 256>>>(hbuf, Wout, bout, out,
                                                    NT, CD, CD);
}

// round 3
// speedup vs baseline: 2.6480x; 2.6480x over previous
#include <cuda_runtime.h>
#include <cuda_bf16.h>
#include <cstdint>
#include <math.h>

#define NT 4096
#define CD 1024
#define NH 16
#define DH 64

typedef __nv_bfloat16 bf16;

// ---------------- scratch (allocation-free rule) ----------------
__device__ float g_qkv[NT * 3 * CD];
__device__ bf16  g_xhi[NT * CD],     g_xlo[NT * CD];
__device__ bf16  g_whi[3 * CD * CD], g_wlo[3 * CD * CD];
__device__ bf16  g_ohi[CD * CD],     g_olo[CD * CD];
__device__ bf16  g_hhi[NT * CD],     g_hlo[NT * CD];

// ---------------- MMA helpers (baseline PTX, works at compute_100) ---------
__device__ __forceinline__ uint32_t smem_u32(const void* p) {
    return (uint32_t)__cvta_generic_to_shared(p);
}
__device__ __forceinline__ void ldsm_x4(uint32_t* r, uint32_t a) {
    asm volatile("ldmatrix.sync.aligned.m8n8.x4.shared.b16 {%0,%1,%2,%3}, [%4];"
                 : "=r"(r[0]), "=r"(r[1]), "=r"(r[2]), "=r"(r[3]) : "r"(a));
}
__device__ __forceinline__ void ldsm_x4_t(uint32_t* r, uint32_t a) {
    asm volatile("ldmatrix.sync.aligned.m8n8.x4.trans.shared.b16 {%0,%1,%2,%3}, [%4];"
                 : "=r"(r[0]), "=r"(r[1]), "=r"(r[2]), "=r"(r[3]) : "r"(a));
}
__device__ __forceinline__ void mma_bf(float* c, const uint32_t* a, const uint32_t* b) {
    asm volatile(
        "mma.sync.aligned.m16n8k16.row.col.f32.bf16.bf16.f32 "
        "{%0,%1,%2,%3}, {%4,%5,%6,%7}, {%8,%9}, {%0,%1,%2,%3};"
        : "+f"(c[0]), "+f"(c[1]), "+f"(c[2]), "+f"(c[3])
        : "r"(a[0]), "r"(a[1]), "r"(a[2]), "r"(a[3]), "r"(b[0]), "r"(b[1]));
}
// pack (a->low, b->high) as bf16x2, plus residual pack
__device__ __forceinline__ uint32_t pack_hi(float a, float b) {
    __nv_bfloat162 h = __floats2bfloat162_rn(a, b);
    return *(uint32_t*)&h;
}
__device__ __forceinline__ void split2(float a, float b, uint32_t& hi, uint32_t& lo) {
    __nv_bfloat162 h = __floats2bfloat162_rn(a, b);
    float ra = a - __bfloat162float(h.x);
    float rb = b - __bfloat162float(h.y);
    __nv_bfloat162 l = __floats2bfloat162_rn(ra, rb);
    hi = *(uint32_t*)&h;
    lo = *(uint32_t*)&l;
}

// ---------------------------------------------------------------------------
// fp32 -> bf16 hi/lo split
// ---------------------------------------------------------------------------
__global__ void split_kernel(const float* __restrict__ in, bf16* __restrict__ hi,
                             bf16* __restrict__ lo, int n) {
    int i = blockIdx.x * blockDim.x + threadIdx.x;
    if (i < n) {
        float v = in[i];
        bf16 h = __float2bfloat16(v);
        hi[i] = h;
        lo[i] = __float2bfloat16(v - __bfloat162float(h));
    }
}

// ---------------------------------------------------------------------------
// MMA GEMM: C[M,Nc] = (Ahi+Alo)[M,K] @ (Bhi+Blo)[Nc,K]^T + bias. K=1024.
// 128x128 block tile, BK=32, 8 warps, warp tile 32x64. Split-bf16 3 products.
// ---------------------------------------------------------------------------
__global__ __launch_bounds__(256)
void gemm_mma(const bf16* __restrict__ Ahi, const bf16* __restrict__ Alo,
              const bf16* __restrict__ Bhi, const bf16* __restrict__ Blo,
              const float* __restrict__ bias, float* __restrict__ C, int Nc)
{
    __shared__ bf16 sAh[128][40], sAl[128][40], sBh[128][40], sBl[128][40];
    const int tid = threadIdx.x, lane = tid & 31, w = tid >> 5;
    const int wm = w >> 1, wn = w & 1;
    const int g = lane >> 2, t = lane & 3;
    const int n0 = blockIdx.x * 128, m0 = blockIdx.y * 128;

    float acc[2][8][4];
    #pragma unroll
    for (int i = 0; i < 2; i++)
        #pragma unroll
        for (int j = 0; j < 8; j++)
            acc[i][j][0] = acc[i][j][1] = acc[i][j][2] = acc[i][j][3] = 0.f;

    uint4 st[8];
    // prefetch chunk 0
    #pragma unroll
    for (int p = 0; p < 2; p++) {
        int idx = tid + p * 256, row = idx >> 2, sg = idx & 3;
        size_t ao = (size_t)(m0 + row) * 1024 + sg * 8;
        size_t bo = (size_t)(n0 + row) * 1024 + sg * 8;
        st[p * 4 + 0] = *(const uint4*)(Ahi + ao);
        st[p * 4 + 1] = *(const uint4*)(Alo + ao);
        st[p * 4 + 2] = *(const uint4*)(Bhi + bo);
        st[p * 4 + 3] = *(const uint4*)(Blo + bo);
    }

    for (int c = 0; c < 32; c++) {
        __syncthreads();
        #pragma unroll
        for (int p = 0; p < 2; p++) {
            int idx = tid + p * 256, row = idx >> 2, sg = idx & 3;
            *(uint4*)&sAh[row][sg * 8] = st[p * 4 + 0];
            *(uint4*)&sAl[row][sg * 8] = st[p * 4 + 1];
            *(uint4*)&sBh[row][sg * 8] = st[p * 4 + 2];
            *(uint4*)&sBl[row][sg * 8] = st[p * 4 + 3];
        }
        __syncthreads();
        if (c < 31) {
            int kt = (c + 1) * 32;
            #pragma unroll
            for (int p = 0; p < 2; p++) {
                int idx = tid + p * 256, row = idx >> 2, sg = idx & 3;
                size_t ao = (size_t)(m0 + row) * 1024 + kt + sg * 8;
                size_t bo = (size_t)(n0 + row) * 1024 + kt + sg * 8;
                st[p * 4 + 0] = *(const uint4*)(Ahi + ao);
                st[p * 4 + 1] = *(const uint4*)(Alo + ao);
                st[p * 4 + 2] = *(const uint4*)(Bhi + bo);
                st[p * 4 + 3] = *(const uint4*)(Blo + bo);
            }
        }
        #pragma unroll
        for (int kk = 0; kk < 2; kk++) {
            uint32_t ah[2][4], al[2][4];
            #pragma unroll
            for (int mt = 0; mt < 2; mt++) {
                int ar = wm * 32 + mt * 16 + (lane & 15);
                int ac = kk * 16 + ((lane & 16) >> 1);
                ldsm_x4(ah[mt], smem_u32(&sAh[ar][ac]));
                ldsm_x4(al[mt], smem_u32(&sAl[ar][ac]));
            }
            #pragma unroll
            for (int u = 0; u < 4; u++) {
                uint32_t bh[4], bl[4];
                int br = wn * 64 + u * 16 + (lane & 7) + ((lane & 16) >> 1);
                int bc = kk * 16 + (lane & 8);
                ldsm_x4(bh, smem_u32(&sBh[br][bc]));
                ldsm_x4(bl, smem_u32(&sBl[br][bc]));
                #pragma unroll
                for (int mt = 0; mt < 2; mt++) {
                    mma_bf(acc[mt][2 * u],     ah[mt], &bh[0]);
                    mma_bf(acc[mt][2 * u],     al[mt], &bh[0]);
                    mma_bf(acc[mt][2 * u],     ah[mt], &bl[0]);
                    mma_bf(acc[mt][2 * u + 1], ah[mt], &bh[2]);
                    mma_bf(acc[mt][2 * u + 1], al[mt], &bh[2]);
                    mma_bf(acc[mt][2 * u + 1], ah[mt], &bl[2]);
                }
            }
        }
    }

    #pragma unroll
    for (int mt = 0; mt < 2; mt++) {
        int r0 = m0 + wm * 32 + mt * 16 + g;
        #pragma unroll
        for (int nt = 0; nt < 8; nt++) {
            int cc = n0 + wn * 64 + nt * 8 + t * 2;
            float2 bv = *(const float2*)&bias[cc];
            float* a = acc[mt][nt];
            *(float2*)&C[(size_t)r0 * Nc + cc]       = make_float2(a[0] + bv.x, a[1] + bv.y);
            *(float2*)&C[(size_t)(r0 + 8) * Nc + cc] = make_float2(a[2] + bv.x, a[3] + bv.y);
        }
    }
}

// ---------------------------------------------------------------------------
// Per-head RMS norm of q and k, in place (unchanged, passing)
// ---------------------------------------------------------------------------
__global__ __launch_bounds__(256)
void rmsnorm_kernel(float* __restrict__ qkv,
                    const float* __restrict__ qg,
                    const float* __restrict__ kg)
{
    int w = (blockIdx.x * blockDim.x + threadIdx.x) >> 5;
    int lane = threadIdx.x & 31;
    int n = w >> 5, rem = w & 31, h = rem >> 1, which = rem & 1;

    float* base = qkv + (size_t)n * (3 * CD) + which * CD + h * DH;
    const float* g = which ? kg : qg;

    float v0 = base[lane], v1 = base[lane + 32];
    float ss = v0 * v0 + v1 * v1;
    #pragma unroll
    for (int off = 16; off >= 1; off >>= 1)
        ss += __shfl_xor_sync(0xffffffffu, ss, off);

    float sc = 8.0f / fmaxf(sqrtf(ss), 1e-12f);
    base[lane]      = v0 * sc * g[h * DH + lane];
    base[lane + 32] = v1 * sc * g[h * DH + lane + 32];
}

// ---------------------------------------------------------------------------
// Flash attention with warp MMA. BM=BN=128, 8 warps, warp owns 16 full rows.
// Q/K/V converted to bf16 hi/lo in smem. Split-bf16 for S and PV (3 products).
// Emits h as bf16 hi/lo for the out-projection GEMM.
// ---------------------------------------------------------------------------
__global__ __launch_bounds__(256)
void flash_mma(const float* __restrict__ qkv,
               bf16* __restrict__ hhi, bf16* __restrict__ hlo)
{
    extern __shared__ bf16 smem[];
    bf16 (*Qh)[72] = (bf16(*)[72])(smem);
    bf16 (*Ql)[72] = (bf16(*)[72])(smem + 128 * 72);
    bf16 (*Kh)[72] = (bf16(*)[72])(smem + 2 * 128 * 72);
    bf16 (*Kl)[72] = (bf16(*)[72])(smem + 3 * 128 * 72);
    bf16 (*Vh)[72] = (bf16(*)[72])(smem + 4 * 128 * 72);
    bf16 (*Vl)[72] = (bf16(*)[72])(smem + 5 * 128 * 72);

    const int tid = threadIdx.x, lane = tid & 31, w = tid >> 5;
    const int g = lane >> 2, t = lane & 3;
    const int h = blockIdx.y, q0 = blockIdx.x * 128;

    const float* qb = qkv + h * DH;
    const float* kb = qkv + CD + h * DH;
    const float* vb = qkv + 2 * CD + h * DH;

    // stage Q once (scaled by 1/sqrt(D) = 0.125)
    #pragma unroll
    for (int p = 0; p < 8; p++) {
        int idx = tid + p * 256, row = idx >> 4, sg = idx & 15;
        float4 v = *(const float4*)&qb[(size_t)(q0 + row) * (3 * CD) + sg * 4];
        v.x *= 0.125f; v.y *= 0.125f; v.z *= 0.125f; v.w *= 0.125f;
        uint32_t h0, l0, h1, l1;
        split2(v.x, v.y, h0, l0);
        split2(v.z, v.w, h1, l1);
        *(uint2*)&Qh[row][sg * 4] = make_uint2(h0, h1);
        *(uint2*)&Ql[row][sg * 4] = make_uint2(l0, l1);
    }
    __syncthreads();

    // preload Q fragments (constant over the whole loop)
    uint32_t qah[4][4], qal[4][4];
    #pragma unroll
    for (int kk = 0; kk < 4; kk++) {
        int ar = w * 16 + (lane & 15);
        int ac = kk * 16 + ((lane & 16) >> 1);
        ldsm_x4(qah[kk], smem_u32(&Qh[ar][ac]));
        ldsm_x4(qal[kk], smem_u32(&Ql[ar][ac]));
    }

    float mi0 = -1e30f, mi1 = -1e30f, li0 = 0.f, li1 = 0.f;
    float oacc[8][4];
    #pragma unroll
    for (int u = 0; u < 8; u++)
        oacc[u][0] = oacc[u][1] = oacc[u][2] = oacc[u][3] = 0.f;

    for (int it = 0; it < NT / 128; it++) {
        const int k0 = it * 128;
        __syncthreads();
        #pragma unroll
        for (int p = 0; p < 8; p++) {
            int idx = tid + p * 256, row = idx >> 4, sg = idx & 15;
            float4 kv = *(const float4*)&kb[(size_t)(k0 + row) * (3 * CD) + sg * 4];
            float4 vv = *(const float4*)&vb[(size_t)(k0 + row) * (3 * CD) + sg * 4];
            uint32_t h0, l0, h1, l1;
            split2(kv.x, kv.y, h0, l0);
            split2(kv.z, kv.w, h1, l1);
            *(uint2*)&Kh[row][sg * 4] = make_uint2(h0, h1);
            *(uint2*)&Kl[row][sg * 4] = make_uint2(l0, l1);
            split2(vv.x, vv.y, h0, l0);
            split2(vv.z, vv.w, h1, l1);
            *(uint2*)&Vh[row][sg * 4] = make_uint2(h0, h1);
            *(uint2*)&Vl[row][sg * 4] = make_uint2(l0, l1);
        }
        __syncthreads();

        // S = Q @ K^T (fp32 accum)
        float s[16][4];
        #pragma unroll
        for (int j = 0; j < 16; j++)
            s[j][0] = s[j][1] = s[j][2] = s[j][3] = 0.f;

        #pragma unroll
        for (int kk = 0; kk < 4; kk++) {
            #pragma unroll
            for (int u = 0; u < 8; u++) {
                uint32_t bh[4], bl[4];
                int br = u * 16 + (lane & 7) + ((lane & 16) >> 1);
                int bc = kk * 16 + (lane & 8);
                ldsm_x4(bh, smem_u32(&Kh[br][bc]));
                ldsm_x4(bl, smem_u32(&Kl[br][bc]));
                mma_bf(s[2 * u],     qah[kk], &bh[0]);
                mma_bf(s[2 * u],     qal[kk], &bh[0]);
                mma_bf(s[2 * u],     qah[kk], &bl[0]);
                mma_bf(s[2 * u + 1], qah[kk], &bh[2]);
                mma_bf(s[2 * u + 1], qal[kk], &bh[2]);
                mma_bf(s[2 * u + 1], qah[kk], &bl[2]);
            }
        }

        // online softmax (rows g and g+8 of this warp's 16-row stripe)
        float rm0 = -1e30f, rm1 = -1e30f;
        #pragma unroll
        for (int j = 0; j < 16; j++) {
            rm0 = fmaxf(rm0, fmaxf(s[j][0], s[j][1]));
            rm1 = fmaxf(rm1, fmaxf(s[j][2], s[j][3]));
        }
        rm0 = fmaxf(rm0, __shfl_xor_sync(0xffffffffu, rm0, 1));
        rm0 = fmaxf(rm0, __shfl_xor_sync(0xffffffffu, rm0, 2));
        rm1 = fmaxf(rm1, __shfl_xor_sync(0xffffffffu, rm1, 1));
        rm1 = fmaxf(rm1, __shfl_xor_sync(0xffffffffu, rm1, 2));

        float mn0 = fmaxf(mi0, rm0), mn1 = fmaxf(mi1, rm1);
        float corr0 = __expf(mi0 - mn0), corr1 = __expf(mi1 - mn1);
        float rs0 = 0.f, rs1 = 0.f;
        #pragma unroll
        for (int j = 0; j < 16; j++) {
            s[j][0] = __expf(s[j][0] - mn0);
            s[j][1] = __expf(s[j][1] - mn0);
            s[j][2] = __expf(s[j][2] - mn1);
            s[j][3] = __expf(s[j][3] - mn1);
            rs0 += s[j][0] + s[j][1];
            rs1 += s[j][2] + s[j][3];
        }
        rs0 += __shfl_xor_sync(0xffffffffu, rs0, 1);
        rs0 += __shfl_xor_sync(0xffffffffu, rs0, 2);
        rs1 += __shfl_xor_sync(0xffffffffu, rs1, 1);
        rs1 += __shfl_xor_sync(0xffffffffu, rs1, 2);

        li0 = li0 * corr0 + rs0;
        li1 = li1 * corr1 + rs1;
        mi0 = mn0; mi1 = mn1;
        #pragma unroll
        for (int u = 0; u < 8; u++) {
            oacc[u][0] *= corr0; oacc[u][1] *= corr0;
            oacc[u][2] *= corr1; oacc[u][3] *= corr1;
        }

        // O += P @ V
        #pragma unroll
        for (int kv = 0; kv < 8; kv++) {
            uint32_t pa[4], pl[4];
            split2(s[2 * kv][0],     s[2 * kv][1],     pa[0], pl[0]);
            split2(s[2 * kv][2],     s[2 * kv][3],     pa[1], pl[1]);
            split2(s[2 * kv + 1][0], s[2 * kv + 1][1], pa[2], pl[2]);
            split2(s[2 * kv + 1][2], s[2 * kv + 1][3], pa[3], pl[3]);
            #pragma unroll
            for (int u = 0; u < 4; u++) {
                uint32_t vh4[4], vl4[4];
                int vr = kv * 16 + (lane & 15);
                int vc = u * 16 + ((lane & 16) >> 1);
                ldsm_x4_t(vh4, smem_u32(&Vh[vr][vc]));
                ldsm_x4_t(vl4, smem_u32(&Vl[vr][vc]));
                mma_bf(oacc[2 * u],     pa, &vh4[0]);
                mma_bf(oacc[2 * u],     pl, &vh4[0]);
                mma_bf(oacc[2 * u],     pa, &vl4[0]);
                mma_bf(oacc[2 * u + 1], pa, &vh4[2]);
                mma_bf(oacc[2 * u + 1], pl, &vh4[2]);
                mma_bf(oacc[2 * u + 1], pa, &vl4[2]);
            }
        }
    }

    // epilogue: normalize and write h as bf16 hi/lo
    float inv0 = 1.0f / li0, inv1 = 1.0f / li1;
    int r0 = q0 + w * 16 + g;
    #pragma unroll
    for (int u = 0; u < 8; u++) {
        uint32_t hi, lo;
        size_t o0 = (size_t)r0 * CD + h * DH + u * 8 + t * 2;
        split2(oacc[u][0] * inv0, oacc[u][1] * inv0, hi, lo);
        *(uint32_t*)&hhi[o0] = hi;
        *(uint32_t*)&hlo[o0] = lo;
        size_t o1 = (size_t)(r0 + 8) * CD + h * DH + u * 8 + t * 2;
        split2(oacc[u][2] * inv1, oacc[u][3] * inv1, hi, lo);
        *(uint32_t*)&hhi[o1] = hi;
        *(uint32_t*)&hlo[o1] = lo;
    }
}

// ---------------------------------------------------------------------------
// kernel_launch — graph-capturable, allocation-free.
// Inputs: x, Wqkv, bqkv, q_gamma, k_gamma, Wout, bout
// ---------------------------------------------------------------------------
extern "C" void kernel_launch(void* const* d_in, const int* in_sizes, int n_in,
                              void* d_out, int out_size)
{
    const float* x    = (const float*)d_in[0];
    const float* Wqkv = (const float*)d_in[1];
    const float* bqkv = (const float*)d_in[2];
    const float* qg   = (const float*)d_in[3];
    const float* kg   = (const float*)d_in[4];
    const float* Wout = (const float*)d_in[5];
    const float* bout = (const float*)d_in[6];
    float* out = (float*)d_out;

    void* p;
    cudaGetSymbolAddress(&p, g_qkv);  float* qkv = (float*)p;
    cudaGetSymbolAddress(&p, g_xhi);  bf16* xhi = (bf16*)p;
    cudaGetSymbolAddress(&p, g_xlo);  bf16* xlo = (bf16*)p;
    cudaGetSymbolAddress(&p, g_whi);  bf16* whi = (bf16*)p;
    cudaGetSymbolAddress(&p, g_wlo);  bf16* wlo = (bf16*)p;
    cudaGetSymbolAddress(&p, g_ohi);  bf16* ohi = (bf16*)p;
    cudaGetSymbolAddress(&p, g_olo);  bf16* olo = (bf16*)p;
    cudaGetSymbolAddress(&p, g_hhi);  bf16* hhi = (bf16*)p;
    cudaGetSymbolAddress(&p, g_hlo);  bf16* hlo = (bf16*)p;

    cudaFuncSetAttribute(flash_mma,
                         cudaFuncAttributeMaxDynamicSharedMemorySize, 110592);

    // 0) fp32 -> bf16 hi/lo splits
    split_kernel<<<(NT * CD + 255) / 256, 256>>>(x, xhi, xlo, NT * CD);
    split_kernel<<<(3 * CD * CD + 255) / 256, 256>>>(Wqkv, whi, wlo, 3 * CD * CD);
    split_kernel<<<(CD * CD + 255) / 256, 256>>>(Wout, ohi, olo, CD * CD);

    // 1) qkv = x @ Wqkv^T + bqkv
    gemm_mma<<<dim3(3 * CD / 128, NT / 128), 256>>>(xhi, xlo, whi, wlo,
                                                    bqkv, qkv, 3 * CD);
    // 2) per-head RMS norm on q and k (in place)
    rmsnorm_kernel<<<(NT * NH * 2 * 32) / 256, 256>>>(qkv, qg, kg);

    // 3) flash attention -> h (bf16 hi/lo)
    flash_mma<<<dim3(NT / 128, NH), 256, 110592>>>(qkv, hhi, hlo);

    // 4) out = h @ Wout^T + bout
    gemm_mma<<<dim3(CD / 128, NT / 128), 256>>>(hhi, hlo, ohi, olo,
                                                bout, out, CD);
}

// round 5
// speedup vs baseline: 3.1090x; 1.1741x over previous
#include <cuda_runtime.h>
#include <cuda_bf16.h>
#include <cstdint>
#include <math.h>

#define NT 4096
#define CD 1024
#define NH 16
#define DH 64

typedef __nv_bfloat16 bf16;

// ---------------- scratch (allocation-free rule) ----------------
__device__ float g_qkv[NT * 3 * CD];
__device__ bf16  g_xhi[NT * CD],     g_xlo[NT * CD];
__device__ bf16  g_whi[3 * CD * CD], g_wlo[3 * CD * CD];
__device__ bf16  g_ohi[CD * CD],     g_olo[CD * CD];
__device__ bf16  g_hhi[NT * CD],     g_hlo[NT * CD];
// head-major [NH][NT][DH] bf16 splits of q (pre-scaled), k, v
__device__ bf16  g_qh[NT * CD], g_ql[NT * CD];
__device__ bf16  g_kh[NT * CD], g_kl[NT * CD];
__device__ bf16  g_vh[NT * CD], g_vl[NT * CD];

// ---------------- helpers ----------------
__device__ __forceinline__ uint32_t smem_u32(const void* p) {
    return (uint32_t)__cvta_generic_to_shared(p);
}
__device__ __forceinline__ void ldsm_x4(uint32_t* r, uint32_t a) {
    asm volatile("ldmatrix.sync.aligned.m8n8.x4.shared.b16 {%0,%1,%2,%3}, [%4];"
                 : "=r"(r[0]), "=r"(r[1]), "=r"(r[2]), "=r"(r[3]) : "r"(a));
}
__device__ __forceinline__ void ldsm_x4_t(uint32_t* r, uint32_t a) {
    asm volatile("ldmatrix.sync.aligned.m8n8.x4.trans.shared.b16 {%0,%1,%2,%3}, [%4];"
                 : "=r"(r[0]), "=r"(r[1]), "=r"(r[2]), "=r"(r[3]) : "r"(a));
}
__device__ __forceinline__ void mma_bf(float* c, const uint32_t* a, const uint32_t* b) {
    asm volatile(
        "mma.sync.aligned.m16n8k16.row.col.f32.bf16.bf16.f32 "
        "{%0,%1,%2,%3}, {%4,%5,%6,%7}, {%8,%9}, {%0,%1,%2,%3};"
        : "+f"(c[0]), "+f"(c[1]), "+f"(c[2]), "+f"(c[3])
        : "r"(a[0]), "r"(a[1]), "r"(a[2]), "r"(a[3]), "r"(b[0]), "r"(b[1]));
}
__device__ __forceinline__ void split2(float a, float b, uint32_t& hi, uint32_t& lo) {
    __nv_bfloat162 h = __floats2bfloat162_rn(a, b);
    float ra = a - __bfloat162float(h.x);
    float rb = b - __bfloat162float(h.y);
    __nv_bfloat162 l = __floats2bfloat162_rn(ra, rb);
    hi = *(uint32_t*)&h;
    lo = *(uint32_t*)&l;
}
__device__ __forceinline__ void cp16(uint32_t dst, const void* src) {
    asm volatile("cp.async.cg.shared.global [%0], [%1], 16;" :: "r"(dst), "l"(src));
}
#define CP_COMMIT() asm volatile("cp.async.commit_group;" ::: "memory")
#define CP_WAIT(n)  asm volatile("cp.async.wait_group %0;" :: "n"(n) : "memory")

// ---------------------------------------------------------------------------
// fp32 -> bf16 hi/lo split (x and weights), 4 elements per thread
// ---------------------------------------------------------------------------
__global__ void split_kernel(const float* __restrict__ in, bf16* __restrict__ hi,
                             bf16* __restrict__ lo, int n4) {
    int i = blockIdx.x * blockDim.x + threadIdx.x;
    if (i < n4) {
        float4 v = ((const float4*)in)[i];
        uint32_t h0, l0, h1, l1;
        split2(v.x, v.y, h0, l0);
        split2(v.z, v.w, h1, l1);
        ((uint2*)hi)[i] = make_uint2(h0, h1);
        ((uint2*)lo)[i] = make_uint2(l0, l1);
    }
}

// ---------------------------------------------------------------------------
// Post-process qkv: per-head RMS norm on q,k + split all of q,k,v to bf16
// hi/lo in head-major [NH][NT][DH]. q pre-scaled by 1/sqrt(D)=0.125.
// One warp per (token, head, {q,k,v}); each lane owns 2 adjacent elements.
// ---------------------------------------------------------------------------
__global__ __launch_bounds__(256)
void post_kernel(const float* __restrict__ qkv,
                 const float* __restrict__ qg, const float* __restrict__ kg,
                 bf16* __restrict__ qh, bf16* __restrict__ ql,
                 bf16* __restrict__ kh, bf16* __restrict__ kl,
                 bf16* __restrict__ vh, bf16* __restrict__ vl)
{
    int w = (blockIdx.x * blockDim.x + threadIdx.x) >> 5;   // 0 .. NT*NH*3-1
    int lane = threadIdx.x & 31;
    int n = w / (NH * 3);
    int rem = w - n * (NH * 3);
    int h = rem / 3, ty = rem - h * 3;                      // 0=q 1=k 2=v

    const float* base = qkv + (size_t)n * (3 * CD) + ty * CD + h * DH;
    float v0 = base[2 * lane], v1 = base[2 * lane + 1];

    if (ty < 2) {
        float ss = v0 * v0 + v1 * v1;
        #pragma unroll
        for (int off = 16; off >= 1; off >>= 1)
            ss += __shfl_xor_sync(0xffffffffu, ss, off);
        float inv = 1.0f / fmaxf(sqrtf(ss), 1e-12f);
        const float* g = (ty == 0) ? qg : kg;
        float gsc = (ty == 0) ? inv : (8.0f * inv);          // q: *8*0.125 = *1
        v0 *= gsc * g[h * DH + 2 * lane];
        v1 *= gsc * g[h * DH + 2 * lane + 1];
    }

    uint32_t hi, lo;
    split2(v0, v1, hi, lo);
    size_t off = (size_t)h * NT * DH + (size_t)n * DH + 2 * lane;
    bf16 *dh, *dl;
    if (ty == 0)      { dh = qh; dl = ql; }
    else if (ty == 1) { dh = kh; dl = kl; }
    else              { dh = vh; dl = vl; }
    *(uint32_t*)&dh[off] = hi;
    *(uint32_t*)&dl[off] = lo;
}

// ---------------------------------------------------------------------------
// MMA GEMM v2: C = (Ahi+Alo) @ (Bhi+Blo)^T + bias. K=1024, 128x128 tile,
// BK=32, 8 warps, warp tile 32x64. cp.async double-buffered, 2 CTAs/SM.
// dyn smem: 2 stages x (Ah,Al,Bh,Bl) x 128x40 bf16 = 81920 B.
// ---------------------------------------------------------------------------
#define G_STG 40960
#define G_ARR 10240
__global__ __launch_bounds__(256, 2)
void gemm_mma(const bf16* __restrict__ Ahi, const bf16* __restrict__ Alo,
              const bf16* __restrict__ Bhi, const bf16* __restrict__ Blo,
              const float* __restrict__ bias, float* __restrict__ C, int Nc)
{
    extern __shared__ char smem[];
    const uint32_t sb = smem_u32(smem);
    const int tid = threadIdx.x, lane = tid & 31, w = tid >> 5;
    const int wm = w >> 1, wn = w & 1;
    const int g = lane >> 2, t = lane & 3;
    const int n0 = blockIdx.x * 128, m0 = blockIdx.y * 128;

    float acc[2][8][4];
    #pragma unroll
    for (int i = 0; i < 2; i++)
        #pragma unroll
        for (int j = 0; j < 8; j++)
            acc[i][j][0] = acc[i][j][1] = acc[i][j][2] = acc[i][j][3] = 0.f;

    const bf16* srcs[4] = {Ahi, Alo, Bhi, Blo};

    // loader: stage s, K-chunk c
    auto load_tile = [&](int c, int s) {
        int kt = c * 32;
        #pragma unroll
        for (int p = 0; p < 8; p++) {
            int idx = tid + p * 256;           // 0..2047
            int arr = idx >> 9;                // 0..3
            int rem = idx & 511;
            int row = rem >> 2, sg = rem & 3;
            int base_row = (arr < 2) ? m0 : n0;
            const bf16* src = srcs[arr] + (size_t)(base_row + row) * 1024 + kt + sg * 8;
            cp16(sb + s * G_STG + arr * G_ARR + row * 80 + sg * 16, src);
        }
    };

    load_tile(0, 0);
    CP_COMMIT();

    for (int c = 0; c < 32; c++) {
        if (c < 31) { load_tile(c + 1, (c + 1) & 1); CP_COMMIT(); CP_WAIT(1); }
        else        { CP_WAIT(0); }
        __syncthreads();

        const uint32_t so = sb + (c & 1) * G_STG;
        #pragma unroll
        for (int kk = 0; kk < 2; kk++) {
            uint32_t ah[2][4], al[2][4];
            #pragma unroll
            for (int mt = 0; mt < 2; mt++) {
                int ar = wm * 32 + mt * 16 + (lane & 15);
                int ac = kk * 16 + ((lane & 16) >> 1);
                ldsm_x4(ah[mt], so + ar * 80 + ac * 2);
                ldsm_x4(al[mt], so + G_ARR + ar * 80 + ac * 2);
            }
            #pragma unroll
            for (int u = 0; u < 4; u++) {
                uint32_t bh[4], bl[4];
                int br = wn * 64 + u * 16 + (lane & 7) + ((lane & 16) >> 1);
                int bc = kk * 16 + (lane & 8);
                ldsm_x4(bh, so + 2 * G_ARR + br * 80 + bc * 2);
                ldsm_x4(bl, so + 3 * G_ARR + br * 80 + bc * 2);
                #pragma unroll
                for (int mt = 0; mt < 2; mt++) {
                    mma_bf(acc[mt][2 * u],     ah[mt], &bh[0]);
                    mma_bf(acc[mt][2 * u],     al[mt], &bh[0]);
                    mma_bf(acc[mt][2 * u],     ah[mt], &bl[0]);
                    mma_bf(acc[mt][2 * u + 1], ah[mt], &bh[2]);
                    mma_bf(acc[mt][2 * u + 1], al[mt], &bh[2]);
                    mma_bf(acc[mt][2 * u + 1], ah[mt], &bl[2]);
                }
            }
        }
        __syncthreads();
    }

    #pragma unroll
    for (int mt = 0; mt < 2; mt++) {
        int r0 = m0 + wm * 32 + mt * 16 + g;
        #pragma unroll
        for (int nt = 0; nt < 8; nt++) {
            int cc = n0 + wn * 64 + nt * 8 + t * 2;
            float2 bv = *(const float2*)&bias[cc];
            float* a = acc[mt][nt];
            *(float2*)&C[(size_t)r0 * Nc + cc]       = make_float2(a[0] + bv.x, a[1] + bv.y);
            *(float2*)&C[(size_t)(r0 + 8) * Nc + cc] = make_float2(a[2] + bv.x, a[3] + bv.y);
        }
    }
}

// ---------------------------------------------------------------------------
// Flash attention v3: BM=BN=128, 8 warps, warp owns 16 rows. K/V arrive as
// pre-split bf16 (head-major) via cp.async double buffering. Q fragments
// loaded directly from gmem. Split-bf16 3-product MMAs for S and PV.
// dyn smem: 2 stages x (Kh,Kl,Vh,Vl) x 128x72 bf16 = 147456 B.
// ---------------------------------------------------------------------------
#define A_STG 73728
#define A_ARR 18432
__global__ __launch_bounds__(256, 1)
void flash_mma(const bf16* __restrict__ qhg, const bf16* __restrict__ qlg,
               const bf16* __restrict__ khg, const bf16* __restrict__ klg,
               const bf16* __restrict__ vhg, const bf16* __restrict__ vlg,
               bf16* __restrict__ hhi, bf16* __restrict__ hlo)
{
    extern __shared__ char smem[];
    const uint32_t sb = smem_u32(smem);
    const int tid = threadIdx.x, lane = tid & 31, w = tid >> 5;
    const int g = lane >> 2, t = lane & 3;
    const int h = blockIdx.y, q0 = blockIdx.x * 128;
    const size_t hoff = (size_t)h * NT * DH;

    // Q fragments straight from gmem (m16n8k16 A layout: 2 adjacent bf16 / reg)
    uint32_t qah[4][4], qal[4][4];
    {
        const bf16* r0h = qhg + hoff + (size_t)(q0 + w * 16 + g) * DH;
        const bf16* r1h = r0h + 8 * DH;
        const bf16* r0l = qlg + hoff + (size_t)(q0 + w * 16 + g) * DH;
        const bf16* r1l = r0l + 8 * DH;
        #pragma unroll
        for (int kk = 0; kk < 4; kk++) {
            qah[kk][0] = *(const uint32_t*)(r0h + kk * 16 + 2 * t);
            qah[kk][1] = *(const uint32_t*)(r1h + kk * 16 + 2 * t);
            qah[kk][2] = *(const uint32_t*)(r0h + kk * 16 + 8 + 2 * t);
            qah[kk][3] = *(const uint32_t*)(r1h + kk * 16 + 8 + 2 * t);
            qal[kk][0] = *(const uint32_t*)(r0l + kk * 16 + 2 * t);
            qal[kk][1] = *(const uint32_t*)(r1l + kk * 16 + 2 * t);
            qal[kk][2] = *(const uint32_t*)(r0l + kk * 16 + 8 + 2 * t);
            qal[kk][3] = *(const uint32_t*)(r1l + kk * 16 + 8 + 2 * t);
        }
    }

    const bf16* srcs[4] = {khg + hoff, klg + hoff, vhg + hoff, vlg + hoff};

    auto load_tile = [&](int it, int s) {
        int k0 = it * 128;
        #pragma unroll
        for (int arr = 0; arr < 4; arr++) {
            #pragma unroll
            for (int p = 0; p < 4; p++) {
                int idx = tid + p * 256;        // 0..1023
                int row = idx >> 3, sg = idx & 7;
                cp16(sb + s * A_STG + arr * A_ARR + row * 144 + sg * 16,
                     srcs[arr] + (size_t)(k0 + row) * DH + sg * 8);
            }
        }
    };

    float mi0 = -1e30f, mi1 = -1e30f, li0 = 0.f, li1 = 0.f;
    float oacc[8][4];
    #pragma unroll
    for (int u = 0; u < 8; u++)
        oacc[u][0] = oacc[u][1] = oacc[u][2] = oacc[u][3] = 0.f;

    load_tile(0, 0);
    CP_COMMIT();

    for (int it = 0; it < NT / 128; it++) {
        if (it < NT / 128 - 1) { load_tile(it + 1, (it + 1) & 1); CP_COMMIT(); CP_WAIT(1); }
        else                   { CP_WAIT(0); }
        __syncthreads();

        const uint32_t so = sb + (it & 1) * A_STG;

        // S = Q @ K^T
        float s[16][4];
        #pragma unroll
        for (int j = 0; j < 16; j++)
            s[j][0] = s[j][1] = s[j][2] = s[j][3] = 0.f;

        #pragma unroll
        for (int kk = 0; kk < 4; kk++) {
            #pragma unroll
            for (int u = 0; u < 8; u++) {
                uint32_t bh[4], bl[4];
                int br = u * 16 + (lane & 7) + ((lane & 16) >> 1);
                int bc = kk * 16 + (lane & 8);
                ldsm_x4(bh, so + br * 144 + bc * 2);
                ldsm_x4(bl, so + A_ARR + br * 144 + bc * 2);
                mma_bf(s[2 * u],     qah[kk], &bh[0]);
                mma_bf(s[2 * u],     qal[kk], &bh[0]);
                mma_bf(s[2 * u],     qah[kk], &bl[0]);
                mma_bf(s[2 * u + 1], qah[kk], &bh[2]);
                mma_bf(s[2 * u + 1], qal[kk], &bh[2]);
                mma_bf(s[2 * u + 1], qah[kk], &bl[2]);
            }
        }

        // online softmax
        float rm0 = -1e30f, rm1 = -1e30f;
        #pragma unroll
        for (int j = 0; j < 16; j++) {
            rm0 = fmaxf(rm0, fmaxf(s[j][0], s[j][1]));
            rm1 = fmaxf(rm1, fmaxf(s[j][2], s[j][3]));
        }
        rm0 = fmaxf(rm0, __shfl_xor_sync(0xffffffffu, rm0, 1));
        rm0 = fmaxf(rm0, __shfl_xor_sync(0xffffffffu, rm0, 2));
        rm1 = fmaxf(rm1, __shfl_xor_sync(0xffffffffu, rm1, 1));
        rm1 = fmaxf(rm1, __shfl_xor_sync(0xffffffffu, rm1, 2));

        float mn0 = fmaxf(mi0, rm0), mn1 = fmaxf(mi1, rm1);
        float corr0 = __expf(mi0 - mn0), corr1 = __expf(mi1 - mn1);
        float rs0 = 0.f, rs1 = 0.f;
        #pragma unroll
        for (int j = 0; j < 16; j++) {
            s[j][0] = __expf(s[j][0] - mn0);
            s[j][1] = __expf(s[j][1] - mn0);
            s[j][2] = __expf(s[j][2] - mn1);
            s[j][3] = __expf(s[j][3] - mn1);
            rs0 += s[j][0] + s[j][1];
            rs1 += s[j][2] + s[j][3];
        }
        rs0 += __shfl_xor_sync(0xffffffffu, rs0, 1);
        rs0 += __shfl_xor_sync(0xffffffffu, rs0, 2);
        rs1 += __shfl_xor_sync(0xffffffffu, rs1, 1);
        rs1 += __shfl_xor_sync(0xffffffffu, rs1, 2);

        li0 = li0 * corr0 + rs0;
        li1 = li1 * corr1 + rs1;
        mi0 = mn0; mi1 = mn1;
        #pragma unroll
        for (int u = 0; u < 8; u++) {
            oacc[u][0] *= corr0; oacc[u][1] *= corr0;
            oacc[u][2] *= corr1; oacc[u][3] *= corr1;
        }

        // O += P @ V
        #pragma unroll
        for (int kv = 0; kv < 8; kv++) {
            uint32_t pa[4], pl[4];
            split2(s[2 * kv][0],     s[2 * kv][1],     pa[0], pl[0]);
            split2(s[2 * kv][2],     s[2 * kv][3],     pa[1], pl[1]);
            split2(s[2 * kv + 1][0], s[2 * kv + 1][1], pa[2], pl[2]);
            split2(s[2 * kv + 1][2], s[2 * kv + 1][3], pa[3], pl[3]);
            #pragma unroll
            for (int u = 0; u < 4; u++) {
                uint32_t vh4[4], vl4[4];
                int vr = kv * 16 + (lane & 15);
                int vc = u * 16 + ((lane & 16) >> 1);
                ldsm_x4_t(vh4, so + 2 * A_ARR + vr * 144 + vc * 2);
                ldsm_x4_t(vl4, so + 3 * A_ARR + vr * 144 + vc * 2);
                mma_bf(oacc[2 * u],     pa, &vh4[0]);
                mma_bf(oacc[2 * u],     pl, &vh4[0]);
                mma_bf(oacc[2 * u],     pa, &vl4[0]);
                mma_bf(oacc[2 * u + 1], pa, &vh4[2]);
                mma_bf(oacc[2 * u + 1], pl, &vh4[2]);
                mma_bf(oacc[2 * u + 1], pa, &vl4[2]);
            }
        }
        __syncthreads();
    }

    // epilogue: normalize, write h as bf16 hi/lo (row-major [NT][CD])
    float inv0 = 1.0f / li0, inv1 = 1.0f / li1;
    int r0 = q0 + w * 16 + g;
    #pragma unroll
    for (int u = 0; u < 8; u++) {
        uint32_t hi, lo;
        size_t o0 = (size_t)r0 * CD + h * DH + u * 8 + t * 2;
        split2(oacc[u][0] * inv0, oacc[u][1] * inv0, hi, lo);
        *(uint32_t*)&hhi[o0] = hi;
        *(uint32_t*)&hlo[o0] = lo;
        size_t o1 = (size_t)(r0 + 8) * CD + h * DH + u * 8 + t * 2;
        split2(oacc[u][2] * inv1, oacc[u][3] * inv1, hi, lo);
        *(uint32_t*)&hhi[o1] = hi;
        *(uint32_t*)&hlo[o1] = lo;
    }
}

// ---------------------------------------------------------------------------
// kernel_launch — graph-capturable, allocation-free.
// Inputs: x, Wqkv, bqkv, q_gamma, k_gamma, Wout, bout
// ---------------------------------------------------------------------------
extern "C" void kernel_launch(void* const* d_in, const int* in_sizes, int n_in,
                              void* d_out, int out_size)
{
    const float* x    = (const float*)d_in[0];
    const float* Wqkv = (const float*)d_in[1];
    const float* bqkv = (const float*)d_in[2];
    const float* qg   = (const float*)d_in[3];
    const float* kg   = (const float*)d_in[4];
    const float* Wout = (const float*)d_in[5];
    const float* bout = (const float*)d_in[6];
    float* out = (float*)d_out;

    void* p;
    cudaGetSymbolAddress(&p, g_qkv);  float* qkv = (float*)p;
    cudaGetSymbolAddress(&p, g_xhi);  bf16* xhi = (bf16*)p;
    cudaGetSymbolAddress(&p, g_xlo);  bf16* xlo = (bf16*)p;
    cudaGetSymbolAddress(&p, g_whi);  bf16* whi = (bf16*)p;
    cudaGetSymbolAddress(&p, g_wlo);  bf16* wlo = (bf16*)p;
    cudaGetSymbolAddress(&p, g_ohi);  bf16* ohi = (bf16*)p;
    cudaGetSymbolAddress(&p, g_olo);  bf16* olo = (bf16*)p;
    cudaGetSymbolAddress(&p, g_hhi);  bf16* hhi = (bf16*)p;
    cudaGetSymbolAddress(&p, g_hlo);  bf16* hlo = (bf16*)p;
    cudaGetSymbolAddress(&p, g_qh);   bf16* qh = (bf16*)p;
    cudaGetSymbolAddress(&p, g_ql);   bf16* ql = (bf16*)p;
    cudaGetSymbolAddress(&p, g_kh);   bf16* kh = (bf16*)p;
    cudaGetSymbolAddress(&p, g_kl);   bf16* kl = (bf16*)p;
    cudaGetSymbolAddress(&p, g_vh);   bf16* vh = (bf16*)p;
    cudaGetSymbolAddress(&p, g_vl);   bf16* vl = (bf16*)p;

    cudaFuncSetAttribute(gemm_mma,
                         cudaFuncAttributeMaxDynamicSharedMemorySize, 81920);
    cudaFuncSetAttribute(flash_mma,
                         cudaFuncAttributeMaxDynamicSharedMemorySize, 147456);

    // 0) fp32 -> bf16 hi/lo splits of x and weights (vectorized x4)
    split_kernel<<<(NT * CD / 4 + 255) / 256, 256>>>(x, xhi, xlo, NT * CD / 4);
    split_kernel<<<(3 * CD * CD / 4 + 255) / 256, 256>>>(Wqkv, whi, wlo, 3 * CD * CD / 4);
    split_kernel<<<(CD * CD / 4 + 255) / 256, 256>>>(Wout, ohi, olo, CD * CD / 4);

    // 1) qkv = x @ Wqkv^T + bqkv
    gemm_mma<<<dim3(3 * CD / 128, NT / 128), 256, 81920>>>(
        xhi, xlo, whi, wlo, bqkv, qkv, 3 * CD);

    // 2) rms norm + split to head-major bf16
    post_kernel<<<(NT * NH * 3 * 32) / 256, 256>>>(qkv, qg, kg,
                                                   qh, ql, kh, kl, vh, vl);

    // 3) flash attention -> h (bf16 hi/lo)
    flash_mma<<<dim3(NT / 128, NH), 256, 147456>>>(qh, ql, kh, kl, vh, vl,
                                                   hhi, hlo);

    // 4) out = h @ Wout^T + bout
    gemm_mma<<<dim3(CD / 128, NT / 128), 256, 81920>>>(
        hhi, hlo, ohi, olo, bout, out, CD);
}

// round 6
// speedup vs baseline: 4.1091x; 1.3217x over previous
#include <cuda_runtime.h>
#include <cuda_bf16.h>
#include <cuda_fp16.h>
#include <cstdint>
#include <math.h>

#define NT 4096
#define CD 1024
#define NH 16
#define DH 64

typedef __nv_bfloat16 bf16;

// ---------------- scratch (allocation-free rule) ----------------
__device__ float  g_qkv[NT * 3 * CD];
__device__ bf16   g_xhi[NT * CD],     g_xlo[NT * CD];
__device__ bf16   g_whi[3 * CD * CD], g_wlo[3 * CD * CD];
__device__ bf16   g_ohi[CD * CD],     g_olo[CD * CD];
__device__ bf16   g_hhi[NT * CD],     g_hlo[NT * CD];
// head-major [NH][NT][DH] fp16: q single (pre-scaled), k hi/lo, v hi/lo
__device__ __half g_qf[NT * CD];
__device__ __half g_khf[NT * CD], g_klf[NT * CD];
__device__ __half g_vhf[NT * CD], g_vlf[NT * CD];

// ---------------- helpers ----------------
__device__ __forceinline__ uint32_t smem_u32(const void* p) {
    return (uint32_t)__cvta_generic_to_shared(p);
}
__device__ __forceinline__ void ldsm_x4(uint32_t* r, uint32_t a) {
    asm volatile("ldmatrix.sync.aligned.m8n8.x4.shared.b16 {%0,%1,%2,%3}, [%4];"
                 : "=r"(r[0]), "=r"(r[1]), "=r"(r[2]), "=r"(r[3]) : "r"(a));
}
__device__ __forceinline__ void ldsm_x4_t(uint32_t* r, uint32_t a) {
    asm volatile("ldmatrix.sync.aligned.m8n8.x4.trans.shared.b16 {%0,%1,%2,%3}, [%4];"
                 : "=r"(r[0]), "=r"(r[1]), "=r"(r[2]), "=r"(r[3]) : "r"(a));
}
__device__ __forceinline__ void mma_bf(float* c, const uint32_t* a, const uint32_t* b) {
    asm volatile(
        "mma.sync.aligned.m16n8k16.row.col.f32.bf16.bf16.f32 "
        "{%0,%1,%2,%3}, {%4,%5,%6,%7}, {%8,%9}, {%0,%1,%2,%3};"
        : "+f"(c[0]), "+f"(c[1]), "+f"(c[2]), "+f"(c[3])
        : "r"(a[0]), "r"(a[1]), "r"(a[2]), "r"(a[3]), "r"(b[0]), "r"(b[1]));
}
__device__ __forceinline__ void mma_f16(float* c, const uint32_t* a, const uint32_t* b) {
    asm volatile(
        "mma.sync.aligned.m16n8k16.row.col.f32.f16.f16.f32 "
        "{%0,%1,%2,%3}, {%4,%5,%6,%7}, {%8,%9}, {%0,%1,%2,%3};"
        : "+f"(c[0]), "+f"(c[1]), "+f"(c[2]), "+f"(c[3])
        : "r"(a[0]), "r"(a[1]), "r"(a[2]), "r"(a[3]), "r"(b[0]), "r"(b[1]));
}
__device__ __forceinline__ void split2(float a, float b, uint32_t& hi, uint32_t& lo) {
    __nv_bfloat162 h = __floats2bfloat162_rn(a, b);
    float ra = a - __bfloat162float(h.x);
    float rb = b - __bfloat162float(h.y);
    __nv_bfloat162 l = __floats2bfloat162_rn(ra, rb);
    hi = *(uint32_t*)&h;
    lo = *(uint32_t*)&l;
}
__device__ __forceinline__ void splith2(float a, float b, uint32_t& hi, uint32_t& lo) {
    __half2 h = __floats2half2_rn(a, b);
    float ra = a - __low2float(h);
    float rb = b - __high2float(h);
    __half2 l = __floats2half2_rn(ra, rb);
    hi = *(uint32_t*)&h;
    lo = *(uint32_t*)&l;
}
__device__ __forceinline__ uint32_t packh2(float a, float b) {
    __half2 h = __floats2half2_rn(a, b);
    return *(uint32_t*)&h;
}
__device__ __forceinline__ void cp16(uint32_t dst, const void* src) {
    asm volatile("cp.async.cg.shared.global [%0], [%1], 16;" :: "r"(dst), "l"(src));
}
#define CP_COMMIT() asm volatile("cp.async.commit_group;" ::: "memory")
#define CP_WAIT(n)  asm volatile("cp.async.wait_group %0;" :: "n"(n) : "memory")

// ---------------------------------------------------------------------------
// fp32 -> bf16 hi/lo split (x and weights), 4 elements per thread
// ---------------------------------------------------------------------------
__global__ void split_kernel(const float* __restrict__ in, bf16* __restrict__ hi,
                             bf16* __restrict__ lo, int n4) {
    int i = blockIdx.x * blockDim.x + threadIdx.x;
    if (i < n4) {
        float4 v = ((const float4*)in)[i];
        uint32_t h0, l0, h1, l1;
        split2(v.x, v.y, h0, l0);
        split2(v.z, v.w, h1, l1);
        ((uint2*)hi)[i] = make_uint2(h0, h1);
        ((uint2*)lo)[i] = make_uint2(l0, l1);
    }
}

// ---------------------------------------------------------------------------
// Post-process qkv: per-head RMS norm on q,k; emit head-major fp16:
// q single (pre-scaled by 1/8 fold), k hi/lo, v hi/lo.
// One warp per (token, head, {q,k,v}); lane owns 2 adjacent elements.
// ---------------------------------------------------------------------------
__global__ __launch_bounds__(256)
void post_kernel(const float* __restrict__ qkv,
                 const float* __restrict__ qg, const float* __restrict__ kg,
                 __half* __restrict__ qf,
                 __half* __restrict__ kh, __half* __restrict__ kl,
                 __half* __restrict__ vh, __half* __restrict__ vl)
{
    int w = (blockIdx.x * blockDim.x + threadIdx.x) >> 5;   // 0 .. NT*NH*3-1
    int lane = threadIdx.x & 31;
    int n = w / (NH * 3);
    int rem = w - n * (NH * 3);
    int h = rem / 3, ty = rem - h * 3;                      // 0=q 1=k 2=v

    const float* base = qkv + (size_t)n * (3 * CD) + ty * CD + h * DH;
    float v0 = base[2 * lane], v1 = base[2 * lane + 1];

    if (ty < 2) {
        float ss = v0 * v0 + v1 * v1;
        #pragma unroll
        for (int off = 16; off >= 1; off >>= 1)
            ss += __shfl_xor_sync(0xffffffffu, ss, off);
        float inv = 1.0f / fmaxf(sqrtf(ss), 1e-12f);
        const float* g = (ty == 0) ? qg : kg;
        float gsc = (ty == 0) ? inv : (8.0f * inv);         // q: *8*0.125 = *1
        v0 *= gsc * g[h * DH + 2 * lane];
        v1 *= gsc * g[h * DH + 2 * lane + 1];
    }

    size_t off = (size_t)h * NT * DH + (size_t)n * DH + 2 * lane;
    if (ty == 0) {
        *(uint32_t*)&qf[off] = packh2(v0, v1);
    } else {
        uint32_t hi, lo;
        splith2(v0, v1, hi, lo);
        __half *dh = (ty == 1) ? kh : vh;
        __half *dl = (ty == 1) ? kl : vl;
        *(uint32_t*)&dh[off] = hi;
        *(uint32_t*)&dl[off] = lo;
    }
}

// ---------------------------------------------------------------------------
// MMA GEMM v3: C = (Ahi+Alo) @ (Bhi+Blo)^T + bias. K=1024, 128x128 tile,
// BK=32, 8 warps, warp tile 32x64. 3-stage cp.async, XOR-swizzled tight smem
// (64B rows), ONE __syncthreads per chunk, 2 CTAs/SM.
// dyn smem: 3 stages x (Ah,Al,Bh,Bl) x 8192 B = 98304 B.
// ---------------------------------------------------------------------------
#define G_STG 32768
#define G_ARR 8192
__global__ __launch_bounds__(256, 2)
void gemm_mma(const bf16* __restrict__ Ahi, const bf16* __restrict__ Alo,
              const bf16* __restrict__ Bhi, const bf16* __restrict__ Blo,
              const float* __restrict__ bias, float* __restrict__ C, int Nc)
{
    extern __shared__ char smem[];
    const uint32_t sb = smem_u32(smem);
    const int tid = threadIdx.x, lane = tid & 31, w = tid >> 5;
    const int wm = w >> 1, wn = w & 1;
    const int g = lane >> 2, t = lane & 3;
    const int n0 = blockIdx.x * 128, m0 = blockIdx.y * 128;

    float acc[2][8][4];
    #pragma unroll
    for (int i = 0; i < 2; i++)
        #pragma unroll
        for (int j = 0; j < 8; j++)
            acc[i][j][0] = acc[i][j][1] = acc[i][j][2] = acc[i][j][3] = 0.f;

    const bf16* srcs[4] = {Ahi, Alo, Bhi, Blo};

    auto load_tile = [&](int c, int s) {
        int kt = c * 32;
        #pragma unroll
        for (int p = 0; p < 8; p++) {
            int idx = tid + p * 256;           // 0..2047
            int arr = idx >> 9;                // 0..3
            int rem = idx & 511;
            int row = rem >> 2, sg = rem & 3;
            int base_row = (arr < 2) ? m0 : n0;
            const bf16* src = srcs[arr] + (size_t)(base_row + row) * 1024 + kt + sg * 8;
            cp16(sb + s * G_STG + arr * G_ARR + row * 64 +
                 ((sg ^ ((row >> 1) & 3)) << 4), src);
        }
    };

    load_tile(0, 0); CP_COMMIT();
    load_tile(1, 1); CP_COMMIT();

    for (int c = 0; c < 32; c++) {
        if (c < 31) { CP_WAIT(1); } else { CP_WAIT(0); }
        __syncthreads();
        if (c + 2 < 32) { load_tile(c + 2, (c + 2) % 3); CP_COMMIT(); }

        const uint32_t so = sb + (c % 3) * G_STG;
        #pragma unroll
        for (int kk = 0; kk < 2; kk++) {
            uint32_t ah[2][4], al[2][4];
            #pragma unroll
            for (int mt = 0; mt < 2; mt++) {
                int ar = wm * 32 + mt * 16 + (lane & 15);
                int ch = 2 * kk + ((lane & 16) >> 4);
                uint32_t off = ar * 64 + (((uint32_t)(ch ^ ((ar >> 1) & 3))) << 4);
                ldsm_x4(ah[mt], so + off);
                ldsm_x4(al[mt], so + G_ARR + off);
            }
            #pragma unroll
            for (int u = 0; u < 4; u++) {
                uint32_t bh[4], bl[4];
                int br = wn * 64 + u * 16 + (lane & 7) + ((lane & 16) >> 1);
                int ch = 2 * kk + ((lane & 8) >> 3);
                uint32_t off = br * 64 + (((uint32_t)(ch ^ ((br >> 1) & 3))) << 4);
                ldsm_x4(bh, so + 2 * G_ARR + off);
                ldsm_x4(bl, so + 3 * G_ARR + off);
                #pragma unroll
                for (int mt = 0; mt < 2; mt++) {
                    mma_bf(acc[mt][2 * u],     ah[mt], &bh[0]);
                    mma_bf(acc[mt][2 * u],     al[mt], &bh[0]);
                    mma_bf(acc[mt][2 * u],     ah[mt], &bl[0]);
                    mma_bf(acc[mt][2 * u + 1], ah[mt], &bh[2]);
                    mma_bf(acc[mt][2 * u + 1], al[mt], &bh[2]);
                    mma_bf(acc[mt][2 * u + 1], ah[mt], &bl[2]);
                }
            }
        }
    }

    #pragma unroll
    for (int mt = 0; mt < 2; mt++) {
        int r0 = m0 + wm * 32 + mt * 16 + g;
        #pragma unroll
        for (int nt = 0; nt < 8; nt++) {
            int cc = n0 + wn * 64 + nt * 8 + t * 2;
            float2 bv = *(const float2*)&bias[cc];
            float* a = acc[mt][nt];
            *(float2*)&C[(size_t)r0 * Nc + cc]       = make_float2(a[0] + bv.x, a[1] + bv.y);
            *(float2*)&C[(size_t)(r0 + 8) * Nc + cc] = make_float2(a[2] + bv.x, a[3] + bv.y);
        }
    }
}

// ---------------------------------------------------------------------------
// Flash attention v4: BM=128, BN=64, 8 warps, warp owns 16 rows.
// fp16 asymmetric: S = qf x (kh + kl), PV = P(fp16) x (vh + vl): 2 MMAs each.
// 3-stage cp.async, swizzled tight 128B rows, one sync per iter, 2 CTAs/SM.
// dyn smem: 3 stages x (Kh,Kl,Vh,Vl) x 8192 B = 98304 B.
// ---------------------------------------------------------------------------
#define A_STG 32768
#define A_ARR 8192
#define NIT   (NT / 64)
__global__ __launch_bounds__(256, 2)
void flash_mma(const __half* __restrict__ qfg,
               const __half* __restrict__ khg, const __half* __restrict__ klg,
               const __half* __restrict__ vhg, const __half* __restrict__ vlg,
               bf16* __restrict__ hhi, bf16* __restrict__ hlo)
{
    extern __shared__ char smem[];
    const uint32_t sb = smem_u32(smem);
    const int tid = threadIdx.x, lane = tid & 31, w = tid >> 5;
    const int g = lane >> 2, t = lane & 3;
    const int h = blockIdx.y, q0 = blockIdx.x * 128;
    const size_t hoff = (size_t)h * NT * DH;

    // Q fragments straight from gmem (m16n8k16 A layout, fp16 single)
    uint32_t qa[4][4];
    {
        const __half* r0 = qfg + hoff + (size_t)(q0 + w * 16 + g) * DH;
        const __half* r1 = r0 + 8 * DH;
        #pragma unroll
        for (int kk = 0; kk < 4; kk++) {
            qa[kk][0] = *(const uint32_t*)(r0 + kk * 16 + 2 * t);
            qa[kk][1] = *(const uint32_t*)(r1 + kk * 16 + 2 * t);
            qa[kk][2] = *(const uint32_t*)(r0 + kk * 16 + 8 + 2 * t);
            qa[kk][3] = *(const uint32_t*)(r1 + kk * 16 + 8 + 2 * t);
        }
    }

    const __half* srcs[4] = {khg + hoff, klg + hoff, vhg + hoff, vlg + hoff};

    auto load_tile = [&](int it, int s) {
        int k0 = it * 64;
        #pragma unroll
        for (int arr = 0; arr < 4; arr++) {
            #pragma unroll
            for (int p = 0; p < 2; p++) {
                int idx = tid + p * 256;        // 0..511
                int row = idx >> 3, sg = idx & 7;
                cp16(sb + s * A_STG + arr * A_ARR + row * 128 +
                     ((sg ^ (row & 7)) << 4),
                     srcs[arr] + (size_t)(k0 + row) * DH + sg * 8);
            }
        }
    };

    float mi0 = -1e30f, mi1 = -1e30f, li0 = 0.f, li1 = 0.f;
    float oacc[8][4];
    #pragma unroll
    for (int u = 0; u < 8; u++)
        oacc[u][0] = oacc[u][1] = oacc[u][2] = oacc[u][3] = 0.f;

    load_tile(0, 0); CP_COMMIT();
    load_tile(1, 1); CP_COMMIT();

    for (int it = 0; it < NIT; it++) {
        if (it < NIT - 1) { CP_WAIT(1); } else { CP_WAIT(0); }
        __syncthreads();
        if (it + 2 < NIT) { load_tile(it + 2, (it + 2) % 3); CP_COMMIT(); }

        const uint32_t so = sb + (it % 3) * A_STG;

        // S = Q @ K^T  (16 x 64 per warp)
        float s[8][4];
        #pragma unroll
        for (int j = 0; j < 8; j++)
            s[j][0] = s[j][1] = s[j][2] = s[j][3] = 0.f;

        #pragma unroll
        for (int kk = 0; kk < 4; kk++) {
            #pragma unroll
            for (int u = 0; u < 4; u++) {
                uint32_t bh[4], bl[4];
                int br = u * 16 + (lane & 7) + ((lane & 16) >> 1);
                int ch = 2 * kk + ((lane & 8) >> 3);
                uint32_t off = br * 128 + (((uint32_t)(ch ^ (br & 7))) << 4);
                ldsm_x4(bh, so + off);
                ldsm_x4(bl, so + A_ARR + off);
                mma_f16(s[2 * u],     qa[kk], &bh[0]);
                mma_f16(s[2 * u],     qa[kk], &bl[0]);
                mma_f16(s[2 * u + 1], qa[kk], &bh[2]);
                mma_f16(s[2 * u + 1], qa[kk], &bl[2]);
            }
        }

        // online softmax (rows g and g+8; quad shuffles)
        float rm0 = -1e30f, rm1 = -1e30f;
        #pragma unroll
        for (int j = 0; j < 8; j++) {
            rm0 = fmaxf(rm0, fmaxf(s[j][0], s[j][1]));
            rm1 = fmaxf(rm1, fmaxf(s[j][2], s[j][3]));
        }
        rm0 = fmaxf(rm0, __shfl_xor_sync(0xffffffffu, rm0, 1));
        rm0 = fmaxf(rm0, __shfl_xor_sync(0xffffffffu, rm0, 2));
        rm1 = fmaxf(rm1, __shfl_xor_sync(0xffffffffu, rm1, 1));
        rm1 = fmaxf(rm1, __shfl_xor_sync(0xffffffffu, rm1, 2));

        float mn0 = fmaxf(mi0, rm0), mn1 = fmaxf(mi1, rm1);
        float corr0 = __expf(mi0 - mn0), corr1 = __expf(mi1 - mn1);
        float rs0 = 0.f, rs1 = 0.f;
        #pragma unroll
        for (int j = 0; j < 8; j++) {
            s[j][0] = __expf(s[j][0] - mn0);
            s[j][1] = __expf(s[j][1] - mn0);
            s[j][2] = __expf(s[j][2] - mn1);
            s[j][3] = __expf(s[j][3] - mn1);
            rs0 += s[j][0] + s[j][1];
            rs1 += s[j][2] + s[j][3];
        }
        rs0 += __shfl_xor_sync(0xffffffffu, rs0, 1);
        rs0 += __shfl_xor_sync(0xffffffffu, rs0, 2);
        rs1 += __shfl_xor_sync(0xffffffffu, rs1, 1);
        rs1 += __shfl_xor_sync(0xffffffffu, rs1, 2);

        li0 = li0 * corr0 + rs0;
        li1 = li1 * corr1 + rs1;
        mi0 = mn0; mi1 = mn1;
        #pragma unroll
        for (int u = 0; u < 8; u++) {
            oacc[u][0] *= corr0; oacc[u][1] *= corr0;
            oacc[u][2] *= corr1; oacc[u][3] *= corr1;
        }

        // O += P @ V   (P fp16 single, V hi/lo)
        #pragma unroll
        for (int kv = 0; kv < 4; kv++) {
            uint32_t pa[4];
            pa[0] = packh2(s[2 * kv][0],     s[2 * kv][1]);
            pa[1] = packh2(s[2 * kv][2],     s[2 * kv][3]);
            pa[2] = packh2(s[2 * kv + 1][0], s[2 * kv + 1][1]);
            pa[3] = packh2(s[2 * kv + 1][2], s[2 * kv + 1][3]);
            #pragma unroll
            for (int u = 0; u < 4; u++) {
                uint32_t vh4[4], vl4[4];
                int vr = kv * 16 + (lane & 15);
                int ch = 2 * u + ((lane & 16) >> 4);
                uint32_t off = vr * 128 + (((uint32_t)(ch ^ (vr & 7))) << 4);
                ldsm_x4_t(vh4, so + 2 * A_ARR + off);
                ldsm_x4_t(vl4, so + 3 * A_ARR + off);
                mma_f16(oacc[2 * u],     pa, &vh4[0]);
                mma_f16(oacc[2 * u],     pa, &vl4[0]);
                mma_f16(oacc[2 * u + 1], pa, &vh4[2]);
                mma_f16(oacc[2 * u + 1], pa, &vl4[2]);
            }
        }
    }

    // epilogue: normalize, write h as bf16 hi/lo (row-major [NT][CD])
    float inv0 = 1.0f / li0, inv1 = 1.0f / li1;
    int r0 = q0 + w * 16 + g;
    #pragma unroll
    for (int u = 0; u < 8; u++) {
        uint32_t hi, lo;
        size_t o0 = (size_t)r0 * CD + h * DH + u * 8 + t * 2;
        split2(oacc[u][0] * inv0, oacc[u][1] * inv0, hi, lo);
        *(uint32_t*)&hhi[o0] = hi;
        *(uint32_t*)&hlo[o0] = lo;
        size_t o1 = (size_t)(r0 + 8) * CD + h * DH + u * 8 + t * 2;
        split2(oacc[u][2] * inv1, oacc[u][3] * inv1, hi, lo);
        *(uint32_t*)&hhi[o1] = hi;
        *(uint32_t*)&hlo[o1] = lo;
    }
}

// ---------------------------------------------------------------------------
// kernel_launch — graph-capturable, allocation-free.
// Inputs: x, Wqkv, bqkv, q_gamma, k_gamma, Wout, bout
// ---------------------------------------------------------------------------
extern "C" void kernel_launch(void* const* d_in, const int* in_sizes, int n_in,
                              void* d_out, int out_size)
{
    const float* x    = (const float*)d_in[0];
    const float* Wqkv = (const float*)d_in[1];
    const float* bqkv = (const float*)d_in[2];
    const float* qg   = (const float*)d_in[3];
    const float* kg   = (const float*)d_in[4];
    const float* Wout = (const float*)d_in[5];
    const float* bout = (const float*)d_in[6];
    float* out = (float*)d_out;

    void* p;
    cudaGetSymbolAddress(&p, g_qkv);  float* qkv = (float*)p;
    cudaGetSymbolAddress(&p, g_xhi);  bf16* xhi = (bf16*)p;
    cudaGetSymbolAddress(&p, g_xlo);  bf16* xlo = (bf16*)p;
    cudaGetSymbolAddress(&p, g_whi);  bf16* whi = (bf16*)p;
    cudaGetSymbolAddress(&p, g_wlo);  bf16* wlo = (bf16*)p;
    cudaGetSymbolAddress(&p, g_ohi);  bf16* ohi = (bf16*)p;
    cudaGetSymbolAddress(&p, g_olo);  bf16* olo = (bf16*)p;
    cudaGetSymbolAddress(&p, g_hhi);  bf16* hhi = (bf16*)p;
    cudaGetSymbolAddress(&p, g_hlo);  bf16* hlo = (bf16*)p;
    cudaGetSymbolAddress(&p, g_qf);   __half* qf = (__half*)p;
    cudaGetSymbolAddress(&p, g_khf);  __half* khf = (__half*)p;
    cudaGetSymbolAddress(&p, g_klf);  __half* klf = (__half*)p;
    cudaGetSymbolAddress(&p, g_vhf);  __half* vhf = (__half*)p;
    cudaGetSymbolAddress(&p, g_vlf);  __half* vlf = (__half*)p;

    cudaFuncSetAttribute(gemm_mma,
                         cudaFuncAttributeMaxDynamicSharedMemorySize, 98304);
    cudaFuncSetAttribute(flash_mma,
                         cudaFuncAttributeMaxDynamicSharedMemorySize, 98304);

    // 0) fp32 -> bf16 hi/lo splits of x and weights
    split_kernel<<<(NT * CD / 4 + 255) / 256, 256>>>(x, xhi, xlo, NT * CD / 4);
    split_kernel<<<(3 * CD * CD / 4 + 255) / 256, 256>>>(Wqkv, whi, wlo, 3 * CD * CD / 4);
    split_kernel<<<(CD * CD / 4 + 255) / 256, 256>>>(Wout, ohi, olo, CD * CD / 4);

    // 1) qkv = x @ Wqkv^T + bqkv  (bf16 3-product)
    gemm_mma<<<dim3(3 * CD / 128, NT / 128), 256, 98304>>>(
        xhi, xlo, whi, wlo, bqkv, qkv, 3 * CD);

    // 2) rms norm + fp16 head-major emit
    post_kernel<<<(NT * NH * 3 * 32) / 256, 256>>>(qkv, qg, kg,
                                                   qf, khf, klf, vhf, vlf);

    // 3) flash attention (fp16 2-product) -> h (bf16 hi/lo)
    flash_mma<<<dim3(NT / 128, NH), 256, 98304>>>(qf, khf, klf, vhf, vlf,
                                                  hhi, hlo);

    // 4) out = h @ Wout^T + bout  (bf16 3-product)
    gemm_mma<<<dim3(CD / 128, NT / 128), 256, 98304>>>(
        hhi, hlo, ohi, olo, bout, out, CD);
}

// round 8
// speedup vs baseline: 5.2849x; 1.2862x over previous
#include <cuda_runtime.h>
#include <cuda_bf16.h>
#include <cuda_fp16.h>
#include <cstdint>
#include <math.h>

#define NT 4096
#define CD 1024
#define NH 16
#define DH 64

// ---------------- scratch (allocation-free rule) ----------------
__device__ float  g_qkv[NT * 3 * CD];
__device__ __half g_xh[NT * CD], g_xl[NT * CD];      // x fp16 hi/lo
__device__ __half g_wq[3 * CD * CD];                 // Wqkv fp16 single
__device__ __half g_wo[CD * CD];                     // Wout fp16 single
__device__ __half g_hh[NT * CD], g_hl[NT * CD];      // h fp16 hi/lo
// head-major [NH][NT][DH] fp16: q single (pre-scaled), k single, v hi/lo
__device__ __half g_qf[NT * CD];
__device__ __half g_kf[NT * CD];
__device__ __half g_vh[NT * CD], g_vl[NT * CD];

// ---------------- helpers ----------------
__device__ __forceinline__ uint32_t smem_u32(const void* p) {
    return (uint32_t)__cvta_generic_to_shared(p);
}
__device__ __forceinline__ void ldsm_x4(uint32_t* r, uint32_t a) {
    asm volatile("ldmatrix.sync.aligned.m8n8.x4.shared.b16 {%0,%1,%2,%3}, [%4];"
                 : "=r"(r[0]), "=r"(r[1]), "=r"(r[2]), "=r"(r[3]) : "r"(a));
}
__device__ __forceinline__ void ldsm_x4_t(uint32_t* r, uint32_t a) {
    asm volatile("ldmatrix.sync.aligned.m8n8.x4.trans.shared.b16 {%0,%1,%2,%3}, [%4];"
                 : "=r"(r[0]), "=r"(r[1]), "=r"(r[2]), "=r"(r[3]) : "r"(a));
}
__device__ __forceinline__ void mma_f16(float* c, const uint32_t* a, const uint32_t* b) {
    asm volatile(
        "mma.sync.aligned.m16n8k16.row.col.f32.f16.f16.f32 "
        "{%0,%1,%2,%3}, {%4,%5,%6,%7}, {%8,%9}, {%0,%1,%2,%3};"
        : "+f"(c[0]), "+f"(c[1]), "+f"(c[2]), "+f"(c[3])
        : "r"(a[0]), "r"(a[1]), "r"(a[2]), "r"(a[3]), "r"(b[0]), "r"(b[1]));
}
__device__ __forceinline__ void splith2(float a, float b, uint32_t& hi, uint32_t& lo) {
    __half2 h = __floats2half2_rn(a, b);
    float ra = a - __low2float(h);
    float rb = b - __high2float(h);
    __half2 l = __floats2half2_rn(ra, rb);
    hi = *(uint32_t*)&h;
    lo = *(uint32_t*)&l;
}
__device__ __forceinline__ uint32_t packh2(float a, float b) {
    __half2 h = __floats2half2_rn(a, b);
    return *(uint32_t*)&h;
}
__device__ __forceinline__ void cp16(uint32_t dst, const void* src) {
    asm volatile("cp.async.cg.shared.global [%0], [%1], 16;" :: "r"(dst), "l"(src));
}
#define CP_COMMIT() asm volatile("cp.async.commit_group;" ::: "memory")
#define CP_WAIT(n)  asm volatile("cp.async.wait_group %0;" :: "n"(n) : "memory")

// ---------------------------------------------------------------------------
// fp32 -> fp16 hi/lo split (x), 4 elements per thread
// ---------------------------------------------------------------------------
__global__ void splitx_kernel(const float* __restrict__ in, __half* __restrict__ hi,
                              __half* __restrict__ lo, int n4) {
    int i = blockIdx.x * blockDim.x + threadIdx.x;
    if (i < n4) {
        float4 v = ((const float4*)in)[i];
        uint32_t h0, l0, h1, l1;
        splith2(v.x, v.y, h0, l0);
        splith2(v.z, v.w, h1, l1);
        ((uint2*)hi)[i] = make_uint2(h0, h1);
        ((uint2*)lo)[i] = make_uint2(l0, l1);
    }
}

// ---------------------------------------------------------------------------
// fp32 -> fp16 single convert (weights), 4 elements per thread
// ---------------------------------------------------------------------------
__global__ void conv_kernel(const float* __restrict__ in, __half* __restrict__ outp,
                            int n4) {
    int i = blockIdx.x * blockDim.x + threadIdx.x;
    if (i < n4) {
        float4 v = ((const float4*)in)[i];
        ((uint2*)outp)[i] = make_uint2(packh2(v.x, v.y), packh2(v.z, v.w));
    }
}

// ---------------------------------------------------------------------------
// Post-process qkv: per-head RMS norm on q,k; emit head-major fp16:
// q single (pre-scaled fold), k single, v hi/lo.
// One warp per (token, head, {q,k,v}); lane owns 2 adjacent elements.
// ---------------------------------------------------------------------------
__global__ __launch_bounds__(256)
void post_kernel(const float* __restrict__ qkv,
                 const float* __restrict__ qg, const float* __restrict__ kg,
                 __half* __restrict__ qf, __half* __restrict__ kf,
                 __half* __restrict__ vh, __half* __restrict__ vl)
{
    int w = (blockIdx.x * blockDim.x + threadIdx.x) >> 5;   // 0 .. NT*NH*3-1
    int lane = threadIdx.x & 31;
    int n = w / (NH * 3);
    int rem = w - n * (NH * 3);
    int h = rem / 3, ty = rem - h * 3;                      // 0=q 1=k 2=v

    const float* base = qkv + (size_t)n * (3 * CD) + ty * CD + h * DH;
    float v0 = base[2 * lane], v1 = base[2 * lane + 1];

    if (ty < 2) {
        float ss = v0 * v0 + v1 * v1;
        #pragma unroll
        for (int off = 16; off >= 1; off >>= 1)
            ss += __shfl_xor_sync(0xffffffffu, ss, off);
        float inv = 1.0f / fmaxf(sqrtf(ss), 1e-12f);
        const float* g = (ty == 0) ? qg : kg;
        float gsc = (ty == 0) ? inv : (8.0f * inv);         // q: *8*0.125 = *1
        v0 *= gsc * g[h * DH + 2 * lane];
        v1 *= gsc * g[h * DH + 2 * lane + 1];
    }

    size_t off = (size_t)h * NT * DH + (size_t)n * DH + 2 * lane;
    if (ty == 0) {
        *(uint32_t*)&qf[off] = packh2(v0, v1);
    } else if (ty == 1) {
        *(uint32_t*)&kf[off] = packh2(v0, v1);
    } else {
        uint32_t hi, lo;
        splith2(v0, v1, hi, lo);
        *(uint32_t*)&vh[off] = hi;
        *(uint32_t*)&vl[off] = lo;
    }
}

// ---------------------------------------------------------------------------
// MMA GEMM v4: C = (Ahi+Alo) @ B^T + bias. fp16, 2 products. K=1024,
// 128x128 tile, BK=32, 8 warps, warp tile 32x64. 3-stage cp.async,
// XOR-swizzled tight smem (64B rows), one sync per chunk, 2 CTAs/SM.
// dyn smem: 3 stages x (Ah,Al,B) x 8192 B = 73728 B.
// ---------------------------------------------------------------------------
#define G_STG 24576
#define G_ARR 8192
__global__ __launch_bounds__(256, 2)
void gemm_mma(const __half* __restrict__ Ahi, const __half* __restrict__ Alo,
              const __half* __restrict__ B,
              const float* __restrict__ bias, float* __restrict__ C, int Nc)
{
    extern __shared__ char smem[];
    const uint32_t sb = smem_u32(smem);
    const int tid = threadIdx.x, lane = tid & 31, w = tid >> 5;
    const int wm = w >> 1, wn = w & 1;
    const int g = lane >> 2, t = lane & 3;
    const int n0 = blockIdx.x * 128, m0 = blockIdx.y * 128;

    float acc[2][8][4];
    #pragma unroll
    for (int i = 0; i < 2; i++)
        #pragma unroll
        for (int j = 0; j < 8; j++)
            acc[i][j][0] = acc[i][j][1] = acc[i][j][2] = acc[i][j][3] = 0.f;

    const __half* srcs[3] = {Ahi, Alo, B};

    auto load_tile = [&](int c, int s) {
        int kt = c * 32;
        #pragma unroll
        for (int p = 0; p < 6; p++) {
            int idx = tid + p * 256;           // 0..1535
            int arr = idx >> 9;                // 0..2
            int rem = idx & 511;
            int row = rem >> 2, sg = rem & 3;
            int base_row = (arr < 2) ? m0 : n0;
            const __half* src = srcs[arr] + (size_t)(base_row + row) * 1024 + kt + sg * 8;
            cp16(sb + s * G_STG + arr * G_ARR + row * 64 +
                 ((sg ^ ((row >> 1) & 3)) << 4), src);
        }
    };

    load_tile(0, 0); CP_COMMIT();
    load_tile(1, 1); CP_COMMIT();

    for (int c = 0; c < 32; c++) {
        if (c < 31) { CP_WAIT(1); } else { CP_WAIT(0); }
        __syncthreads();
        if (c + 2 < 32) { load_tile(c + 2, (c + 2) % 3); CP_COMMIT(); }

        const uint32_t so = sb + (c % 3) * G_STG;
        #pragma unroll
        for (int kk = 0; kk < 2; kk++) {
            uint32_t ah[2][4], al[2][4];
            #pragma unroll
            for (int mt = 0; mt < 2; mt++) {
                int ar = wm * 32 + mt * 16 + (lane & 15);
                int ch = 2 * kk + ((lane & 16) >> 4);
                uint32_t off = ar * 64 + (((uint32_t)(ch ^ ((ar >> 1) & 3))) << 4);
                ldsm_x4(ah[mt], so + off);
                ldsm_x4(al[mt], so + G_ARR + off);
            }
            #pragma unroll
            for (int u = 0; u < 4; u++) {
                uint32_t bh[4];
                int br = wn * 64 + u * 16 + (lane & 7) + ((lane & 16) >> 1);
                int ch = 2 * kk + ((lane & 8) >> 3);
                uint32_t off = br * 64 + (((uint32_t)(ch ^ ((br >> 1) & 3))) << 4);
                ldsm_x4(bh, so + 2 * G_ARR + off);
                #pragma unroll
                for (int mt = 0; mt < 2; mt++) {
                    mma_f16(acc[mt][2 * u],     ah[mt], &bh[0]);
                    mma_f16(acc[mt][2 * u],     al[mt], &bh[0]);
                    mma_f16(acc[mt][2 * u + 1], ah[mt], &bh[2]);
                    mma_f16(acc[mt][2 * u + 1], al[mt], &bh[2]);
                }
            }
        }
    }

    #pragma unroll
    for (int mt = 0; mt < 2; mt++) {
        int r0 = m0 + wm * 32 + mt * 16 + g;
        #pragma unroll
        for (int nt = 0; nt < 8; nt++) {
            int cc = n0 + wn * 64 + nt * 8 + t * 2;
            float2 bv = *(const float2*)&bias[cc];
            float* a = acc[mt][nt];
            *(float2*)&C[(size_t)r0 * Nc + cc]       = make_float2(a[0] + bv.x, a[1] + bv.y);
            *(float2*)&C[(size_t)(r0 + 8) * Nc + cc] = make_float2(a[2] + bv.x, a[3] + bv.y);
        }
    }
}

// ---------------------------------------------------------------------------
// Flash attention v5: BM=128, BN=64, 8 warps, warp owns 16 rows.
// S = q(fp16) x k(fp16): 1 MMA. PV = P(fp16) x (vh + vl): 2 MMAs.
// 3-stage cp.async, swizzled tight 128B rows, one sync per iter, 2 CTAs/SM.
// dyn smem: 3 stages x (K,Vh,Vl) x 8192 B = 73728 B.
// Epilogue writes h as fp16 hi/lo for the out-proj GEMM.
// ---------------------------------------------------------------------------
#define A_STG 24576
#define A_ARR 8192
#define NIT   (NT / 64)
__global__ __launch_bounds__(256, 2)
void flash_mma(const __half* __restrict__ qfg, const __half* __restrict__ kfg,
               const __half* __restrict__ vhg, const __half* __restrict__ vlg,
               __half* __restrict__ hhi, __half* __restrict__ hlo)
{
    extern __shared__ char smem[];
    const uint32_t sb = smem_u32(smem);
    const int tid = threadIdx.x, lane = tid & 31, w = tid >> 5;
    const int g = lane >> 2, t = lane & 3;
    const int h = blockIdx.y, q0 = blockIdx.x * 128;
    const size_t hoff = (size_t)h * NT * DH;

    // Q fragments straight from gmem (m16n8k16 A layout, fp16 single)
    uint32_t qa[4][4];
    {
        const __half* r0 = qfg + hoff + (size_t)(q0 + w * 16 + g) * DH;
        const __half* r1 = r0 + 8 * DH;
        #pragma unroll
        for (int kk = 0; kk < 4; kk++) {
            qa[kk][0] = *(const uint32_t*)(r0 + kk * 16 + 2 * t);
            qa[kk][1] = *(const uint32_t*)(r1 + kk * 16 + 2 * t);
            qa[kk][2] = *(const uint32_t*)(r0 + kk * 16 + 8 + 2 * t);
            qa[kk][3] = *(const uint32_t*)(r1 + kk * 16 + 8 + 2 * t);
        }
    }

    const __half* srcs[3] = {kfg + hoff, vhg + hoff, vlg + hoff};

    auto load_tile = [&](int it, int s) {
        int k0 = it * 64;
        #pragma unroll
        for (int p = 0; p < 6; p++) {
            int idx = tid + p * 256;            // 0..1535
            int arr = idx >> 9;                 // 0..2
            int rem = idx & 511;
            int row = rem >> 3, sg = rem & 7;
            cp16(sb + s * A_STG + arr * A_ARR + row * 128 +
                 ((sg ^ (row & 7)) << 4),
                 srcs[arr] + (size_t)(k0 + row) * DH + sg * 8);
        }
    };

    float mi0 = -1e30f, mi1 = -1e30f, li0 = 0.f, li1 = 0.f;
    float oacc[8][4];
    #pragma unroll
    for (int u = 0; u < 8; u++)
        oacc[u][0] = oacc[u][1] = oacc[u][2] = oacc[u][3] = 0.f;

    load_tile(0, 0); CP_COMMIT();
    load_tile(1, 1); CP_COMMIT();

    for (int it = 0; it < NIT; it++) {
        if (it < NIT - 1) { CP_WAIT(1); } else { CP_WAIT(0); }
        __syncthreads();
        if (it + 2 < NIT) { load_tile(it + 2, (it + 2) % 3); CP_COMMIT(); }

        const uint32_t so = sb + (it % 3) * A_STG;

        // S = Q @ K^T  (16 x 64 per warp, single product)
        float s[8][4];
        #pragma unroll
        for (int j = 0; j < 8; j++)
            s[j][0] = s[j][1] = s[j][2] = s[j][3] = 0.f;

        #pragma unroll
        for (int kk = 0; kk < 4; kk++) {
            #pragma unroll
            for (int u = 0; u < 4; u++) {
                uint32_t bh[4];
                int br = u * 16 + (lane & 7) + ((lane & 16) >> 1);
                int ch = 2 * kk + ((lane & 8) >> 3);
                uint32_t off = br * 128 + (((uint32_t)(ch ^ (br & 7))) << 4);
                ldsm_x4(bh, so + off);
                mma_f16(s[2 * u],     qa[kk], &bh[0]);
                mma_f16(s[2 * u + 1], qa[kk], &bh[2]);
            }
        }

        // online softmax (rows g and g+8; quad shuffles)
        float rm0 = -1e30f, rm1 = -1e30f;
        #pragma unroll
        for (int j = 0; j < 8; j++) {
            rm0 = fmaxf(rm0, fmaxf(s[j][0], s[j][1]));
            rm1 = fmaxf(rm1, fmaxf(s[j][2], s[j][3]));
        }
        rm0 = fmaxf(rm0, __shfl_xor_sync(0xffffffffu, rm0, 1));
        rm0 = fmaxf(rm0, __shfl_xor_sync(0xffffffffu, rm0, 2));
        rm1 = fmaxf(rm1, __shfl_xor_sync(0xffffffffu, rm1, 1));
        rm1 = fmaxf(rm1, __shfl_xor_sync(0xffffffffu, rm1, 2));

        float mn0 = fmaxf(mi0, rm0), mn1 = fmaxf(mi1, rm1);
        float corr0 = __expf(mi0 - mn0), corr1 = __expf(mi1 - mn1);
        float rs0 = 0.f, rs1 = 0.f;
        #pragma unroll
        for (int j = 0; j < 8; j++) {
            s[j][0] = __expf(s[j][0] - mn0);
            s[j][1] = __expf(s[j][1] - mn0);
            s[j][2] = __expf(s[j][2] - mn1);
            s[j][3] = __expf(s[j][3] - mn1);
            rs0 += s[j][0] + s[j][1];
            rs1 += s[j][2] + s[j][3];
        }
        rs0 += __shfl_xor_sync(0xffffffffu, rs0, 1);
        rs0 += __shfl_xor_sync(0xffffffffu, rs0, 2);
        rs1 += __shfl_xor_sync(0xffffffffu, rs1, 1);
        rs1 += __shfl_xor_sync(0xffffffffu, rs1, 2);

        li0 = li0 * corr0 + rs0;
        li1 = li1 * corr1 + rs1;
        mi0 = mn0; mi1 = mn1;
        #pragma unroll
        for (int u = 0; u < 8; u++) {
            oacc[u][0] *= corr0; oacc[u][1] *= corr0;
            oacc[u][2] *= corr1; oacc[u][3] *= corr1;
        }

        // O += P @ V   (P fp16 single, V hi/lo)
        #pragma unroll
        for (int kv = 0; kv < 4; kv++) {
            uint32_t pa[4];
            pa[0] = packh2(s[2 * kv][0],     s[2 * kv][1]);
            pa[1] = packh2(s[2 * kv][2],     s[2 * kv][3]);
            pa[2] = packh2(s[2 * kv + 1][0], s[2 * kv + 1][1]);
            pa[3] = packh2(s[2 * kv + 1][2], s[2 * kv + 1][3]);
            #pragma unroll
            for (int u = 0; u < 4; u++) {
                uint32_t vh4[4], vl4[4];
                int vr = kv * 16 + (lane & 15);
                int ch = 2 * u + ((lane & 16) >> 4);
                uint32_t off = vr * 128 + (((uint32_t)(ch ^ (vr & 7))) << 4);
                ldsm_x4_t(vh4, so + 1 * A_ARR + off);
                ldsm_x4_t(vl4, so + 2 * A_ARR + off);
                mma_f16(oacc[2 * u],     pa, &vh4[0]);
                mma_f16(oacc[2 * u],     pa, &vl4[0]);
                mma_f16(oacc[2 * u + 1], pa, &vh4[2]);
                mma_f16(oacc[2 * u + 1], pa, &vl4[2]);
            }
        }
    }

    // epilogue: normalize, write h as fp16 hi/lo (row-major [NT][CD])
    float inv0 = 1.0f / li0, inv1 = 1.0f / li1;
    int r0 = q0 + w * 16 + g;
    #pragma unroll
    for (int u = 0; u < 8; u++) {
        uint32_t hi, lo;
        size_t o0 = (size_t)r0 * CD + h * DH + u * 8 + t * 2;
        splith2(oacc[u][0] * inv0, oacc[u][1] * inv0, hi, lo);
        *(uint32_t*)&hhi[o0] = hi;
        *(uint32_t*)&hlo[o0] = lo;
        size_t o1 = (size_t)(r0 + 8) * CD + h * DH + u * 8 + t * 2;
        splith2(oacc[u][2] * inv1, oacc[u][3] * inv1, hi, lo);
        *(uint32_t*)&hhi[o1] = hi;
        *(uint32_t*)&hlo[o1] = lo;
    }
}

// ---------------------------------------------------------------------------
// kernel_launch — graph-capturable, allocation-free.
// Inputs: x, Wqkv, bqkv, q_gamma, k_gamma, Wout, bout
// ---------------------------------------------------------------------------
extern "C" void kernel_launch(void* const* d_in, const int* in_sizes, int n_in,
                              void* d_out, int out_size)
{
    const float* x    = (const float*)d_in[0];
    const float* Wqkv = (const float*)d_in[1];
    const float* bqkv = (const float*)d_in[2];
    const float* qg   = (const float*)d_in[3];
    const float* kg   = (const float*)d_in[4];
    const float* Wout = (const float*)d_in[5];
    const float* bout = (const float*)d_in[6];
    float* out = (float*)d_out;

    void* p;
    cudaGetSymbolAddress(&p, g_qkv); float*  qkv = (float*)p;
    cudaGetSymbolAddress(&p, g_xh);  __half* xh  = (__half*)p;
    cudaGetSymbolAddress(&p, g_xl);  __half* xl  = (__half*)p;
    cudaGetSymbolAddress(&p, g_wq);  __half* wq  = (__half*)p;
    cudaGetSymbolAddress(&p, g_wo);  __half* wo  = (__half*)p;
    cudaGetSymbolAddress(&p, g_hh);  __half* hh  = (__half*)p;
    cudaGetSymbolAddress(&p, g_hl);  __half* hl  = (__half*)p;
    cudaGetSymbolAddress(&p, g_qf);  __half* qf  = (__half*)p;
    cudaGetSymbolAddress(&p, g_kf);  __half* kf  = (__half*)p;
    cudaGetSymbolAddress(&p, g_vh);  __half* vh  = (__half*)p;
    cudaGetSymbolAddress(&p, g_vl);  __half* vl  = (__half*)p;

    cudaFuncSetAttribute(gemm_mma,
                         cudaFuncAttributeMaxDynamicSharedMemorySize, 73728);
    cudaFuncSetAttribute(flash_mma,
                         cudaFuncAttributeMaxDynamicSharedMemorySize, 73728);

    // 0) prep: x -> fp16 hi/lo, weights -> fp16 single
    splitx_kernel<<<(NT * CD / 4 + 255) / 256, 256>>>(x, xh, xl, NT * CD / 4);
    conv_kernel<<<(3 * CD * CD / 4 + 255) / 256, 256>>>(Wqkv, wq, 3 * CD * CD / 4);
    conv_kernel<<<(CD * CD / 4 + 255) / 256, 256>>>(Wout, wo, CD * CD / 4);

    // 1) qkv = x @ Wqkv^T + bqkv  (fp16 2-product)
    gemm_mma<<<dim3(3 * CD / 128, NT / 128), 256, 73728>>>(
        xh, xl, wq, bqkv, qkv, 3 * CD);

    // 2) rms norm + fp16 head-major emit (q single, k single, v hi/lo)
    post_kernel<<<(NT * NH * 3 * 32) / 256, 256>>>(qkv, qg, kg, qf, kf, vh, vl);

    // 3) flash attention -> h (fp16 hi/lo)
    flash_mma<<<dim3(NT / 128, NH), 256, 73728>>>(qf, kf, vh, vl, hh, hl);

    // 4) out = h @ Wout^T + bout  (fp16 2-product)
    gemm_mma<<<dim3(CD / 128, NT / 128), 256, 73728>>>(
        hh, hl, wo, bout, out, CD);
}

// round 9
// speedup vs baseline: 6.1443x; 1.1626x over previous
#include <cuda_runtime.h>
#include <cuda_bf16.h>
#include <cuda_fp16.h>
#include <cstdint>
#include <math.h>

#define NT 4096
#define CD 1024
#define NH 16
#define DH 64

// ---------------- scratch (allocation-free rule) ----------------
__device__ float  g_qkv[NT * 3 * CD];
__device__ __half g_xh[NT * CD], g_xl[NT * CD];      // x fp16 hi/lo
__device__ __half g_wq[3 * CD * CD];                 // Wqkv fp16 single
__device__ __half g_wo[CD * CD];                     // Wout fp16 single
__device__ __half g_hh[NT * CD], g_hl[NT * CD];      // h fp16 hi/lo
// head-major [NH][NT][DH] fp16 singles: q (pre-scaled), k, v
__device__ __half g_qf[NT * CD];
__device__ __half g_kf[NT * CD];
__device__ __half g_vf[NT * CD];

// ---------------- helpers ----------------
__device__ __forceinline__ uint32_t smem_u32(const void* p) {
    return (uint32_t)__cvta_generic_to_shared(p);
}
__device__ __forceinline__ void ldsm_x4(uint32_t* r, uint32_t a) {
    asm volatile("ldmatrix.sync.aligned.m8n8.x4.shared.b16 {%0,%1,%2,%3}, [%4];"
                 : "=r"(r[0]), "=r"(r[1]), "=r"(r[2]), "=r"(r[3]) : "r"(a));
}
__device__ __forceinline__ void ldsm_x4_t(uint32_t* r, uint32_t a) {
    asm volatile("ldmatrix.sync.aligned.m8n8.x4.trans.shared.b16 {%0,%1,%2,%3}, [%4];"
                 : "=r"(r[0]), "=r"(r[1]), "=r"(r[2]), "=r"(r[3]) : "r"(a));
}
__device__ __forceinline__ void mma_f16(float* c, const uint32_t* a, const uint32_t* b) {
    asm volatile(
        "mma.sync.aligned.m16n8k16.row.col.f32.f16.f16.f32 "
        "{%0,%1,%2,%3}, {%4,%5,%6,%7}, {%8,%9}, {%0,%1,%2,%3};"
        : "+f"(c[0]), "+f"(c[1]), "+f"(c[2]), "+f"(c[3])
        : "r"(a[0]), "r"(a[1]), "r"(a[2]), "r"(a[3]), "r"(b[0]), "r"(b[1]));
}
__device__ __forceinline__ void splith2(float a, float b, uint32_t& hi, uint32_t& lo) {
    __half2 h = __floats2half2_rn(a, b);
    float ra = a - __low2float(h);
    float rb = b - __high2float(h);
    __half2 l = __floats2half2_rn(ra, rb);
    hi = *(uint32_t*)&h;
    lo = *(uint32_t*)&l;
}
__device__ __forceinline__ uint32_t packh2(float a, float b) {
    __half2 h = __floats2half2_rn(a, b);
    return *(uint32_t*)&h;
}
__device__ __forceinline__ void cp16(uint32_t dst, const void* src) {
    asm volatile("cp.async.cg.shared.global [%0], [%1], 16;" :: "r"(dst), "l"(src));
}
#define CP_COMMIT() asm volatile("cp.async.commit_group;" ::: "memory")
#define CP_WAIT(n)  asm volatile("cp.async.wait_group %0;" :: "n"(n) : "memory")

// ---------------------------------------------------------------------------
// Merged prep: x -> fp16 hi/lo split; Wqkv, Wout -> fp16 single.
// One grid; branch by flat index range. 4 fp32 elements per thread.
// ---------------------------------------------------------------------------
#define NX4  (NT * CD / 4)
#define NWQ4 (3 * CD * CD / 4)
#define NWO4 (CD * CD / 4)
__global__ __launch_bounds__(256)
void prep_kernel(const float* __restrict__ x, const float* __restrict__ Wqkv,
                 const float* __restrict__ Wout,
                 __half* __restrict__ xh, __half* __restrict__ xl,
                 __half* __restrict__ wq, __half* __restrict__ wo)
{
    int i = blockIdx.x * blockDim.x + threadIdx.x;
    if (i < NX4) {
        float4 v = ((const float4*)x)[i];
        uint32_t h0, l0, h1, l1;
        splith2(v.x, v.y, h0, l0);
        splith2(v.z, v.w, h1, l1);
        ((uint2*)xh)[i] = make_uint2(h0, h1);
        ((uint2*)xl)[i] = make_uint2(l0, l1);
    } else if (i < NX4 + NWQ4) {
        int j = i - NX4;
        float4 v = ((const float4*)Wqkv)[j];
        ((uint2*)wq)[j] = make_uint2(packh2(v.x, v.y), packh2(v.z, v.w));
    } else {
        int j = i - NX4 - NWQ4;
        float4 v = ((const float4*)Wout)[j];
        ((uint2*)wo)[j] = make_uint2(packh2(v.x, v.y), packh2(v.z, v.w));
    }
}

// ---------------------------------------------------------------------------
// Post-process qkv: per-head RMS norm on q,k; emit head-major fp16 singles.
// One warp per (token, head, {q,k,v}); lane owns 2 adjacent elements.
// ---------------------------------------------------------------------------
__global__ __launch_bounds__(256)
void post_kernel(const float* __restrict__ qkv,
                 const float* __restrict__ qg, const float* __restrict__ kg,
                 __half* __restrict__ qf, __half* __restrict__ kf,
                 __half* __restrict__ vf)
{
    int w = (blockIdx.x * blockDim.x + threadIdx.x) >> 5;   // 0 .. NT*NH*3-1
    int lane = threadIdx.x & 31;
    int n = w / (NH * 3);
    int rem = w - n * (NH * 3);
    int h = rem / 3, ty = rem - h * 3;                      // 0=q 1=k 2=v

    const float* base = qkv + (size_t)n * (3 * CD) + ty * CD + h * DH;
    float v0 = base[2 * lane], v1 = base[2 * lane + 1];

    if (ty < 2) {
        float ss = v0 * v0 + v1 * v1;
        #pragma unroll
        for (int off = 16; off >= 1; off >>= 1)
            ss += __shfl_xor_sync(0xffffffffu, ss, off);
        float inv = 1.0f / fmaxf(sqrtf(ss), 1e-12f);
        const float* g = (ty == 0) ? qg : kg;
        float gsc = (ty == 0) ? inv : (8.0f * inv);         // q: *8*0.125 = *1
        v0 *= gsc * g[h * DH + 2 * lane];
        v1 *= gsc * g[h * DH + 2 * lane + 1];
    }

    size_t off = (size_t)h * NT * DH + (size_t)n * DH + 2 * lane;
    __half* dst = (ty == 0) ? qf : (ty == 1) ? kf : vf;
    *(uint32_t*)&dst[off] = packh2(v0, v1);
}

// ---------------------------------------------------------------------------
// MMA GEMM v4 (unchanged): C = (Ahi+Alo) @ B^T + bias. fp16, 2 products.
// K=1024, 128x128 tile, BK=32, 8 warps, 3-stage cp.async, 2 CTAs/SM.
// dyn smem: 3 stages x (Ah,Al,B) x 8192 B = 73728 B.
// ---------------------------------------------------------------------------
#define G_STG 24576
#define G_ARR 8192
__global__ __launch_bounds__(256, 2)
void gemm_mma(const __half* __restrict__ Ahi, const __half* __restrict__ Alo,
              const __half* __restrict__ B,
              const float* __restrict__ bias, float* __restrict__ C, int Nc)
{
    extern __shared__ char smem[];
    const uint32_t sb = smem_u32(smem);
    const int tid = threadIdx.x, lane = tid & 31, w = tid >> 5;
    const int wm = w >> 1, wn = w & 1;
    const int g = lane >> 2, t = lane & 3;
    const int n0 = blockIdx.x * 128, m0 = blockIdx.y * 128;

    float acc[2][8][4];
    #pragma unroll
    for (int i = 0; i < 2; i++)
        #pragma unroll
        for (int j = 0; j < 8; j++)
            acc[i][j][0] = acc[i][j][1] = acc[i][j][2] = acc[i][j][3] = 0.f;

    const __half* srcs[3] = {Ahi, Alo, B};

    auto load_tile = [&](int c, int s) {
        int kt = c * 32;
        #pragma unroll
        for (int p = 0; p < 6; p++) {
            int idx = tid + p * 256;           // 0..1535
            int arr = idx >> 9;                // 0..2
            int rem = idx & 511;
            int row = rem >> 2, sg = rem & 3;
            int base_row = (arr < 2) ? m0 : n0;
            const __half* src = srcs[arr] + (size_t)(base_row + row) * 1024 + kt + sg * 8;
            cp16(sb + s * G_STG + arr * G_ARR + row * 64 +
                 ((sg ^ ((row >> 1) & 3)) << 4), src);
        }
    };

    load_tile(0, 0); CP_COMMIT();
    load_tile(1, 1); CP_COMMIT();

    for (int c = 0; c < 32; c++) {
        if (c < 31) { CP_WAIT(1); } else { CP_WAIT(0); }
        __syncthreads();
        if (c + 2 < 32) { load_tile(c + 2, (c + 2) % 3); CP_COMMIT(); }

        const uint32_t so = sb + (c % 3) * G_STG;
        #pragma unroll
        for (int kk = 0; kk < 2; kk++) {
            uint32_t ah[2][4], al[2][4];
            #pragma unroll
            for (int mt = 0; mt < 2; mt++) {
                int ar = wm * 32 + mt * 16 + (lane & 15);
                int ch = 2 * kk + ((lane & 16) >> 4);
                uint32_t off = ar * 64 + (((uint32_t)(ch ^ ((ar >> 1) & 3))) << 4);
                ldsm_x4(ah[mt], so + off);
                ldsm_x4(al[mt], so + G_ARR + off);
            }
            #pragma unroll
            for (int u = 0; u < 4; u++) {
                uint32_t bh[4];
                int br = wn * 64 + u * 16 + (lane & 7) + ((lane & 16) >> 1);
                int ch = 2 * kk + ((lane & 8) >> 3);
                uint32_t off = br * 64 + (((uint32_t)(ch ^ ((br >> 1) & 3))) << 4);
                ldsm_x4(bh, so + 2 * G_ARR + off);
                #pragma unroll
                for (int mt = 0; mt < 2; mt++) {
                    mma_f16(acc[mt][2 * u],     ah[mt], &bh[0]);
                    mma_f16(acc[mt][2 * u],     al[mt], &bh[0]);
                    mma_f16(acc[mt][2 * u + 1], ah[mt], &bh[2]);
                    mma_f16(acc[mt][2 * u + 1], al[mt], &bh[2]);
                }
            }
        }
    }

    #pragma unroll
    for (int mt = 0; mt < 2; mt++) {
        int r0 = m0 + wm * 32 + mt * 16 + g;
        #pragma unroll
        for (int nt = 0; nt < 8; nt++) {
            int cc = n0 + wn * 64 + nt * 8 + t * 2;
            float2 bv = *(const float2*)&bias[cc];
            float* a = acc[mt][nt];
            *(float2*)&C[(size_t)r0 * Nc + cc]       = make_float2(a[0] + bv.x, a[1] + bv.y);
            *(float2*)&C[(size_t)(r0 + 8) * Nc + cc] = make_float2(a[2] + bv.x, a[3] + bv.y);
        }
    }
}

// ---------------------------------------------------------------------------
// Flash attention v6: BM=128, BN=64, 8 warps, warp owns 16 rows.
// S = q x k: 1 MMA. PV = P x v: 1 MMA (all fp16 single).
// 3-stage cp.async, swizzled tight 128B rows, one sync per iter, 2 CTAs/SM.
// dyn smem: 3 stages x (K,V) x 8192 B = 49152 B.
// Epilogue writes h as fp16 hi/lo for the out-proj GEMM.
// ---------------------------------------------------------------------------
#define A_STG 16384
#define A_ARR 8192
#define NIT   (NT / 64)
__global__ __launch_bounds__(256, 2)
void flash_mma(const __half* __restrict__ qfg, const __half* __restrict__ kfg,
               const __half* __restrict__ vfg,
               __half* __restrict__ hhi, __half* __restrict__ hlo)
{
    extern __shared__ char smem[];
    const uint32_t sb = smem_u32(smem);
    const int tid = threadIdx.x, lane = tid & 31, w = tid >> 5;
    const int g = lane >> 2, t = lane & 3;
    const int h = blockIdx.y, q0 = blockIdx.x * 128;
    const size_t hoff = (size_t)h * NT * DH;

    // Q fragments straight from gmem (m16n8k16 A layout, fp16 single)
    uint32_t qa[4][4];
    {
        const __half* r0 = qfg + hoff + (size_t)(q0 + w * 16 + g) * DH;
        const __half* r1 = r0 + 8 * DH;
        #pragma unroll
        for (int kk = 0; kk < 4; kk++) {
            qa[kk][0] = *(const uint32_t*)(r0 + kk * 16 + 2 * t);
            qa[kk][1] = *(const uint32_t*)(r1 + kk * 16 + 2 * t);
            qa[kk][2] = *(const uint32_t*)(r0 + kk * 16 + 8 + 2 * t);
            qa[kk][3] = *(const uint32_t*)(r1 + kk * 16 + 8 + 2 * t);
        }
    }

    const __half* srcs[2] = {kfg + hoff, vfg + hoff};

    auto load_tile = [&](int it, int s) {
        int k0 = it * 64;
        #pragma unroll
        for (int p = 0; p < 4; p++) {
            int idx = tid + p * 256;            // 0..1023
            int arr = idx >> 9;                 // 0..1
            int rem = idx & 511;
            int row = rem >> 3, sg = rem & 7;
            cp16(sb + s * A_STG + arr * A_ARR + row * 128 +
                 ((sg ^ (row & 7)) << 4),
                 srcs[arr] + (size_t)(k0 + row) * DH + sg * 8);
        }
    };

    float mi0 = -1e30f, mi1 = -1e30f, li0 = 0.f, li1 = 0.f;
    float oacc[8][4];
    #pragma unroll
    for (int u = 0; u < 8; u++)
        oacc[u][0] = oacc[u][1] = oacc[u][2] = oacc[u][3] = 0.f;

    load_tile(0, 0); CP_COMMIT();
    load_tile(1, 1); CP_COMMIT();

    for (int it = 0; it < NIT; it++) {
        if (it < NIT - 1) { CP_WAIT(1); } else { CP_WAIT(0); }
        __syncthreads();
        if (it + 2 < NIT) { load_tile(it + 2, (it + 2) % 3); CP_COMMIT(); }

        const uint32_t so = sb + (it % 3) * A_STG;

        // S = Q @ K^T  (16 x 64 per warp, single product)
        float s[8][4];
        #pragma unroll
        for (int j = 0; j < 8; j++)
            s[j][0] = s[j][1] = s[j][2] = s[j][3] = 0.f;

        #pragma unroll
        for (int kk = 0; kk < 4; kk++) {
            #pragma unroll
            for (int u = 0; u < 4; u++) {
                uint32_t bh[4];
                int br = u * 16 + (lane & 7) + ((lane & 16) >> 1);
                int ch = 2 * kk + ((lane & 8) >> 3);
                uint32_t off = br * 128 + (((uint32_t)(ch ^ (br & 7))) << 4);
                ldsm_x4(bh, so + off);
                mma_f16(s[2 * u],     qa[kk], &bh[0]);
                mma_f16(s[2 * u + 1], qa[kk], &bh[2]);
            }
        }

        // online softmax (rows g and g+8; quad shuffles)
        float rm0 = -1e30f, rm1 = -1e30f;
        #pragma unroll
        for (int j = 0; j < 8; j++) {
            rm0 = fmaxf(rm0, fmaxf(s[j][0], s[j][1]));
            rm1 = fmaxf(rm1, fmaxf(s[j][2], s[j][3]));
        }
        rm0 = fmaxf(rm0, __shfl_xor_sync(0xffffffffu, rm0, 1));
        rm0 = fmaxf(rm0, __shfl_xor_sync(0xffffffffu, rm0, 2));
        rm1 = fmaxf(rm1, __shfl_xor_sync(0xffffffffu, rm1, 1));
        rm1 = fmaxf(rm1, __shfl_xor_sync(0xffffffffu, rm1, 2));

        float mn0 = fmaxf(mi0, rm0), mn1 = fmaxf(mi1, rm1);
        float corr0 = __expf(mi0 - mn0), corr1 = __expf(mi1 - mn1);
        float rs0 = 0.f, rs1 = 0.f;
        #pragma unroll
        for (int j = 0; j < 8; j++) {
            s[j][0] = __expf(s[j][0] - mn0);
            s[j][1] = __expf(s[j][1] - mn0);
            s[j][2] = __expf(s[j][2] - mn1);
            s[j][3] = __expf(s[j][3] - mn1);
            rs0 += s[j][0] + s[j][1];
            rs1 += s[j][2] + s[j][3];
        }
        rs0 += __shfl_xor_sync(0xffffffffu, rs0, 1);
        rs0 += __shfl_xor_sync(0xffffffffu, rs0, 2);
        rs1 += __shfl_xor_sync(0xffffffffu, rs1, 1);
        rs1 += __shfl_xor_sync(0xffffffffu, rs1, 2);

        li0 = li0 * corr0 + rs0;
        li1 = li1 * corr1 + rs1;
        mi0 = mn0; mi1 = mn1;
        #pragma unroll
        for (int u = 0; u < 8; u++) {
            oacc[u][0] *= corr0; oacc[u][1] *= corr0;
            oacc[u][2] *= corr1; oacc[u][3] *= corr1;
        }

        // O += P @ V   (single product)
        #pragma unroll
        for (int kv = 0; kv < 4; kv++) {
            uint32_t pa[4];
            pa[0] = packh2(s[2 * kv][0],     s[2 * kv][1]);
            pa[1] = packh2(s[2 * kv][2],     s[2 * kv][3]);
            pa[2] = packh2(s[2 * kv + 1][0], s[2 * kv + 1][1]);
            pa[3] = packh2(s[2 * kv + 1][2], s[2 * kv + 1][3]);
            #pragma unroll
            for (int u = 0; u < 4; u++) {
                uint32_t vh4[4];
                int vr = kv * 16 + (lane & 15);
                int ch = 2 * u + ((lane & 16) >> 4);
                uint32_t off = vr * 128 + (((uint32_t)(ch ^ (vr & 7))) << 4);
                ldsm_x4_t(vh4, so + A_ARR + off);
                mma_f16(oacc[2 * u],     pa, &vh4[0]);
                mma_f16(oacc[2 * u + 1], pa, &vh4[2]);
            }
        }
    }

    // epilogue: normalize, write h as fp16 hi/lo (row-major [NT][CD])
    float inv0 = 1.0f / li0, inv1 = 1.0f / li1;
    int r0 = q0 + w * 16 + g;
    #pragma unroll
    for (int u = 0; u < 8; u++) {
        uint32_t hi, lo;
        size_t o0 = (size_t)r0 * CD + h * DH + u * 8 + t * 2;
        splith2(oacc[u][0] * inv0, oacc[u][1] * inv0, hi, lo);
        *(uint32_t*)&hhi[o0] = hi;
        *(uint32_t*)&hlo[o0] = lo;
        size_t o1 = (size_t)(r0 + 8) * CD + h * DH + u * 8 + t * 2;
        splith2(oacc[u][2] * inv1, oacc[u][3] * inv1, hi, lo);
        *(uint32_t*)&hhi[o1] = hi;
        *(uint32_t*)&hlo[o1] = lo;
    }
}

// ---------------------------------------------------------------------------
// kernel_launch — graph-capturable, allocation-free.
// Inputs: x, Wqkv, bqkv, q_gamma, k_gamma, Wout, bout
// ---------------------------------------------------------------------------
extern "C" void kernel_launch(void* const* d_in, const int* in_sizes, int n_in,
                              void* d_out, int out_size)
{
    const float* x    = (const float*)d_in[0];
    const float* Wqkv = (const float*)d_in[1];
    const float* bqkv = (const float*)d_in[2];
    const float* qg   = (const float*)d_in[3];
    const float* kg   = (const float*)d_in[4];
    const float* Wout = (const float*)d_in[5];
    const float* bout = (const float*)d_in[6];
    float* out = (float*)d_out;

    void* p;
    cudaGetSymbolAddress(&p, g_qkv); float*  qkv = (float*)p;
    cudaGetSymbolAddress(&p, g_xh);  __half* xh  = (__half*)p;
    cudaGetSymbolAddress(&p, g_xl);  __half* xl  = (__half*)p;
    cudaGetSymbolAddress(&p, g_wq);  __half* wq  = (__half*)p;
    cudaGetSymbolAddress(&p, g_wo);  __half* wo  = (__half*)p;
    cudaGetSymbolAddress(&p, g_hh);  __half* hh  = (__half*)p;
    cudaGetSymbolAddress(&p, g_hl);  __half* hl  = (__half*)p;
    cudaGetSymbolAddress(&p, g_qf);  __half* qf  = (__half*)p;
    cudaGetSymbolAddress(&p, g_kf);  __half* kf  = (__half*)p;
    cudaGetSymbolAddress(&p, g_vf);  __half* vf  = (__half*)p;

    cudaFuncSetAttribute(gemm_mma,
                         cudaFuncAttributeMaxDynamicSharedMemorySize, 73728);
    cudaFuncSetAttribute(flash_mma,
                         cudaFuncAttributeMaxDynamicSharedMemorySize, 49152);

    // 0) merged prep: x -> fp16 hi/lo, weights -> fp16 single
    prep_kernel<<<(NX4 + NWQ4 + NWO4) / 256, 256>>>(x, Wqkv, Wout,
                                                    xh, xl, wq, wo);

    // 1) qkv = x @ Wqkv^T + bqkv  (fp16 2-product)
    gemm_mma<<<dim3(3 * CD / 128, NT / 128), 256, 73728>>>(
        xh, xl, wq, bqkv, qkv, 3 * CD);

    // 2) rms norm + fp16 head-major emit (q, k, v all single)
    post_kernel<<<(NT * NH * 3 * 32) / 256, 256>>>(qkv, qg, kg, qf, kf, vf);

    // 3) flash attention -> h (fp16 hi/lo)
    flash_mma<<<dim3(NT / 128, NH), 256, 49152>>>(qf, kf, vf, hh, hl);

    // 4) out = h @ Wout^T + bout  (fp16 2-product)
    gemm_mma<<<dim3(CD / 128, NT / 128), 256, 73728>>>(
        hh, hl, wo, bout, out, CD);
}

// round 10
// speedup vs baseline: 6.3417x; 1.0321x over previous
#include <cuda_runtime.h>
#include <cuda_bf16.h>
#include <cuda_fp16.h>
#include <cstdint>
#include <math.h>

#define NT 4096
#define CD 1024
#define NH 16
#define DH 64
#define LOG2E 1.4426950408889634f

// ---------------- scratch (allocation-free rule) ----------------
__device__ float  g_qkv[NT * 3 * CD];
__device__ __half g_xh[NT * CD], g_xl[NT * CD];      // x fp16 hi/lo
__device__ __half g_wq[3 * CD * CD];                 // Wqkv fp16 single
__device__ __half g_wo[CD * CD];                     // Wout fp16 single
__device__ __half g_hh[NT * CD], g_hl[NT * CD];      // h fp16 hi/lo
// head-major [NH][NT][DH] fp16 singles: q (pre-scaled by log2e/8-fold), k, v
__device__ __half g_qf[NT * CD];
__device__ __half g_kf[NT * CD];
__device__ __half g_vf[NT * CD];
__device__ float  g_kmax[NH];                        // per-head max ||k||

// ---------------- helpers ----------------
__device__ __forceinline__ uint32_t smem_u32(const void* p) {
    return (uint32_t)__cvta_generic_to_shared(p);
}
__device__ __forceinline__ void ldsm_x4(uint32_t* r, uint32_t a) {
    asm volatile("ldmatrix.sync.aligned.m8n8.x4.shared.b16 {%0,%1,%2,%3}, [%4];"
                 : "=r"(r[0]), "=r"(r[1]), "=r"(r[2]), "=r"(r[3]) : "r"(a));
}
__device__ __forceinline__ void ldsm_x4_t(uint32_t* r, uint32_t a) {
    asm volatile("ldmatrix.sync.aligned.m8n8.x4.trans.shared.b16 {%0,%1,%2,%3}, [%4];"
                 : "=r"(r[0]), "=r"(r[1]), "=r"(r[2]), "=r"(r[3]) : "r"(a));
}
__device__ __forceinline__ void mma_f16(float* c, const uint32_t* a, const uint32_t* b) {
    asm volatile(
        "mma.sync.aligned.m16n8k16.row.col.f32.f16.f16.f32 "
        "{%0,%1,%2,%3}, {%4,%5,%6,%7}, {%8,%9}, {%0,%1,%2,%3};"
        : "+f"(c[0]), "+f"(c[1]), "+f"(c[2]), "+f"(c[3])
        : "r"(a[0]), "r"(a[1]), "r"(a[2]), "r"(a[3]), "r"(b[0]), "r"(b[1]));
}
__device__ __forceinline__ void splith2(float a, float b, uint32_t& hi, uint32_t& lo) {
    __half2 h = __floats2half2_rn(a, b);
    float ra = a - __low2float(h);
    float rb = b - __high2float(h);
    __half2 l = __floats2half2_rn(ra, rb);
    hi = *(uint32_t*)&h;
    lo = *(uint32_t*)&l;
}
__device__ __forceinline__ uint32_t packh2(float a, float b) {
    __half2 h = __floats2half2_rn(a, b);
    return *(uint32_t*)&h;
}
__device__ __forceinline__ float ex2f(float x) {
    float y;
    asm("ex2.approx.f32 %0, %1;" : "=f"(y) : "f"(x));
    return y;
}
__device__ __forceinline__ void cp16(uint32_t dst, const void* src) {
    asm volatile("cp.async.cg.shared.global [%0], [%1], 16;" :: "r"(dst), "l"(src));
}
#define CP_COMMIT() asm volatile("cp.async.commit_group;" ::: "memory")
#define CP_WAIT(n)  asm volatile("cp.async.wait_group %0;" :: "n"(n) : "memory")

// ---------------------------------------------------------------------------
// Merged prep: x -> fp16 hi/lo split; Wqkv, Wout -> fp16 single.
// ---------------------------------------------------------------------------
#define NX4  (NT * CD / 4)
#define NWQ4 (3 * CD * CD / 4)
#define NWO4 (CD * CD / 4)
__global__ __launch_bounds__(256)
void prep_kernel(const float* __restrict__ x, const float* __restrict__ Wqkv,
                 const float* __restrict__ Wout,
                 __half* __restrict__ xh, __half* __restrict__ xl,
                 __half* __restrict__ wq, __half* __restrict__ wo)
{
    int i = blockIdx.x * blockDim.x + threadIdx.x;
    if (i < NX4) {
        float4 v = ((const float4*)x)[i];
        uint32_t h0, l0, h1, l1;
        splith2(v.x, v.y, h0, l0);
        splith2(v.z, v.w, h1, l1);
        ((uint2*)xh)[i] = make_uint2(h0, h1);
        ((uint2*)xl)[i] = make_uint2(l0, l1);
    } else if (i < NX4 + NWQ4) {
        int j = i - NX4;
        float4 v = ((const float4*)Wqkv)[j];
        ((uint2*)wq)[j] = make_uint2(packh2(v.x, v.y), packh2(v.z, v.w));
    } else {
        int j = i - NX4 - NWQ4;
        float4 v = ((const float4*)Wout)[j];
        ((uint2*)wo)[j] = make_uint2(packh2(v.x, v.y), packh2(v.z, v.w));
    }
}

// ---------------------------------------------------------------------------
// Post-process qkv: per-head RMS norm on q,k; emit head-major fp16 singles.
// q folded with log2(e) (score scale 1/8 folded as before). k rows also
// contribute ||k|| to per-head atomic max (for the softmax shift bound).
// ---------------------------------------------------------------------------
__global__ __launch_bounds__(256)
void post_kernel(const float* __restrict__ qkv,
                 const float* __restrict__ qg, const float* __restrict__ kg,
                 __half* __restrict__ qf, __half* __restrict__ kf,
                 __half* __restrict__ vf, float* __restrict__ kmax)
{
    int w = (blockIdx.x * blockDim.x + threadIdx.x) >> 5;   // 0 .. NT*NH*3-1
    int lane = threadIdx.x & 31;
    int n = w / (NH * 3);
    int rem = w - n * (NH * 3);
    int h = rem / 3, ty = rem - h * 3;                      // 0=q 1=k 2=v

    const float* base = qkv + (size_t)n * (3 * CD) + ty * CD + h * DH;
    float v0 = base[2 * lane], v1 = base[2 * lane + 1];

    if (ty < 2) {
        float ss = v0 * v0 + v1 * v1;
        #pragma unroll
        for (int off = 16; off >= 1; off >>= 1)
            ss += __shfl_xor_sync(0xffffffffu, ss, off);
        float inv = 1.0f / fmaxf(sqrtf(ss), 1e-12f);
        const float* g = (ty == 0) ? qg : kg;
        // q: (1/||q||) * gamma * (8 * 0.125 = 1) * log2e ;  k: 8/||k|| * gamma
        float gsc = (ty == 0) ? (inv * LOG2E) : (8.0f * inv);
        v0 *= gsc * g[h * DH + 2 * lane];
        v1 *= gsc * g[h * DH + 2 * lane + 1];
        if (ty == 1) {
            float ss2 = v0 * v0 + v1 * v1;
            #pragma unroll
            for (int off = 16; off >= 1; off >>= 1)
                ss2 += __shfl_xor_sync(0xffffffffu, ss2, off);
            if (lane == 0)
                atomicMax((int*)&kmax[h], __float_as_int(sqrtf(ss2)));
        }
    }

    size_t off = (size_t)h * NT * DH + (size_t)n * DH + 2 * lane;
    __half* dst = (ty == 0) ? qf : (ty == 1) ? kf : vf;
    *(uint32_t*)&dst[off] = packh2(v0, v1);
}

// ---------------------------------------------------------------------------
// MMA GEMM v4 (unchanged): C = (Ahi+Alo) @ B^T + bias. fp16, 2 products.
// ---------------------------------------------------------------------------
#define G_STG 24576
#define G_ARR 8192
__global__ __launch_bounds__(256, 2)
void gemm_mma(const __half* __restrict__ Ahi, const __half* __restrict__ Alo,
              const __half* __restrict__ B,
              const float* __restrict__ bias, float* __restrict__ C, int Nc)
{
    extern __shared__ char smem[];
    const uint32_t sb = smem_u32(smem);
    const int tid = threadIdx.x, lane = tid & 31, w = tid >> 5;
    const int wm = w >> 1, wn = w & 1;
    const int g = lane >> 2, t = lane & 3;
    const int n0 = blockIdx.x * 128, m0 = blockIdx.y * 128;

    float acc[2][8][4];
    #pragma unroll
    for (int i = 0; i < 2; i++)
        #pragma unroll
        for (int j = 0; j < 8; j++)
            acc[i][j][0] = acc[i][j][1] = acc[i][j][2] = acc[i][j][3] = 0.f;

    const __half* srcs[3] = {Ahi, Alo, B};

    auto load_tile = [&](int c, int s) {
        int kt = c * 32;
        #pragma unroll
        for (int p = 0; p < 6; p++) {
            int idx = tid + p * 256;           // 0..1535
            int arr = idx >> 9;                // 0..2
            int rem = idx & 511;
            int row = rem >> 2, sg = rem & 3;
            int base_row = (arr < 2) ? m0 : n0;
            const __half* src = srcs[arr] + (size_t)(base_row + row) * 1024 + kt + sg * 8;
            cp16(sb + s * G_STG + arr * G_ARR + row * 64 +
                 ((sg ^ ((row >> 1) & 3)) << 4), src);
        }
    };

    load_tile(0, 0); CP_COMMIT();
    load_tile(1, 1); CP_COMMIT();

    for (int c = 0; c < 32; c++) {
        if (c < 31) { CP_WAIT(1); } else { CP_WAIT(0); }
        __syncthreads();
        if (c + 2 < 32) { load_tile(c + 2, (c + 2) % 3); CP_COMMIT(); }

        const uint32_t so = sb + (c % 3) * G_STG;
        #pragma unroll
        for (int kk = 0; kk < 2; kk++) {
            uint32_t ah[2][4], al[2][4];
            #pragma unroll
            for (int mt = 0; mt < 2; mt++) {
                int ar = wm * 32 + mt * 16 + (lane & 15);
                int ch = 2 * kk + ((lane & 16) >> 4);
                uint32_t off = ar * 64 + (((uint32_t)(ch ^ ((ar >> 1) & 3))) << 4);
                ldsm_x4(ah[mt], so + off);
                ldsm_x4(al[mt], so + G_ARR + off);
            }
            #pragma unroll
            for (int u = 0; u < 4; u++) {
                uint32_t bh[4];
                int br = wn * 64 + u * 16 + (lane & 7) + ((lane & 16) >> 1);
                int ch = 2 * kk + ((lane & 8) >> 3);
                uint32_t off = br * 64 + (((uint32_t)(ch ^ ((br >> 1) & 3))) << 4);
                ldsm_x4(bh, so + 2 * G_ARR + off);
                #pragma unroll
                for (int mt = 0; mt < 2; mt++) {
                    mma_f16(acc[mt][2 * u],     ah[mt], &bh[0]);
                    mma_f16(acc[mt][2 * u],     al[mt], &bh[0]);
                    mma_f16(acc[mt][2 * u + 1], ah[mt], &bh[2]);
                    mma_f16(acc[mt][2 * u + 1], al[mt], &bh[2]);
                }
            }
        }
    }

    #pragma unroll
    for (int mt = 0; mt < 2; mt++) {
        int r0 = m0 + wm * 32 + mt * 16 + g;
        #pragma unroll
        for (int nt = 0; nt < 8; nt++) {
            int cc = n0 + wn * 64 + nt * 8 + t * 2;
            float2 bv = *(const float2*)&bias[cc];
            float* a = acc[mt][nt];
            *(float2*)&C[(size_t)r0 * Nc + cc]       = make_float2(a[0] + bv.x, a[1] + bv.y);
            *(float2*)&C[(size_t)(r0 + 8) * Nc + cc] = make_float2(a[2] + bv.x, a[3] + bv.y);
        }
    }
}

// ---------------------------------------------------------------------------
// Flash attention v7: fixed-shift softmax (b = ||q_row||*max||k||, Cauchy-
// Schwarz bound; shift cancels mathematically). No running max, no O rescale,
// no per-iter shuffles. S init = -b (free subtract via MMA accumulate),
// P = ex2(s). l accumulated per-thread, quad-reduced once at end.
// BM=128, BN=64, 8 warps, 3-stage cp.async, 2 CTAs/SM.
// ---------------------------------------------------------------------------
#define A_STG 16384
#define A_ARR 8192
#define NIT   (NT / 64)
__global__ __launch_bounds__(256, 2)
void flash_mma(const __half* __restrict__ qfg, const __half* __restrict__ kfg,
               const __half* __restrict__ vfg, const float* __restrict__ kmaxp,
               __half* __restrict__ hhi, __half* __restrict__ hlo)
{
    extern __shared__ char smem[];
    const uint32_t sb = smem_u32(smem);
    const int tid = threadIdx.x, lane = tid & 31, w = tid >> 5;
    const int g = lane >> 2, t = lane & 3;
    const int h = blockIdx.y, q0 = blockIdx.x * 128;
    const size_t hoff = (size_t)h * NT * DH;

    // Q fragments straight from gmem (m16n8k16 A layout, fp16 single)
    uint32_t qa[4][4];
    {
        const __half* r0 = qfg + hoff + (size_t)(q0 + w * 16 + g) * DH;
        const __half* r1 = r0 + 8 * DH;
        #pragma unroll
        for (int kk = 0; kk < 4; kk++) {
            qa[kk][0] = *(const uint32_t*)(r0 + kk * 16 + 2 * t);
            qa[kk][1] = *(const uint32_t*)(r1 + kk * 16 + 2 * t);
            qa[kk][2] = *(const uint32_t*)(r0 + kk * 16 + 8 + 2 * t);
            qa[kk][3] = *(const uint32_t*)(r1 + kk * 16 + 8 + 2 * t);
        }
    }

    // per-row softmax shift b = ||q_row|| * max||k||  (Cauchy-Schwarz bound)
    float qn0 = 0.f, qn1 = 0.f;
    #pragma unroll
    for (int kk = 0; kk < 4; kk++) {
        float2 f;
        f = __half22float2(*(__half2*)&qa[kk][0]); qn0 += f.x * f.x + f.y * f.y;
        f = __half22float2(*(__half2*)&qa[kk][2]); qn0 += f.x * f.x + f.y * f.y;
        f = __half22float2(*(__half2*)&qa[kk][1]); qn1 += f.x * f.x + f.y * f.y;
        f = __half22float2(*(__half2*)&qa[kk][3]); qn1 += f.x * f.x + f.y * f.y;
    }
    qn0 += __shfl_xor_sync(0xffffffffu, qn0, 1);
    qn0 += __shfl_xor_sync(0xffffffffu, qn0, 2);
    qn1 += __shfl_xor_sync(0xffffffffu, qn1, 1);
    qn1 += __shfl_xor_sync(0xffffffffu, qn1, 2);
    float km = kmaxp[h];
    float b0 = sqrtf(qn0) * km, b1 = sqrtf(qn1) * km;

    const __half* srcs[2] = {kfg + hoff, vfg + hoff};

    auto load_tile = [&](int it, int s) {
        int k0 = it * 64;
        #pragma unroll
        for (int p = 0; p < 4; p++) {
            int idx = tid + p * 256;            // 0..1023
            int arr = idx >> 9;                 // 0..1
            int rem = idx & 511;
            int row = rem >> 3, sg = rem & 7;
            cp16(sb + s * A_STG + arr * A_ARR + row * 128 +
                 ((sg ^ (row & 7)) << 4),
                 srcs[arr] + (size_t)(k0 + row) * DH + sg * 8);
        }
    };

    float l0 = 0.f, l1 = 0.f;
    float oacc[8][4];
    #pragma unroll
    for (int u = 0; u < 8; u++)
        oacc[u][0] = oacc[u][1] = oacc[u][2] = oacc[u][3] = 0.f;

    load_tile(0, 0); CP_COMMIT();
    load_tile(1, 1); CP_COMMIT();

    for (int it = 0; it < NIT; it++) {
        if (it < NIT - 1) { CP_WAIT(1); } else { CP_WAIT(0); }
        __syncthreads();
        if (it + 2 < NIT) { load_tile(it + 2, (it + 2) % 3); CP_COMMIT(); }

        const uint32_t so = sb + (it % 3) * A_STG;

        // S = Q @ K^T - b  (b folded into accumulator init)
        float s[8][4];
        #pragma unroll
        for (int j = 0; j < 8; j++) {
            s[j][0] = -b0; s[j][1] = -b0;
            s[j][2] = -b1; s[j][3] = -b1;
        }

        #pragma unroll
        for (int kk = 0; kk < 4; kk++) {
            #pragma unroll
            for (int u = 0; u < 4; u++) {
                uint32_t bh[4];
                int br = u * 16 + (lane & 7) + ((lane & 16) >> 1);
                int ch = 2 * kk + ((lane & 8) >> 3);
                uint32_t off = br * 128 + (((uint32_t)(ch ^ (br & 7))) << 4);
                ldsm_x4(bh, so + off);
                mma_f16(s[2 * u],     qa[kk], &bh[0]);
                mma_f16(s[2 * u + 1], qa[kk], &bh[2]);
            }
        }

        // P = 2^s (s <= 0 guaranteed); accumulate l; O += P @ V
        #pragma unroll
        for (int kv = 0; kv < 4; kv++) {
            float e00 = ex2f(s[2 * kv][0]),     e01 = ex2f(s[2 * kv][1]);
            float e02 = ex2f(s[2 * kv][2]),     e03 = ex2f(s[2 * kv][3]);
            float e10 = ex2f(s[2 * kv + 1][0]), e11 = ex2f(s[2 * kv + 1][1]);
            float e12 = ex2f(s[2 * kv + 1][2]), e13 = ex2f(s[2 * kv + 1][3]);
            l0 += (e00 + e01) + (e10 + e11);
            l1 += (e02 + e03) + (e12 + e13);
            uint32_t pa[4];
            pa[0] = packh2(e00, e01);
            pa[1] = packh2(e02, e03);
            pa[2] = packh2(e10, e11);
            pa[3] = packh2(e12, e13);
            #pragma unroll
            for (int u = 0; u < 4; u++) {
                uint32_t vh4[4];
                int vr = kv * 16 + (lane & 15);
                int ch = 2 * u + ((lane & 16) >> 4);
                uint32_t off = vr * 128 + (((uint32_t)(ch ^ (vr & 7))) << 4);
                ldsm_x4_t(vh4, so + A_ARR + off);
                mma_f16(oacc[2 * u],     pa, &vh4[0]);
                mma_f16(oacc[2 * u + 1], pa, &vh4[2]);
            }
        }
    }

    // single final reduction of l across the quad
    l0 += __shfl_xor_sync(0xffffffffu, l0, 1);
    l0 += __shfl_xor_sync(0xffffffffu, l0, 2);
    l1 += __shfl_xor_sync(0xffffffffu, l1, 1);
    l1 += __shfl_xor_sync(0xffffffffu, l1, 2);

    // epilogue: normalize, write h as fp16 hi/lo (row-major [NT][CD])
    float inv0 = 1.0f / l0, inv1 = 1.0f / l1;
    int r0 = q0 + w * 16 + g;
    #pragma unroll
    for (int u = 0; u < 8; u++) {
        uint32_t hi, lo;
        size_t o0 = (size_t)r0 * CD + h * DH + u * 8 + t * 2;
        splith2(oacc[u][0] * inv0, oacc[u][1] * inv0, hi, lo);
        *(uint32_t*)&hhi[o0] = hi;
        *(uint32_t*)&hlo[o0] = lo;
        size_t o1 = (size_t)(r0 + 8) * CD + h * DH + u * 8 + t * 2;
        splith2(oacc[u][2] * inv1, oacc[u][3] * inv1, hi, lo);
        *(uint32_t*)&hhi[o1] = hi;
        *(uint32_t*)&hlo[o1] = lo;
    }
}

// ---------------------------------------------------------------------------
// kernel_launch — graph-capturable, allocation-free.
// Inputs: x, Wqkv, bqkv, q_gamma, k_gamma, Wout, bout
// ---------------------------------------------------------------------------
extern "C" void kernel_launch(void* const* d_in, const int* in_sizes, int n_in,
                              void* d_out, int out_size)
{
    const float* x    = (const float*)d_in[0];
    const float* Wqkv = (const float*)d_in[1];
    const float* bqkv = (const float*)d_in[2];
    const float* qg   = (const float*)d_in[3];
    const float* kg   = (const float*)d_in[4];
    const float* Wout = (const float*)d_in[5];
    const float* bout = (const float*)d_in[6];
    float* out = (float*)d_out;

    void* p;
    cudaGetSymbolAddress(&p, g_qkv);  float*  qkv  = (float*)p;
    cudaGetSymbolAddress(&p, g_xh);   __half* xh   = (__half*)p;
    cudaGetSymbolAddress(&p, g_xl);   __half* xl   = (__half*)p;
    cudaGetSymbolAddress(&p, g_wq);   __half* wq   = (__half*)p;
    cudaGetSymbolAddress(&p, g_wo);   __half* wo   = (__half*)p;
    cudaGetSymbolAddress(&p, g_hh);   __half* hh   = (__half*)p;
    cudaGetSymbolAddress(&p, g_hl);   __half* hl   = (__half*)p;
    cudaGetSymbolAddress(&p, g_qf);   __half* qf   = (__half*)p;
    cudaGetSymbolAddress(&p, g_kf);   __half* kf   = (__half*)p;
    cudaGetSymbolAddress(&p, g_vf);   __half* vf   = (__half*)p;
    cudaGetSymbolAddress(&p, g_kmax); float*  kmax = (float*)p;

    cudaFuncSetAttribute(gemm_mma,
                         cudaFuncAttributeMaxDynamicSharedMemorySize, 73728);
    cudaFuncSetAttribute(flash_mma,
                         cudaFuncAttributeMaxDynamicSharedMemorySize, 49152);

    // 0) merged prep + zero per-head kmax
    cudaMemsetAsync(kmax, 0, NH * sizeof(float), 0);
    prep_kernel<<<(NX4 + NWQ4 + NWO4) / 256, 256>>>(x, Wqkv, Wout,
                                                    xh, xl, wq, wo);

    // 1) qkv = x @ Wqkv^T + bqkv  (fp16 2-product)
    gemm_mma<<<dim3(3 * CD / 128, NT / 128), 256, 73728>>>(
        xh, xl, wq, bqkv, qkv, 3 * CD);

    // 2) rms norm + fp16 head-major emit + per-head max||k||
    post_kernel<<<(NT * NH * 3 * 32) / 256, 256>>>(qkv, qg, kg, qf, kf, vf, kmax);

    // 3) flash attention (fixed-shift softmax) -> h (fp16 hi/lo)
    flash_mma<<<dim3(NT / 128, NH), 256, 49152>>>(qf, kf, vf, kmax, hh, hl);

    // 4) out = h @ Wout^T + bout  (fp16 2-product)
    gemm_mma<<<dim3(CD / 128, NT / 128), 256, 73728>>>(
        hh, hl, wo, bout, out, CD);
}

// round 11
// speedup vs baseline: 6.8176x; 1.0750x over previous
#include <cuda_runtime.h>
#include <cuda_bf16.h>
#include <cuda_fp16.h>
#include <cstdint>
#include <math.h>

#define NT 4096
#define CD 1024
#define NH 16
#define DH 64
#define LOG2E 1.4426950408889634f

// ---------------- scratch (allocation-free rule) ----------------
__device__ float  g_qkv[NT * 3 * CD];
__device__ __half g_xh[NT * CD], g_xl[NT * CD];      // x fp16 hi/lo
__device__ __half g_wq[3 * CD * CD];                 // Wqkv fp16 single
__device__ __half g_wo[CD * CD];                     // Wout fp16 single
__device__ __half g_hh[NT * CD];                     // h fp16 single
// head-major [NH][NT][DH] fp16 singles: q (pre-scaled by log2e/8-fold), k, v
__device__ __half g_qf[NT * CD];
__device__ __half g_kf[NT * CD];
__device__ __half g_vf[NT * CD];
__device__ float  g_kmax[NH];                        // per-head max ||k||

// ---------------- helpers ----------------
__device__ __forceinline__ uint32_t smem_u32(const void* p) {
    return (uint32_t)__cvta_generic_to_shared(p);
}
__device__ __forceinline__ void ldsm_x4(uint32_t* r, uint32_t a) {
    asm volatile("ldmatrix.sync.aligned.m8n8.x4.shared.b16 {%0,%1,%2,%3}, [%4];"
                 : "=r"(r[0]), "=r"(r[1]), "=r"(r[2]), "=r"(r[3]) : "r"(a));
}
__device__ __forceinline__ void ldsm_x4_t(uint32_t* r, uint32_t a) {
    asm volatile("ldmatrix.sync.aligned.m8n8.x4.trans.shared.b16 {%0,%1,%2,%3}, [%4];"
                 : "=r"(r[0]), "=r"(r[1]), "=r"(r[2]), "=r"(r[3]) : "r"(a));
}
__device__ __forceinline__ void mma_f16(float* c, const uint32_t* a, const uint32_t* b) {
    asm volatile(
        "mma.sync.aligned.m16n8k16.row.col.f32.f16.f16.f32 "
        "{%0,%1,%2,%3}, {%4,%5,%6,%7}, {%8,%9}, {%0,%1,%2,%3};"
        : "+f"(c[0]), "+f"(c[1]), "+f"(c[2]), "+f"(c[3])
        : "r"(a[0]), "r"(a[1]), "r"(a[2]), "r"(a[3]), "r"(b[0]), "r"(b[1]));
}
__device__ __forceinline__ void splith2(float a, float b, uint32_t& hi, uint32_t& lo) {
    __half2 h = __floats2half2_rn(a, b);
    float ra = a - __low2float(h);
    float rb = b - __high2float(h);
    __half2 l = __floats2half2_rn(ra, rb);
    hi = *(uint32_t*)&h;
    lo = *(uint32_t*)&l;
}
__device__ __forceinline__ uint32_t packh2(float a, float b) {
    __half2 h = __floats2half2_rn(a, b);
    return *(uint32_t*)&h;
}
__device__ __forceinline__ float ex2f(float x) {
    float y;
    asm("ex2.approx.f32 %0, %1;" : "=f"(y) : "f"(x));
    return y;
}
__device__ __forceinline__ void cp16(uint32_t dst, const void* src) {
    asm volatile("cp.async.cg.shared.global [%0], [%1], 16;" :: "r"(dst), "l"(src));
}
#define CP_COMMIT() asm volatile("cp.async.commit_group;" ::: "memory")
#define CP_WAIT(n)  asm volatile("cp.async.wait_group %0;" :: "n"(n) : "memory")

// ---------------------------------------------------------------------------
// Merged prep: x -> fp16 hi/lo split; Wqkv, Wout -> fp16 single.
// ---------------------------------------------------------------------------
#define NX4  (NT * CD / 4)
#define NWQ4 (3 * CD * CD / 4)
#define NWO4 (CD * CD / 4)
__global__ __launch_bounds__(256)
void prep_kernel(const float* __restrict__ x, const float* __restrict__ Wqkv,
                 const float* __restrict__ Wout,
                 __half* __restrict__ xh, __half* __restrict__ xl,
                 __half* __restrict__ wq, __half* __restrict__ wo)
{
    int i = blockIdx.x * blockDim.x + threadIdx.x;
    if (i < NX4) {
        float4 v = ((const float4*)x)[i];
        uint32_t h0, l0, h1, l1;
        splith2(v.x, v.y, h0, l0);
        splith2(v.z, v.w, h1, l1);
        ((uint2*)xh)[i] = make_uint2(h0, h1);
        ((uint2*)xl)[i] = make_uint2(l0, l1);
    } else if (i < NX4 + NWQ4) {
        int j = i - NX4;
        float4 v = ((const float4*)Wqkv)[j];
        ((uint2*)wq)[j] = make_uint2(packh2(v.x, v.y), packh2(v.z, v.w));
    } else {
        int j = i - NX4 - NWQ4;
        float4 v = ((const float4*)Wout)[j];
        ((uint2*)wo)[j] = make_uint2(packh2(v.x, v.y), packh2(v.z, v.w));
    }
}

// ---------------------------------------------------------------------------
// Post-process qkv: per-head RMS norm on q,k; emit head-major fp16 singles.
// q folded with log2(e); k contributes ||k|| to per-head atomic max.
// ---------------------------------------------------------------------------
__global__ __launch_bounds__(256)
void post_kernel(const float* __restrict__ qkv,
                 const float* __restrict__ qg, const float* __restrict__ kg,
                 __half* __restrict__ qf, __half* __restrict__ kf,
                 __half* __restrict__ vf, float* __restrict__ kmax)
{
    int w = (blockIdx.x * blockDim.x + threadIdx.x) >> 5;   // 0 .. NT*NH*3-1
    int lane = threadIdx.x & 31;
    int n = w / (NH * 3);
    int rem = w - n * (NH * 3);
    int h = rem / 3, ty = rem - h * 3;                      // 0=q 1=k 2=v

    const float* base = qkv + (size_t)n * (3 * CD) + ty * CD + h * DH;
    float v0 = base[2 * lane], v1 = base[2 * lane + 1];

    if (ty < 2) {
        float ss = v0 * v0 + v1 * v1;
        #pragma unroll
        for (int off = 16; off >= 1; off >>= 1)
            ss += __shfl_xor_sync(0xffffffffu, ss, off);
        float inv = 1.0f / fmaxf(sqrtf(ss), 1e-12f);
        const float* g = (ty == 0) ? qg : kg;
        float gsc = (ty == 0) ? (inv * LOG2E) : (8.0f * inv);
        v0 *= gsc * g[h * DH + 2 * lane];
        v1 *= gsc * g[h * DH + 2 * lane + 1];
        if (ty == 1) {
            float ss2 = v0 * v0 + v1 * v1;
            #pragma unroll
            for (int off = 16; off >= 1; off >>= 1)
                ss2 += __shfl_xor_sync(0xffffffffu, ss2, off);
            if (lane == 0)
                atomicMax((int*)&kmax[h], __float_as_int(sqrtf(ss2)));
        }
    }

    size_t off = (size_t)h * NT * DH + (size_t)n * DH + 2 * lane;
    __half* dst = (ty == 0) ? qf : (ty == 1) ? kf : vf;
    *(uint32_t*)&dst[off] = packh2(v0, v1);
}

// ---------------------------------------------------------------------------
// MMA GEMM v5: C = (Ahi+Alo) @ B^T + bias. fp16 2-product, K=1024,
// 128x128 tile, BK=32, 8 warps. 4-stage cp.async, 2 CTAs/SM.
// dyn smem: 4 stages x (Ah,Al,B) x 8192 B = 98304 B.
// ---------------------------------------------------------------------------
#define G_STG 24576
#define G_ARR 8192
__global__ __launch_bounds__(256, 2)
void gemm_mma(const __half* __restrict__ Ahi, const __half* __restrict__ Alo,
              const __half* __restrict__ B,
              const float* __restrict__ bias, float* __restrict__ C, int Nc)
{
    extern __shared__ char smem[];
    const uint32_t sb = smem_u32(smem);
    const int tid = threadIdx.x, lane = tid & 31, w = tid >> 5;
    const int wm = w >> 1, wn = w & 1;
    const int g = lane >> 2, t = lane & 3;
    const int n0 = blockIdx.x * 128, m0 = blockIdx.y * 128;

    float acc[2][8][4];
    #pragma unroll
    for (int i = 0; i < 2; i++)
        #pragma unroll
        for (int j = 0; j < 8; j++)
            acc[i][j][0] = acc[i][j][1] = acc[i][j][2] = acc[i][j][3] = 0.f;

    const __half* srcs[3] = {Ahi, Alo, B};

    auto load_tile = [&](int c, int s) {
        int kt = c * 32;
        #pragma unroll
        for (int p = 0; p < 6; p++) {
            int idx = tid + p * 256;           // 0..1535
            int arr = idx >> 9;                // 0..2
            int rem = idx & 511;
            int row = rem >> 2, sg = rem & 3;
            int base_row = (arr < 2) ? m0 : n0;
            const __half* src = srcs[arr] + (size_t)(base_row + row) * 1024 + kt + sg * 8;
            cp16(sb + s * G_STG + arr * G_ARR + row * 64 +
                 ((sg ^ ((row >> 1) & 3)) << 4), src);
        }
    };

    load_tile(0, 0); CP_COMMIT();
    load_tile(1, 1); CP_COMMIT();
    load_tile(2, 2); CP_COMMIT();

    for (int c = 0; c < 32; c++) {
        if (c < 30)      { CP_WAIT(2); }
        else if (c == 30){ CP_WAIT(1); }
        else             { CP_WAIT(0); }
        __syncthreads();
        if (c + 3 < 32) { load_tile(c + 3, (c + 3) & 3); CP_COMMIT(); }

        const uint32_t so = sb + (c & 3) * G_STG;
        #pragma unroll
        for (int kk = 0; kk < 2; kk++) {
            uint32_t ah[2][4], al[2][4];
            #pragma unroll
            for (int mt = 0; mt < 2; mt++) {
                int ar = wm * 32 + mt * 16 + (lane & 15);
                int ch = 2 * kk + ((lane & 16) >> 4);
                uint32_t off = ar * 64 + (((uint32_t)(ch ^ ((ar >> 1) & 3))) << 4);
                ldsm_x4(ah[mt], so + off);
                ldsm_x4(al[mt], so + G_ARR + off);
            }
            #pragma unroll
            for (int u = 0; u < 4; u++) {
                uint32_t bh[4];
                int br = wn * 64 + u * 16 + (lane & 7) + ((lane & 16) >> 1);
                int ch = 2 * kk + ((lane & 8) >> 3);
                uint32_t off = br * 64 + (((uint32_t)(ch ^ ((br >> 1) & 3))) << 4);
                ldsm_x4(bh, so + 2 * G_ARR + off);
                #pragma unroll
                for (int mt = 0; mt < 2; mt++) {
                    mma_f16(acc[mt][2 * u],     ah[mt], &bh[0]);
                    mma_f16(acc[mt][2 * u],     al[mt], &bh[0]);
                    mma_f16(acc[mt][2 * u + 1], ah[mt], &bh[2]);
                    mma_f16(acc[mt][2 * u + 1], al[mt], &bh[2]);
                }
            }
        }
    }

    #pragma unroll
    for (int mt = 0; mt < 2; mt++) {
        int r0 = m0 + wm * 32 + mt * 16 + g;
        #pragma unroll
        for (int nt = 0; nt < 8; nt++) {
            int cc = n0 + wn * 64 + nt * 8 + t * 2;
            float2 bv = *(const float2*)&bias[cc];
            float* a = acc[mt][nt];
            *(float2*)&C[(size_t)r0 * Nc + cc]       = make_float2(a[0] + bv.x, a[1] + bv.y);
            *(float2*)&C[(size_t)(r0 + 8) * Nc + cc] = make_float2(a[2] + bv.x, a[3] + bv.y);
        }
    }
}

// ---------------------------------------------------------------------------
// MMA GEMM single-product: C = A @ B^T + bias (both fp16 single).
// Same structure, 2 smem arrays, 4 stages x 16384 B = 65536 B.
// ---------------------------------------------------------------------------
#define G1_STG 16384
__global__ __launch_bounds__(256, 2)
void gemm_mma1(const __half* __restrict__ A, const __half* __restrict__ B,
               const float* __restrict__ bias, float* __restrict__ C, int Nc)
{
    extern __shared__ char smem[];
    const uint32_t sb = smem_u32(smem);
    const int tid = threadIdx.x, lane = tid & 31, w = tid >> 5;
    const int wm = w >> 1, wn = w & 1;
    const int g = lane >> 2, t = lane & 3;
    const int n0 = blockIdx.x * 128, m0 = blockIdx.y * 128;

    float acc[2][8][4];
    #pragma unroll
    for (int i = 0; i < 2; i++)
        #pragma unroll
        for (int j = 0; j < 8; j++)
            acc[i][j][0] = acc[i][j][1] = acc[i][j][2] = acc[i][j][3] = 0.f;

    const __half* srcs[2] = {A, B};

    auto load_tile = [&](int c, int s) {
        int kt = c * 32;
        #pragma unroll
        for (int p = 0; p < 4; p++) {
            int idx = tid + p * 256;           // 0..1023
            int arr = idx >> 9;                // 0..1
            int rem = idx & 511;
            int row = rem >> 2, sg = rem & 3;
            int base_row = (arr == 0) ? m0 : n0;
            const __half* src = srcs[arr] + (size_t)(base_row + row) * 1024 + kt + sg * 8;
            cp16(sb + s * G1_STG + arr * G_ARR + row * 64 +
                 ((sg ^ ((row >> 1) & 3)) << 4), src);
        }
    };

    load_tile(0, 0); CP_COMMIT();
    load_tile(1, 1); CP_COMMIT();
    load_tile(2, 2); CP_COMMIT();

    for (int c = 0; c < 32; c++) {
        if (c < 30)      { CP_WAIT(2); }
        else if (c == 30){ CP_WAIT(1); }
        else             { CP_WAIT(0); }
        __syncthreads();
        if (c + 3 < 32) { load_tile(c + 3, (c + 3) & 3); CP_COMMIT(); }

        const uint32_t so = sb + (c & 3) * G1_STG;
        #pragma unroll
        for (int kk = 0; kk < 2; kk++) {
            uint32_t ah[2][4];
            #pragma unroll
            for (int mt = 0; mt < 2; mt++) {
                int ar = wm * 32 + mt * 16 + (lane & 15);
                int ch = 2 * kk + ((lane & 16) >> 4);
                uint32_t off = ar * 64 + (((uint32_t)(ch ^ ((ar >> 1) & 3))) << 4);
                ldsm_x4(ah[mt], so + off);
            }
            #pragma unroll
            for (int u = 0; u < 4; u++) {
                uint32_t bh[4];
                int br = wn * 64 + u * 16 + (lane & 7) + ((lane & 16) >> 1);
                int ch = 2 * kk + ((lane & 8) >> 3);
                uint32_t off = br * 64 + (((uint32_t)(ch ^ ((br >> 1) & 3))) << 4);
                ldsm_x4(bh, so + G_ARR + off);
                #pragma unroll
                for (int mt = 0; mt < 2; mt++) {
                    mma_f16(acc[mt][2 * u],     ah[mt], &bh[0]);
                    mma_f16(acc[mt][2 * u + 1], ah[mt], &bh[2]);
                }
            }
        }
    }

    #pragma unroll
    for (int mt = 0; mt < 2; mt++) {
        int r0 = m0 + wm * 32 + mt * 16 + g;
        #pragma unroll
        for (int nt = 0; nt < 8; nt++) {
            int cc = n0 + wn * 64 + nt * 8 + t * 2;
            float2 bv = *(const float2*)&bias[cc];
            float* a = acc[mt][nt];
            *(float2*)&C[(size_t)r0 * Nc + cc]       = make_float2(a[0] + bv.x, a[1] + bv.y);
            *(float2*)&C[(size_t)(r0 + 8) * Nc + cc] = make_float2(a[2] + bv.x, a[3] + bv.y);
        }
    }
}

// ---------------------------------------------------------------------------
// Flash attention v8: fixed-shift softmax; 128 KV rows staged per pipeline
// step, computed as two 64-row half-passes (register footprint unchanged,
// loop/sync overhead halved). h emitted as fp16 single.
// 3 stages x (K,V) x 16384 B = 98304 B. 2 CTAs/SM.
// ---------------------------------------------------------------------------
#define A_STG 32768
#define A_VOFF 16384
#define NIT   (NT / 128)
__global__ __launch_bounds__(256, 2)
void flash_mma(const __half* __restrict__ qfg, const __half* __restrict__ kfg,
               const __half* __restrict__ vfg, const float* __restrict__ kmaxp,
               __half* __restrict__ hh)
{
    extern __shared__ char smem[];
    const uint32_t sb = smem_u32(smem);
    const int tid = threadIdx.x, lane = tid & 31, w = tid >> 5;
    const int g = lane >> 2, t = lane & 3;
    const int h = blockIdx.y, q0 = blockIdx.x * 128;
    const size_t hoff = (size_t)h * NT * DH;

    // Q fragments straight from gmem (m16n8k16 A layout, fp16 single)
    uint32_t qa[4][4];
    {
        const __half* r0 = qfg + hoff + (size_t)(q0 + w * 16 + g) * DH;
        const __half* r1 = r0 + 8 * DH;
        #pragma unroll
        for (int kk = 0; kk < 4; kk++) {
            qa[kk][0] = *(const uint32_t*)(r0 + kk * 16 + 2 * t);
            qa[kk][1] = *(const uint32_t*)(r1 + kk * 16 + 2 * t);
            qa[kk][2] = *(const uint32_t*)(r0 + kk * 16 + 8 + 2 * t);
            qa[kk][3] = *(const uint32_t*)(r1 + kk * 16 + 8 + 2 * t);
        }
    }

    // per-row softmax shift b = ||q_row|| * max||k||
    float qn0 = 0.f, qn1 = 0.f;
    #pragma unroll
    for (int kk = 0; kk < 4; kk++) {
        float2 f;
        f = __half22float2(*(__half2*)&qa[kk][0]); qn0 += f.x * f.x + f.y * f.y;
        f = __half22float2(*(__half2*)&qa[kk][2]); qn0 += f.x * f.x + f.y * f.y;
        f = __half22float2(*(__half2*)&qa[kk][1]); qn1 += f.x * f.x + f.y * f.y;
        f = __half22float2(*(__half2*)&qa[kk][3]); qn1 += f.x * f.x + f.y * f.y;
    }
    qn0 += __shfl_xor_sync(0xffffffffu, qn0, 1);
    qn0 += __shfl_xor_sync(0xffffffffu, qn0, 2);
    qn1 += __shfl_xor_sync(0xffffffffu, qn1, 1);
    qn1 += __shfl_xor_sync(0xffffffffu, qn1, 2);
    float km = kmaxp[h];
    float b0 = sqrtf(qn0) * km, b1 = sqrtf(qn1) * km;

    const __half* kfh = kfg + hoff;
    const __half* vfh = vfg + hoff;

    auto load_tile = [&](int it, int s) {
        int k0 = it * 128;
        #pragma unroll
        for (int p = 0; p < 8; p++) {
            int idx = tid + p * 256;            // 0..2047
            int arr = idx >> 10;                // 0..1
            int rem = idx & 1023;
            int row = rem >> 3, sg = rem & 7;
            const __half* src = (arr == 0 ? kfh : vfh) + (size_t)(k0 + row) * DH + sg * 8;
            cp16(sb + s * A_STG + arr * A_VOFF + row * 128 +
                 ((sg ^ (row & 7)) << 4), src);
        }
    };

    float l0 = 0.f, l1 = 0.f;
    float oacc[8][4];
    #pragma unroll
    for (int u = 0; u < 8; u++)
        oacc[u][0] = oacc[u][1] = oacc[u][2] = oacc[u][3] = 0.f;

    load_tile(0, 0); CP_COMMIT();
    load_tile(1, 1); CP_COMMIT();

    for (int it = 0; it < NIT; it++) {
        if (it < NIT - 1) { CP_WAIT(1); } else { CP_WAIT(0); }
        __syncthreads();
        if (it + 2 < NIT) { load_tile(it + 2, (it + 2) % 3); CP_COMMIT(); }

        const uint32_t so = sb + (it % 3) * A_STG;

        #pragma unroll
        for (int hp = 0; hp < 2; hp++) {
            const uint32_t soh = so + hp * 8192;

            // S = Q @ K^T - b
            float s[8][4];
            #pragma unroll
            for (int j = 0; j < 8; j++) {
                s[j][0] = -b0; s[j][1] = -b0;
                s[j][2] = -b1; s[j][3] = -b1;
            }

            #pragma unroll
            for (int kk = 0; kk < 4; kk++) {
                #pragma unroll
                for (int u = 0; u < 4; u++) {
                    uint32_t bh[4];
                    int br = u * 16 + (lane & 7) + ((lane & 16) >> 1);
                    int ch = 2 * kk + ((lane & 8) >> 3);
                    uint32_t off = br * 128 + (((uint32_t)(ch ^ (br & 7))) << 4);
                    ldsm_x4(bh, soh + off);
                    mma_f16(s[2 * u],     qa[kk], &bh[0]);
                    mma_f16(s[2 * u + 1], qa[kk], &bh[2]);
                }
            }

            // P = 2^s; accumulate l; O += P @ V
            #pragma unroll
            for (int kv = 0; kv < 4; kv++) {
                float e00 = ex2f(s[2 * kv][0]),     e01 = ex2f(s[2 * kv][1]);
                float e02 = ex2f(s[2 * kv][2]),     e03 = ex2f(s[2 * kv][3]);
                float e10 = ex2f(s[2 * kv + 1][0]), e11 = ex2f(s[2 * kv + 1][1]);
                float e12 = ex2f(s[2 * kv + 1][2]), e13 = ex2f(s[2 * kv + 1][3]);
                l0 += (e00 + e01) + (e10 + e11);
                l1 += (e02 + e03) + (e12 + e13);
                uint32_t pa[4];
                pa[0] = packh2(e00, e01);
                pa[1] = packh2(e02, e03);
                pa[2] = packh2(e10, e11);
                pa[3] = packh2(e12, e13);
                #pragma unroll
                for (int u = 0; u < 4; u++) {
                    uint32_t vh4[4];
                    int vr = kv * 16 + (lane & 15);
                    int ch = 2 * u + ((lane & 16) >> 4);
                    uint32_t off = vr * 128 + (((uint32_t)(ch ^ (vr & 7))) << 4);
                    ldsm_x4_t(vh4, soh + A_VOFF + off);
                    mma_f16(oacc[2 * u],     pa, &vh4[0]);
                    mma_f16(oacc[2 * u + 1], pa, &vh4[2]);
                }
            }
        }
    }

    // final l reduction across the quad
    l0 += __shfl_xor_sync(0xffffffffu, l0, 1);
    l0 += __shfl_xor_sync(0xffffffffu, l0, 2);
    l1 += __shfl_xor_sync(0xffffffffu, l1, 1);
    l1 += __shfl_xor_sync(0xffffffffu, l1, 2);

    // epilogue: normalize, write h as fp16 single (row-major [NT][CD])
    float inv0 = 1.0f / l0, inv1 = 1.0f / l1;
    int r0 = q0 + w * 16 + g;
    #pragma unroll
    for (int u = 0; u < 8; u++) {
        size_t o0 = (size_t)r0 * CD + h * DH + u * 8 + t * 2;
        *(uint32_t*)&hh[o0] = packh2(oacc[u][0] * inv0, oacc[u][1] * inv0);
        size_t o1 = (size_t)(r0 + 8) * CD + h * DH + u * 8 + t * 2;
        *(uint32_t*)&hh[o1] = packh2(oacc[u][2] * inv1, oacc[u][3] * inv1);
    }
}

// ---------------------------------------------------------------------------
// kernel_launch — graph-capturable, allocation-free.
// Inputs: x, Wqkv, bqkv, q_gamma, k_gamma, Wout, bout
// ---------------------------------------------------------------------------
extern "C" void kernel_launch(void* const* d_in, const int* in_sizes, int n_in,
                              void* d_out, int out_size)
{
    const float* x    = (const float*)d_in[0];
    const float* Wqkv = (const float*)d_in[1];
    const float* bqkv = (const float*)d_in[2];
    const float* qg   = (const float*)d_in[3];
    const float* kg   = (const float*)d_in[4];
    const float* Wout = (const float*)d_in[5];
    const float* bout = (const float*)d_in[6];
    float* out = (float*)d_out;

    void* p;
    cudaGetSymbolAddress(&p, g_qkv);  float*  qkv  = (float*)p;
    cudaGetSymbolAddress(&p, g_xh);   __half* xh   = (__half*)p;
    cudaGetSymbolAddress(&p, g_xl);   __half* xl   = (__half*)p;
    cudaGetSymbolAddress(&p, g_wq);   __half* wq   = (__half*)p;
    cudaGetSymbolAddress(&p, g_wo);   __half* wo   = (__half*)p;
    cudaGetSymbolAddress(&p, g_hh);   __half* hh   = (__half*)p;
    cudaGetSymbolAddress(&p, g_qf);   __half* qf   = (__half*)p;
    cudaGetSymbolAddress(&p, g_kf);   __half* kf   = (__half*)p;
    cudaGetSymbolAddress(&p, g_vf);   __half* vf   = (__half*)p;
    cudaGetSymbolAddress(&p, g_kmax); float*  kmax = (float*)p;

    cudaFuncSetAttribute(gemm_mma,
                         cudaFuncAttributeMaxDynamicSharedMemorySize, 98304);
    cudaFuncSetAttribute(gemm_mma1,
                         cudaFuncAttributeMaxDynamicSharedMemorySize, 65536);
    cudaFuncSetAttribute(flash_mma,
                         cudaFuncAttributeMaxDynamicSharedMemorySize, 98304);

    // 0) merged prep + zero per-head kmax
    cudaMemsetAsync(kmax, 0, NH * sizeof(float), 0);
    prep_kernel<<<(NX4 + NWQ4 + NWO4) / 256, 256>>>(x, Wqkv, Wout,
                                                    xh, xl, wq, wo);

    // 1) qkv = x @ Wqkv^T + bqkv  (fp16 2-product, 4-stage)
    gemm_mma<<<dim3(3 * CD / 128, NT / 128), 256, 98304>>>(
        xh, xl, wq, bqkv, qkv, 3 * CD);

    // 2) rms norm + fp16 head-major emit + per-head max||k||
    post_kernel<<<(NT * NH * 3 * 32) / 256, 256>>>(qkv, qg, kg, qf, kf, vf, kmax);

    // 3) flash attention (fixed-shift softmax, half-pass BN=128) -> h fp16
    flash_mma<<<dim3(NT / 128, NH), 256, 98304>>>(qf, kf, vf, kmax, hh);

    // 4) out = h @ Wout^T + bout  (fp16 single-product, 4-stage)
    gemm_mma1<<<dim3(CD / 128, NT / 128), 256, 65536>>>(hh, wo, bout, out, CD);
}

// round 13
// speedup vs baseline: 7.9299x; 1.1632x over previous
#include <cuda_runtime.h>
#include <cuda_bf16.h>
#include <cuda_fp16.h>
#include <cstdint>
#include <math.h>

#define NT 4096
#define CD 1024
#define NH 16
#define DH 64
#define LOG2E 1.4426950408889634f

// ---------------- scratch (allocation-free rule) ----------------
__device__ float  g_qkv[NT * 3 * CD];
__device__ __half g_xf[NT * CD];                     // x fp16 single
__device__ __half g_wq[3 * CD * CD];                 // Wqkv fp16 single
__device__ __half g_wo[CD * CD];                     // Wout fp16 single
__device__ __half g_hh[NT * CD];                     // h fp16 single
// head-major [NH][NT][DH] fp16 singles: q (pre-scaled by log2e fold), k, v
__device__ __half g_qf[NT * CD];
__device__ __half g_kf[NT * CD];
__device__ __half g_vf[NT * CD];
__device__ float  g_kmax[NH];                        // per-head max ||k||

// ---------------- helpers ----------------
__device__ __forceinline__ uint32_t smem_u32(const void* p) {
    return (uint32_t)__cvta_generic_to_shared(p);
}
__device__ __forceinline__ void ldsm_x4(uint32_t* r, uint32_t a) {
    asm volatile("ldmatrix.sync.aligned.m8n8.x4.shared.b16 {%0,%1,%2,%3}, [%4];"
                 : "=r"(r[0]), "=r"(r[1]), "=r"(r[2]), "=r"(r[3]) : "r"(a));
}
__device__ __forceinline__ void ldsm_x4_t(uint32_t* r, uint32_t a) {
    asm volatile("ldmatrix.sync.aligned.m8n8.x4.trans.shared.b16 {%0,%1,%2,%3}, [%4];"
                 : "=r"(r[0]), "=r"(r[1]), "=r"(r[2]), "=r"(r[3]) : "r"(a));
}
__device__ __forceinline__ void mma_f16(float* c, const uint32_t* a, const uint32_t* b) {
    asm volatile(
        "mma.sync.aligned.m16n8k16.row.col.f32.f16.f16.f32 "
        "{%0,%1,%2,%3}, {%4,%5,%6,%7}, {%8,%9}, {%0,%1,%2,%3};"
        : "+f"(c[0]), "+f"(c[1]), "+f"(c[2]), "+f"(c[3])
        : "r"(a[0]), "r"(a[1]), "r"(a[2]), "r"(a[3]), "r"(b[0]), "r"(b[1]));
}
__device__ __forceinline__ uint32_t packh2(float a, float b) {
    __half2 h = __floats2half2_rn(a, b);
    return *(uint32_t*)&h;
}
__device__ __forceinline__ float ex2f(float x) {
    float y;
    asm("ex2.approx.f32 %0, %1;" : "=f"(y) : "f"(x));
    return y;
}
__device__ __forceinline__ void cp16(uint32_t dst, const void* src) {
    asm volatile("cp.async.cg.shared.global [%0], [%1], 16;" :: "r"(dst), "l"(src));
}
#define CP_COMMIT() asm volatile("cp.async.commit_group;" ::: "memory")
#define CP_WAIT(n)  asm volatile("cp.async.wait_group %0;" :: "n"(n) : "memory")

// ---------------------------------------------------------------------------
// Merged prep: x, Wqkv, Wout -> fp16 single. 4 fp32 elements per thread.
// ---------------------------------------------------------------------------
#define NX4  (NT * CD / 4)
#define NWQ4 (3 * CD * CD / 4)
#define NWO4 (CD * CD / 4)
__global__ __launch_bounds__(256)
void prep_kernel(const float* __restrict__ x, const float* __restrict__ Wqkv,
                 const float* __restrict__ Wout,
                 __half* __restrict__ xf,
                 __half* __restrict__ wq, __half* __restrict__ wo)
{
    int i = blockIdx.x * blockDim.x + threadIdx.x;
    if (i < NX4) {
        float4 v = ((const float4*)x)[i];
        ((uint2*)xf)[i] = make_uint2(packh2(v.x, v.y), packh2(v.z, v.w));
    } else if (i < NX4 + NWQ4) {
        int j = i - NX4;
        float4 v = ((const float4*)Wqkv)[j];
        ((uint2*)wq)[j] = make_uint2(packh2(v.x, v.y), packh2(v.z, v.w));
    } else {
        int j = i - NX4 - NWQ4;
        float4 v = ((const float4*)Wout)[j];
        ((uint2*)wo)[j] = make_uint2(packh2(v.x, v.y), packh2(v.z, v.w));
    }
}

// ---------------------------------------------------------------------------
// Post-process qkv: per-head RMS norm on q,k; emit head-major fp16 singles.
// q folded with log2(e); k contributes ||k|| to per-head atomic max.
// ---------------------------------------------------------------------------
__global__ __launch_bounds__(256)
void post_kernel(const float* __restrict__ qkv,
                 const float* __restrict__ qg, const float* __restrict__ kg,
                 __half* __restrict__ qf, __half* __restrict__ kf,
                 __half* __restrict__ vf, float* __restrict__ kmax)
{
    int w = (blockIdx.x * blockDim.x + threadIdx.x) >> 5;   // 0 .. NT*NH*3-1
    int lane = threadIdx.x & 31;
    int n = w / (NH * 3);
    int rem = w - n * (NH * 3);
    int h = rem / 3, ty = rem - h * 3;                      // 0=q 1=k 2=v

    const float* base = qkv + (size_t)n * (3 * CD) + ty * CD + h * DH;
    float v0 = base[2 * lane], v1 = base[2 * lane + 1];

    if (ty < 2) {
        float ss = v0 * v0 + v1 * v1;
        #pragma unroll
        for (int off = 16; off >= 1; off >>= 1)
            ss += __shfl_xor_sync(0xffffffffu, ss, off);
        float inv = 1.0f / fmaxf(sqrtf(ss), 1e-12f);
        const float* g = (ty == 0) ? qg : kg;
        float gsc = (ty == 0) ? (inv * LOG2E) : (8.0f * inv);
        v0 *= gsc * g[h * DH + 2 * lane];
        v1 *= gsc * g[h * DH + 2 * lane + 1];
        if (ty == 1) {
            float ss2 = v0 * v0 + v1 * v1;
            #pragma unroll
            for (int off = 16; off >= 1; off >>= 1)
                ss2 += __shfl_xor_sync(0xffffffffu, ss2, off);
            if (lane == 0)
                atomicMax((int*)&kmax[h], __float_as_int(sqrtf(ss2)));
        }
    }

    size_t off = (size_t)h * NT * DH + (size_t)n * DH + 2 * lane;
    __half* dst = (ty == 0) ? qf : (ty == 1) ? kf : vf;
    *(uint32_t*)&dst[off] = packh2(v0, v1);
}

// ---------------------------------------------------------------------------
// MMA GEMM single-product: C = A @ B^T + bias (both fp16 single). K=1024,
// 128x128 tile, BK=32, 8 warps, 4-stage cp.async, 2 CTAs/SM.
// dyn smem: 4 stages x (A,B) x 8192 B = 65536 B.
// ---------------------------------------------------------------------------
#define G_ARR  8192
#define G1_STG 16384
__global__ __launch_bounds__(256, 2)
void gemm_mma1(const __half* __restrict__ A, const __half* __restrict__ B,
               const float* __restrict__ bias, float* __restrict__ C, int Nc)
{
    extern __shared__ char smem[];
    const uint32_t sb = smem_u32(smem);
    const int tid = threadIdx.x, lane = tid & 31, w = tid >> 5;
    const int wm = w >> 1, wn = w & 1;
    const int g = lane >> 2, t = lane & 3;
    const int n0 = blockIdx.x * 128, m0 = blockIdx.y * 128;

    float acc[2][8][4];
    #pragma unroll
    for (int i = 0; i < 2; i++)
        #pragma unroll
        for (int j = 0; j < 8; j++)
            acc[i][j][0] = acc[i][j][1] = acc[i][j][2] = acc[i][j][3] = 0.f;

    const __half* srcs[2] = {A, B};

    auto load_tile = [&](int c, int s) {
        int kt = c * 32;
        #pragma unroll
        for (int p = 0; p < 4; p++) {
            int idx = tid + p * 256;           // 0..1023
            int arr = idx >> 9;                // 0..1
            int rem = idx & 511;
            int row = rem >> 2, sg = rem & 3;
            int base_row = (arr == 0) ? m0 : n0;
            const __half* src = srcs[arr] + (size_t)(base_row + row) * 1024 + kt + sg * 8;
            cp16(sb + s * G1_STG + arr * G_ARR + row * 64 +
                 ((sg ^ ((row >> 1) & 3)) << 4), src);
        }
    };

    load_tile(0, 0); CP_COMMIT();
    load_tile(1, 1); CP_COMMIT();
    load_tile(2, 2); CP_COMMIT();

    for (int c = 0; c < 32; c++) {
        if (c < 30)      { CP_WAIT(2); }
        else if (c == 30){ CP_WAIT(1); }
        else             { CP_WAIT(0); }
        __syncthreads();
        if (c + 3 < 32) { load_tile(c + 3, (c + 3) & 3); CP_COMMIT(); }

        const uint32_t so = sb + (c & 3) * G1_STG;
        #pragma unroll
        for (int kk = 0; kk < 2; kk++) {
            uint32_t ah[2][4];
            #pragma unroll
            for (int mt = 0; mt < 2; mt++) {
                int ar = wm * 32 + mt * 16 + (lane & 15);
                int ch = 2 * kk + ((lane & 16) >> 4);
                uint32_t off = ar * 64 + (((uint32_t)(ch ^ ((ar >> 1) & 3))) << 4);
                ldsm_x4(ah[mt], so + off);
            }
            #pragma unroll
            for (int u = 0; u < 4; u++) {
                uint32_t bh[4];
                int br = wn * 64 + u * 16 + (lane & 7) + ((lane & 16) >> 1);
                int ch = 2 * kk + ((lane & 8) >> 3);
                uint32_t off = br * 64 + (((uint32_t)(ch ^ ((br >> 1) & 3))) << 4);
                ldsm_x4(bh, so + G_ARR + off);
                #pragma unroll
                for (int mt = 0; mt < 2; mt++) {
                    mma_f16(acc[mt][2 * u],     ah[mt], &bh[0]);
                    mma_f16(acc[mt][2 * u + 1], ah[mt], &bh[2]);
                }
            }
        }
    }

    #pragma unroll
    for (int mt = 0; mt < 2; mt++) {
        int r0 = m0 + wm * 32 + mt * 16 + g;
        #pragma unroll
        for (int nt = 0; nt < 8; nt++) {
            int cc = n0 + wn * 64 + nt * 8 + t * 2;
            float2 bv = *(const float2*)&bias[cc];
            float* a = acc[mt][nt];
            *(float2*)&C[(size_t)r0 * Nc + cc]       = make_float2(a[0] + bv.x, a[1] + bv.y);
            *(float2*)&C[(size_t)(r0 + 8) * Nc + cc] = make_float2(a[2] + bv.x, a[3] + bv.y);
        }
    }
}

// ---------------------------------------------------------------------------
// Flash attention v8 (unchanged from R11): fixed-shift softmax; 128 KV rows
// per pipeline step as two 64-row half-passes. h emitted fp16 single.
// 3 stages x (K,V) x 16384 B = 98304 B. 2 CTAs/SM.
// ---------------------------------------------------------------------------
#define A_STG 32768
#define A_VOFF 16384
#define NIT   (NT / 128)
__global__ __launch_bounds__(256, 2)
void flash_mma(const __half* __restrict__ qfg, const __half* __restrict__ kfg,
               const __half* __restrict__ vfg, const float* __restrict__ kmaxp,
               __half* __restrict__ hh)
{
    extern __shared__ char smem[];
    const uint32_t sb = smem_u32(smem);
    const int tid = threadIdx.x, lane = tid & 31, w = tid >> 5;
    const int g = lane >> 2, t = lane & 3;
    const int h = blockIdx.y, q0 = blockIdx.x * 128;
    const size_t hoff = (size_t)h * NT * DH;

    uint32_t qa[4][4];
    {
        const __half* r0 = qfg + hoff + (size_t)(q0 + w * 16 + g) * DH;
        const __half* r1 = r0 + 8 * DH;
        #pragma unroll
        for (int kk = 0; kk < 4; kk++) {
            qa[kk][0] = *(const uint32_t*)(r0 + kk * 16 + 2 * t);
            qa[kk][1] = *(const uint32_t*)(r1 + kk * 16 + 2 * t);
            qa[kk][2] = *(const uint32_t*)(r0 + kk * 16 + 8 + 2 * t);
            qa[kk][3] = *(const uint32_t*)(r1 + kk * 16 + 8 + 2 * t);
        }
    }

    float qn0 = 0.f, qn1 = 0.f;
    #pragma unroll
    for (int kk = 0; kk < 4; kk++) {
        float2 f;
        f = __half22float2(*(__half2*)&qa[kk][0]); qn0 += f.x * f.x + f.y * f.y;
        f = __half22float2(*(__half2*)&qa[kk][2]); qn0 += f.x * f.x + f.y * f.y;
        f = __half22float2(*(__half2*)&qa[kk][1]); qn1 += f.x * f.x + f.y * f.y;
        f = __half22float2(*(__half2*)&qa[kk][3]); qn1 += f.x * f.x + f.y * f.y;
    }
    qn0 += __shfl_xor_sync(0xffffffffu, qn0, 1);
    qn0 += __shfl_xor_sync(0xffffffffu, qn0, 2);
    qn1 += __shfl_xor_sync(0xffffffffu, qn1, 1);
    qn1 += __shfl_xor_sync(0xffffffffu, qn1, 2);
    float km = kmaxp[h];
    float b0 = sqrtf(qn0) * km, b1 = sqrtf(qn1) * km;

    const __half* kfh = kfg + hoff;
    const __half* vfh = vfg + hoff;

    auto load_tile = [&](int it, int s) {
        int k0 = it * 128;
        #pragma unroll
        for (int p = 0; p < 8; p++) {
            int idx = tid + p * 256;            // 0..2047
            int arr = idx >> 10;                // 0..1
            int rem = idx & 1023;
            int row = rem >> 3, sg = rem & 7;
            const __half* src = (arr == 0 ? kfh : vfh) + (size_t)(k0 + row) * DH + sg * 8;
            cp16(sb + s * A_STG + arr * A_VOFF + row * 128 +
                 ((sg ^ (row & 7)) << 4), src);
        }
    };

    float l0 = 0.f, l1 = 0.f;
    float oacc[8][4];
    #pragma unroll
    for (int u = 0; u < 8; u++)
        oacc[u][0] = oacc[u][1] = oacc[u][2] = oacc[u][3] = 0.f;

    load_tile(0, 0); CP_COMMIT();
    load_tile(1, 1); CP_COMMIT();

    for (int it = 0; it < NIT; it++) {
        if (it < NIT - 1) { CP_WAIT(1); } else { CP_WAIT(0); }
        __syncthreads();
        if (it + 2 < NIT) { load_tile(it + 2, (it + 2) % 3); CP_COMMIT(); }

        const uint32_t so = sb + (it % 3) * A_STG;

        #pragma unroll
        for (int hp = 0; hp < 2; hp++) {
            const uint32_t soh = so + hp * 8192;

            float s[8][4];
            #pragma unroll
            for (int j = 0; j < 8; j++) {
                s[j][0] = -b0; s[j][1] = -b0;
                s[j][2] = -b1; s[j][3] = -b1;
            }

            #pragma unroll
            for (int kk = 0; kk < 4; kk++) {
                #pragma unroll
                for (int u = 0; u < 4; u++) {
                    uint32_t bh[4];
                    int br = u * 16 + (lane & 7) + ((lane & 16) >> 1);
                    int ch = 2 * kk + ((lane & 8) >> 3);
                    uint32_t off = br * 128 + (((uint32_t)(ch ^ (br & 7))) << 4);
                    ldsm_x4(bh, soh + off);
                    mma_f16(s[2 * u],     qa[kk], &bh[0]);
                    mma_f16(s[2 * u + 1], qa[kk], &bh[2]);
                }
            }

            #pragma unroll
            for (int kv = 0; kv < 4; kv++) {
                float e00 = ex2f(s[2 * kv][0]),     e01 = ex2f(s[2 * kv][1]);
                float e02 = ex2f(s[2 * kv][2]),     e03 = ex2f(s[2 * kv][3]);
                float e10 = ex2f(s[2 * kv + 1][0]), e11 = ex2f(s[2 * kv + 1][1]);
                float e12 = ex2f(s[2 * kv + 1][2]), e13 = ex2f(s[2 * kv + 1][3]);
                l0 += (e00 + e01) + (e10 + e11);
                l1 += (e02 + e03) + (e12 + e13);
                uint32_t pa[4];
                pa[0] = packh2(e00, e01);
                pa[1] = packh2(e02, e03);
                pa[2] = packh2(e10, e11);
                pa[3] = packh2(e12, e13);
                #pragma unroll
                for (int u = 0; u < 4; u++) {
                    uint32_t vh4[4];
                    int vr = kv * 16 + (lane & 15);
                    int ch = 2 * u + ((lane & 16) >> 4);
                    uint32_t off = vr * 128 + (((uint32_t)(ch ^ (vr & 7))) << 4);
                    ldsm_x4_t(vh4, soh + A_VOFF + off);
                    mma_f16(oacc[2 * u],     pa, &vh4[0]);
                    mma_f16(oacc[2 * u + 1], pa, &vh4[2]);
                }
            }
        }
    }

    l0 += __shfl_xor_sync(0xffffffffu, l0, 1);
    l0 += __shfl_xor_sync(0xffffffffu, l0, 2);
    l1 += __shfl_xor_sync(0xffffffffu, l1, 1);
    l1 += __shfl_xor_sync(0xffffffffu, l1, 2);

    float inv0 = 1.0f / l0, inv1 = 1.0f / l1;
    int r0 = q0 + w * 16 + g;
    #pragma unroll
    for (int u = 0; u < 8; u++) {
        size_t o0 = (size_t)r0 * CD + h * DH + u * 8 + t * 2;
        *(uint32_t*)&hh[o0] = packh2(oacc[u][0] * inv0, oacc[u][1] * inv0);
        size_t o1 = (size_t)(r0 + 8) * CD + h * DH + u * 8 + t * 2;
        *(uint32_t*)&hh[o1] = packh2(oacc[u][2] * inv1, oacc[u][3] * inv1);
    }
}

// ---------------------------------------------------------------------------
// kernel_launch — graph-capturable, allocation-free.
// Inputs: x, Wqkv, bqkv, q_gamma, k_gamma, Wout, bout
// ---------------------------------------------------------------------------
extern "C" void kernel_launch(void* const* d_in, const int* in_sizes, int n_in,
                              void* d_out, int out_size)
{
    const float* x    = (const float*)d_in[0];
    const float* Wqkv = (const float*)d_in[1];
    const float* bqkv = (const float*)d_in[2];
    const float* qg   = (const float*)d_in[3];
    const float* kg   = (const float*)d_in[4];
    const float* Wout = (const float*)d_in[5];
    const float* bout = (const float*)d_in[6];
    float* out = (float*)d_out;

    void* p;
    cudaGetSymbolAddress(&p, g_qkv);  float*  qkv  = (float*)p;
    cudaGetSymbolAddress(&p, g_xf);   __half* xf   = (__half*)p;
    cudaGetSymbolAddress(&p, g_wq);   __half* wq   = (__half*)p;
    cudaGetSymbolAddress(&p, g_wo);   __half* wo   = (__half*)p;
    cudaGetSymbolAddress(&p, g_hh);   __half* hh   = (__half*)p;
    cudaGetSymbolAddress(&p, g_qf);   __half* qf   = (__half*)p;
    cudaGetSymbolAddress(&p, g_kf);   __half* kf   = (__half*)p;
    cudaGetSymbolAddress(&p, g_vf);   __half* vf   = (__half*)p;
    cudaGetSymbolAddress(&p, g_kmax); float*  kmax = (float*)p;

    cudaFuncSetAttribute(gemm_mma1,
                         cudaFuncAttributeMaxDynamicSharedMemorySize, 65536);
    cudaFuncSetAttribute(flash_mma,
                         cudaFuncAttributeMaxDynamicSharedMemorySize, 98304);

    // 0) merged prep + zero per-head kmax
    cudaMemsetAsync(kmax, 0, NH * sizeof(float), 0);
    prep_kernel<<<(NX4 + NWQ4 + NWO4) / 256, 256>>>(x, Wqkv, Wout, xf, wq, wo);

    // 1) qkv = x @ Wqkv^T + bqkv  (fp16 single-product, 4-stage)
    gemm_mma1<<<dim3(3 * CD / 128, NT / 128), 256, 65536>>>(
        xf, wq, bqkv, qkv, 3 * CD);

    // 2) rms norm + fp16 head-major emit + per-head max||k||
    post_kernel<<<(NT * NH * 3 * 32) / 256, 256>>>(qkv, qg, kg, qf, kf, vf, kmax);

    // 3) flash attention (fixed-shift softmax) -> h fp16
    flash_mma<<<dim3(NT / 128, NH), 256, 98304>>>(qf, kf, vf, kmax, hh);

    // 4) out = h @ Wout^T + bout  (fp16 single-product, 4-stage)
    gemm_mma1<<<dim3(CD / 128, NT / 128), 256, 65536>>>(hh, wo, bout, out, CD);
}

// round 15
// speedup vs baseline: 8.2250x; 1.0372x over previous
#include <cuda_runtime.h>
#include <cuda_bf16.h>
#include <cuda_fp16.h>
#include <cstdint>
#include <math.h>

#define NT 4096
#define CD 1024
#define NH 16
#define DH 64
#define LOG2E 1.4426950408889634f

// ---------------- scratch (allocation-free rule) ----------------
__device__ float  g_qkv[NT * 3 * CD];
__device__ __half g_xf[NT * CD];                     // x fp16 single
__device__ __half g_wq[3 * CD * CD];                 // Wqkv fp16 single
__device__ __half g_wo[CD * CD];                     // Wout fp16 single
__device__ __half g_hh[NT * CD];                     // h fp16 single
// head-major [NH][NT][DH] fp16 singles: q (pre-scaled by log2e fold), k, v
__device__ __half g_qf[NT * CD];
__device__ __half g_kf[NT * CD];
__device__ __half g_vf[NT * CD];
__device__ float  g_kmax[NH];                        // per-head max ||k||

// ---------------- helpers ----------------
__device__ __forceinline__ uint32_t smem_u32(const void* p) {
    return (uint32_t)__cvta_generic_to_shared(p);
}
__device__ __forceinline__ void ldsm_x4(uint32_t* r, uint32_t a) {
    asm volatile("ldmatrix.sync.aligned.m8n8.x4.shared.b16 {%0,%1,%2,%3}, [%4];"
                 : "=r"(r[0]), "=r"(r[1]), "=r"(r[2]), "=r"(r[3]) : "r"(a));
}
__device__ __forceinline__ void ldsm_x4_t(uint32_t* r, uint32_t a) {
    asm volatile("ldmatrix.sync.aligned.m8n8.x4.trans.shared.b16 {%0,%1,%2,%3}, [%4];"
                 : "=r"(r[0]), "=r"(r[1]), "=r"(r[2]), "=r"(r[3]) : "r"(a));
}
__device__ __forceinline__ void mma_f16(float* c, const uint32_t* a, const uint32_t* b) {
    asm volatile(
        "mma.sync.aligned.m16n8k16.row.col.f32.f16.f16.f32 "
        "{%0,%1,%2,%3}, {%4,%5,%6,%7}, {%8,%9}, {%0,%1,%2,%3};"
        : "+f"(c[0]), "+f"(c[1]), "+f"(c[2]), "+f"(c[3])
        : "r"(a[0]), "r"(a[1]), "r"(a[2]), "r"(a[3]), "r"(b[0]), "r"(b[1]));
}
__device__ __forceinline__ uint32_t packh2(float a, float b) {
    __half2 h = __floats2half2_rn(a, b);
    return *(uint32_t*)&h;
}
__device__ __forceinline__ float ex2f(float x) {
    float y;
    asm("ex2.approx.f32 %0, %1;" : "=f"(y) : "f"(x));
    return y;
}
__device__ __forceinline__ void cp16(uint32_t dst, const void* src) {
    asm volatile("cp.async.cg.shared.global [%0], [%1], 16;" :: "r"(dst), "l"(src));
}
#define CP_COMMIT() asm volatile("cp.async.commit_group;" ::: "memory")
#define CP_WAIT(n)  asm volatile("cp.async.wait_group %0;" :: "n"(n) : "memory")

// ---------------------------------------------------------------------------
// Merged prep: x, Wqkv, Wout -> fp16 single. 4 fp32 elements per thread.
// ---------------------------------------------------------------------------
#define NX4  (NT * CD / 4)
#define NWQ4 (3 * CD * CD / 4)
#define NWO4 (CD * CD / 4)
__global__ __launch_bounds__(256)
void prep_kernel(const float* __restrict__ x, const float* __restrict__ Wqkv,
                 const float* __restrict__ Wout,
                 __half* __restrict__ xf,
                 __half* __restrict__ wq, __half* __restrict__ wo)
{
    int i = blockIdx.x * blockDim.x + threadIdx.x;
    if (i < NX4) {
        float4 v = ((const float4*)x)[i];
        ((uint2*)xf)[i] = make_uint2(packh2(v.x, v.y), packh2(v.z, v.w));
    } else if (i < NX4 + NWQ4) {
        int j = i - NX4;
        float4 v = ((const float4*)Wqkv)[j];
        ((uint2*)wq)[j] = make_uint2(packh2(v.x, v.y), packh2(v.z, v.w));
    } else {
        int j = i - NX4 - NWQ4;
        float4 v = ((const float4*)Wout)[j];
        ((uint2*)wo)[j] = make_uint2(packh2(v.x, v.y), packh2(v.z, v.w));
    }
}

// ---------------------------------------------------------------------------
// Post-process qkv: per-head RMS norm on q,k; emit head-major fp16 singles.
// q folded with log2(e); k contributes ||k|| to per-head atomic max.
// ---------------------------------------------------------------------------
__global__ __launch_bounds__(256)
void post_kernel(const float* __restrict__ qkv,
                 const float* __restrict__ qg, const float* __restrict__ kg,
                 __half* __restrict__ qf, __half* __restrict__ kf,
                 __half* __restrict__ vf, float* __restrict__ kmax)
{
    int w = (blockIdx.x * blockDim.x + threadIdx.x) >> 5;   // 0 .. NT*NH*3-1
    int lane = threadIdx.x & 31;
    int n = w / (NH * 3);
    int rem = w - n * (NH * 3);
    int h = rem / 3, ty = rem - h * 3;                      // 0=q 1=k 2=v

    const float* base = qkv + (size_t)n * (3 * CD) + ty * CD + h * DH;
    float v0 = base[2 * lane], v1 = base[2 * lane + 1];

    if (ty < 2) {
        float ss = v0 * v0 + v1 * v1;
        #pragma unroll
        for (int off = 16; off >= 1; off >>= 1)
            ss += __shfl_xor_sync(0xffffffffu, ss, off);
        float inv = 1.0f / fmaxf(sqrtf(ss), 1e-12f);
        const float* g = (ty == 0) ? qg : kg;
        float gsc = (ty == 0) ? (inv * LOG2E) : (8.0f * inv);
        v0 *= gsc * g[h * DH + 2 * lane];
        v1 *= gsc * g[h * DH + 2 * lane + 1];
        if (ty == 1) {
            float ss2 = v0 * v0 + v1 * v1;
            #pragma unroll
            for (int off = 16; off >= 1; off >>= 1)
                ss2 += __shfl_xor_sync(0xffffffffu, ss2, off);
            if (lane == 0)
                atomicMax((int*)&kmax[h], __float_as_int(sqrtf(ss2)));
        }
    }

    size_t off = (size_t)h * NT * DH + (size_t)n * DH + 2 * lane;
    __half* dst = (ty == 0) ? qf : (ty == 1) ? kf : vf;
    *(uint32_t*)&dst[off] = packh2(v0, v1);
}

// ---------------------------------------------------------------------------
// MMA GEMM single-product: C = A @ B^T + bias (both fp16 single). K=1024,
// 128x128 tile, BK=32, 8 warps, 4-stage cp.async, 2 CTAs/SM.
// dyn smem: 4 stages x (A,B) x 8192 B = 65536 B.
// ---------------------------------------------------------------------------
#define G_ARR  8192
#define G1_STG 16384
__global__ __launch_bounds__(256, 2)
void gemm_mma1(const __half* __restrict__ A, const __half* __restrict__ B,
               const float* __restrict__ bias, float* __restrict__ C, int Nc)
{
    extern __shared__ char smem[];
    const uint32_t sb = smem_u32(smem);
    const int tid = threadIdx.x, lane = tid & 31, w = tid >> 5;
    const int wm = w >> 1, wn = w & 1;
    const int g = lane >> 2, t = lane & 3;
    const int n0 = blockIdx.x * 128, m0 = blockIdx.y * 128;

    float acc[2][8][4];
    #pragma unroll
    for (int i = 0; i < 2; i++)
        #pragma unroll
        for (int j = 0; j < 8; j++)
            acc[i][j][0] = acc[i][j][1] = acc[i][j][2] = acc[i][j][3] = 0.f;

    const __half* srcs[2] = {A, B};

    auto load_tile = [&](int c, int s) {
        int kt = c * 32;
        #pragma unroll
        for (int p = 0; p < 4; p++) {
            int idx = tid + p * 256;           // 0..1023
            int arr = idx >> 9;                // 0..1
            int rem = idx & 511;
            int row = rem >> 2, sg = rem & 3;
            int base_row = (arr == 0) ? m0 : n0;
            const __half* src = srcs[arr] + (size_t)(base_row + row) * 1024 + kt + sg * 8;
            cp16(sb + s * G1_STG + arr * G_ARR + row * 64 +
                 ((sg ^ ((row >> 1) & 3)) << 4), src);
        }
    };

    load_tile(0, 0); CP_COMMIT();
    load_tile(1, 1); CP_COMMIT();
    load_tile(2, 2); CP_COMMIT();

    for (int c = 0; c < 32; c++) {
        if (c < 30)      { CP_WAIT(2); }
        else if (c == 30){ CP_WAIT(1); }
        else             { CP_WAIT(0); }
        __syncthreads();
        if (c + 3 < 32) { load_tile(c + 3, (c + 3) & 3); CP_COMMIT(); }

        const uint32_t so = sb + (c & 3) * G1_STG;
        #pragma unroll
        for (int kk = 0; kk < 2; kk++) {
            uint32_t ah[2][4];
            #pragma unroll
            for (int mt = 0; mt < 2; mt++) {
                int ar = wm * 32 + mt * 16 + (lane & 15);
                int ch = 2 * kk + ((lane & 16) >> 4);
                uint32_t off = ar * 64 + (((uint32_t)(ch ^ ((ar >> 1) & 3))) << 4);
                ldsm_x4(ah[mt], so + off);
            }
            #pragma unroll
            for (int u = 0; u < 4; u++) {
                uint32_t bh[4];
                int br = wn * 64 + u * 16 + (lane & 7) + ((lane & 16) >> 1);
                int ch = 2 * kk + ((lane & 8) >> 3);
                uint32_t off = br * 64 + (((uint32_t)(ch ^ ((br >> 1) & 3))) << 4);
                ldsm_x4(bh, so + G_ARR + off);
                #pragma unroll
                for (int mt = 0; mt < 2; mt++) {
                    mma_f16(acc[mt][2 * u],     ah[mt], &bh[0]);
                    mma_f16(acc[mt][2 * u + 1], ah[mt], &bh[2]);
                }
            }
        }
    }

    #pragma unroll
    for (int mt = 0; mt < 2; mt++) {
        int r0 = m0 + wm * 32 + mt * 16 + g;
        #pragma unroll
        for (int nt = 0; nt < 8; nt++) {
            int cc = n0 + wn * 64 + nt * 8 + t * 2;
            float2 bv = *(const float2*)&bias[cc];
            float* a = acc[mt][nt];
            *(float2*)&C[(size_t)r0 * Nc + cc]       = make_float2(a[0] + bv.x, a[1] + bv.y);
            *(float2*)&C[(size_t)(r0 + 8) * Nc + cc] = make_float2(a[2] + bv.x, a[3] + bv.y);
        }
    }
}

// ---------------------------------------------------------------------------
// Flash attention v10: fixed-shift softmax; P via ex2.approx.f32 + packh2
// (the R13-proven precision path); l accumulated by an extra MMA against an
// all-ones B fragment (exact, consistent with PV's fp16 P; no shuffles, no
// scalar adds, no epilogue reduction). 128 KV rows per pipeline step, two
// 64-row half-passes. h fp16 single. 3 stages x 32768 B = 98304 B, 2 CTAs/SM.
// ---------------------------------------------------------------------------
#define A_STG 32768
#define A_VOFF 16384
#define NIT   (NT / 128)
__global__ __launch_bounds__(256, 2)
void flash_mma(const __half* __restrict__ qfg, const __half* __restrict__ kfg,
               const __half* __restrict__ vfg, const float* __restrict__ kmaxp,
               __half* __restrict__ hh)
{
    extern __shared__ char smem[];
    const uint32_t sb = smem_u32(smem);
    const int tid = threadIdx.x, lane = tid & 31, w = tid >> 5;
    const int g = lane >> 2, t = lane & 3;
    const int h = blockIdx.y, q0 = blockIdx.x * 128;
    const size_t hoff = (size_t)h * NT * DH;

    uint32_t qa[4][4];
    {
        const __half* r0 = qfg + hoff + (size_t)(q0 + w * 16 + g) * DH;
        const __half* r1 = r0 + 8 * DH;
        #pragma unroll
        for (int kk = 0; kk < 4; kk++) {
            qa[kk][0] = *(const uint32_t*)(r0 + kk * 16 + 2 * t);
            qa[kk][1] = *(const uint32_t*)(r1 + kk * 16 + 2 * t);
            qa[kk][2] = *(const uint32_t*)(r0 + kk * 16 + 8 + 2 * t);
            qa[kk][3] = *(const uint32_t*)(r1 + kk * 16 + 8 + 2 * t);
        }
    }

    // per-row softmax shift b = ||q_row|| * max||k||
    float qn0 = 0.f, qn1 = 0.f;
    #pragma unroll
    for (int kk = 0; kk < 4; kk++) {
        float2 f;
        f = __half22float2(*(__half2*)&qa[kk][0]); qn0 += f.x * f.x + f.y * f.y;
        f = __half22float2(*(__half2*)&qa[kk][2]); qn0 += f.x * f.x + f.y * f.y;
        f = __half22float2(*(__half2*)&qa[kk][1]); qn1 += f.x * f.x + f.y * f.y;
        f = __half22float2(*(__half2*)&qa[kk][3]); qn1 += f.x * f.x + f.y * f.y;
    }
    qn0 += __shfl_xor_sync(0xffffffffu, qn0, 1);
    qn0 += __shfl_xor_sync(0xffffffffu, qn0, 2);
    qn1 += __shfl_xor_sync(0xffffffffu, qn1, 1);
    qn1 += __shfl_xor_sync(0xffffffffu, qn1, 2);
    float km = kmaxp[h];
    float b0 = sqrtf(qn0) * km, b1 = sqrtf(qn1) * km;

    const __half* kfh = kfg + hoff;
    const __half* vfh = vfg + hoff;

    auto load_tile = [&](int it, int s) {
        int k0 = it * 128;
        #pragma unroll
        for (int p = 0; p < 8; p++) {
            int idx = tid + p * 256;            // 0..2047
            int arr = idx >> 10;                // 0..1
            int rem = idx & 1023;
            int row = rem >> 3, sg = rem & 7;
            const __half* src = (arr == 0 ? kfh : vfh) + (size_t)(k0 + row) * DH + sg * 8;
            cp16(sb + s * A_STG + arr * A_VOFF + row * 128 +
                 ((sg ^ (row & 7)) << 4), src);
        }
    };

    const uint32_t ones2[2] = {0x3C003C00u, 0x3C003C00u};   // fp16 1.0 x4
    float lacc[4] = {0.f, 0.f, 0.f, 0.f};                   // l via ones-MMA
    float oacc[8][4];
    #pragma unroll
    for (int u = 0; u < 8; u++)
        oacc[u][0] = oacc[u][1] = oacc[u][2] = oacc[u][3] = 0.f;

    load_tile(0, 0); CP_COMMIT();
    load_tile(1, 1); CP_COMMIT();

    for (int it = 0; it < NIT; it++) {
        if (it < NIT - 1) { CP_WAIT(1); } else { CP_WAIT(0); }
        __syncthreads();
        if (it + 2 < NIT) { load_tile(it + 2, (it + 2) % 3); CP_COMMIT(); }

        const uint32_t so = sb + (it % 3) * A_STG;

        #pragma unroll
        for (int hp = 0; hp < 2; hp++) {
            const uint32_t soh = so + hp * 8192;

            // S = Q @ K^T - b  (b folded into accumulator init)
            float s[8][4];
            #pragma unroll
            for (int j = 0; j < 8; j++) {
                s[j][0] = -b0; s[j][1] = -b0;
                s[j][2] = -b1; s[j][3] = -b1;
            }

            #pragma unroll
            for (int kk = 0; kk < 4; kk++) {
                #pragma unroll
                for (int u = 0; u < 4; u++) {
                    uint32_t bh[4];
                    int br = u * 16 + (lane & 7) + ((lane & 16) >> 1);
                    int ch = 2 * kk + ((lane & 8) >> 3);
                    uint32_t off = br * 128 + (((uint32_t)(ch ^ (br & 7))) << 4);
                    ldsm_x4(bh, soh + off);
                    mma_f16(s[2 * u],     qa[kk], &bh[0]);
                    mma_f16(s[2 * u + 1], qa[kk], &bh[2]);
                }
            }

            // P = 2^s (f32 exp, fp16 pack); l += P @ ones; O += P @ V
            #pragma unroll
            for (int kv = 0; kv < 4; kv++) {
                float e00 = ex2f(s[2 * kv][0]),     e01 = ex2f(s[2 * kv][1]);
                float e02 = ex2f(s[2 * kv][2]),     e03 = ex2f(s[2 * kv][3]);
                float e10 = ex2f(s[2 * kv + 1][0]), e11 = ex2f(s[2 * kv + 1][1]);
                float e12 = ex2f(s[2 * kv + 1][2]), e13 = ex2f(s[2 * kv + 1][3]);
                uint32_t pa[4];
                pa[0] = packh2(e00, e01);
                pa[1] = packh2(e02, e03);
                pa[2] = packh2(e10, e11);
                pa[3] = packh2(e12, e13);
                mma_f16(lacc, pa, ones2);
                #pragma unroll
                for (int u = 0; u < 4; u++) {
                    uint32_t vh4[4];
                    int vr = kv * 16 + (lane & 15);
                    int ch = 2 * u + ((lane & 16) >> 4);
                    uint32_t off = vr * 128 + (((uint32_t)(ch ^ (vr & 7))) << 4);
                    ldsm_x4_t(vh4, soh + A_VOFF + off);
                    mma_f16(oacc[2 * u],     pa, &vh4[0]);
                    mma_f16(oacc[2 * u + 1], pa, &vh4[2]);
                }
            }
        }
    }

    // l is fully replicated across quad lanes by the ones-MMA: no reduction.
    float inv0 = 1.0f / lacc[0], inv1 = 1.0f / lacc[2];
    int r0 = q0 + w * 16 + g;
    #pragma unroll
    for (int u = 0; u < 8; u++) {
        size_t o0 = (size_t)r0 * CD + h * DH + u * 8 + t * 2;
        *(uint32_t*)&hh[o0] = packh2(oacc[u][0] * inv0, oacc[u][1] * inv0);
        size_t o1 = (size_t)(r0 + 8) * CD + h * DH + u * 8 + t * 2;
        *(uint32_t*)&hh[o1] = packh2(oacc[u][2] * inv1, oacc[u][3] * inv1);
    }
}

// ---------------------------------------------------------------------------
// kernel_launch — graph-capturable, allocation-free.
// Inputs: x, Wqkv, bqkv, q_gamma, k_gamma, Wout, bout
// ---------------------------------------------------------------------------
extern "C" void kernel_launch(void* const* d_in, const int* in_sizes, int n_in,
                              void* d_out, int out_size)
{
    const float* x    = (const float*)d_in[0];
    const float* Wqkv = (const float*)d_in[1];
    const float* bqkv = (const float*)d_in[2];
    const float* qg   = (const float*)d_in[3];
    const float* kg   = (const float*)d_in[4];
    const float* Wout = (const float*)d_in[5];
    const float* bout = (const float*)d_in[6];
    float* out = (float*)d_out;

    void* p;
    cudaGetSymbolAddress(&p, g_qkv);  float*  qkv  = (float*)p;
    cudaGetSymbolAddress(&p, g_xf);   __half* xf   = (__half*)p;
    cudaGetSymbolAddress(&p, g_wq);   __half* wq   = (__half*)p;
    cudaGetSymbolAddress(&p, g_wo);   __half* wo   = (__half*)p;
    cudaGetSymbolAddress(&p, g_hh);   __half* hh   = (__half*)p;
    cudaGetSymbolAddress(&p, g_qf);   __half* qf   = (__half*)p;
    cudaGetSymbolAddress(&p, g_kf);   __half* kf   = (__half*)p;
    cudaGetSymbolAddress(&p, g_vf);   __half* vf   = (__half*)p;
    cudaGetSymbolAddress(&p, g_kmax); float*  kmax = (float*)p;

    cudaFuncSetAttribute(gemm_mma1,
                         cudaFuncAttributeMaxDynamicSharedMemorySize, 65536);
    cudaFuncSetAttribute(flash_mma,
                         cudaFuncAttributeMaxDynamicSharedMemorySize, 98304);

    // 0) merged prep + zero per-head kmax
    cudaMemsetAsync(kmax, 0, NH * sizeof(float), 0);
    prep_kernel<<<(NX4 + NWQ4 + NWO4) / 256, 256>>>(x, Wqkv, Wout, xf, wq, wo);

    // 1) qkv = x @ Wqkv^T + bqkv  (fp16 single-product, 4-stage)
    gemm_mma1<<<dim3(3 * CD / 128, NT / 128), 256, 65536>>>(
        xf, wq, bqkv, qkv, 3 * CD);

    // 2) rms norm + fp16 head-major emit + per-head max||k||
    post_kernel<<<(NT * NH * 3 * 32) / 256, 256>>>(qkv, qg, kg, qf, kf, vf, kmax);

    // 3) flash attention (fixed-shift softmax, f32 exp, ones-MMA l) -> h
    flash_mma<<<dim3(NT / 128, NH), 256, 98304>>>(qf, kf, vf, kmax, hh);

    // 4) out = h @ Wout^T + bout  (fp16 single-product, 4-stage)
    gemm_mma1<<<dim3(CD / 128, NT / 128), 256, 65536>>>(hh, wo, bout, out, CD);
}

// round 16
// speedup vs baseline: 9.1975x; 1.1182x over previous
#include <cuda_runtime.h>
#include <cuda_bf16.h>
#include <cuda_fp16.h>
#include <cstdint>
#include <math.h>

#define NT 4096
#define CD 1024
#define NH 16
#define DH 64
#define LOG2E 1.4426950408889634f

// ---------------- scratch (allocation-free rule) ----------------
__device__ __half g_xf[NT * CD];                     // x fp16 single
__device__ __half g_wq[3 * CD * CD];                 // Wqkv fp16 single
__device__ __half g_wo[CD * CD];                     // Wout fp16 single
__device__ __half g_hh[NT * CD];                     // h fp16 single
// head-major [NH][NT][DH] fp16 singles: q (pre-scaled by log2e fold), k, v
__device__ __half g_qf[NT * CD];
__device__ __half g_kf[NT * CD];
__device__ __half g_vf[NT * CD];
__device__ float  g_kmax[NH];                        // per-head max ||k||

// ---------------- helpers ----------------
__device__ __forceinline__ uint32_t smem_u32(const void* p) {
    return (uint32_t)__cvta_generic_to_shared(p);
}
__device__ __forceinline__ void ldsm_x4(uint32_t* r, uint32_t a) {
    asm volatile("ldmatrix.sync.aligned.m8n8.x4.shared.b16 {%0,%1,%2,%3}, [%4];"
                 : "=r"(r[0]), "=r"(r[1]), "=r"(r[2]), "=r"(r[3]) : "r"(a));
}
__device__ __forceinline__ void ldsm_x4_t(uint32_t* r, uint32_t a) {
    asm volatile("ldmatrix.sync.aligned.m8n8.x4.trans.shared.b16 {%0,%1,%2,%3}, [%4];"
                 : "=r"(r[0]), "=r"(r[1]), "=r"(r[2]), "=r"(r[3]) : "r"(a));
}
__device__ __forceinline__ void mma_f16(float* c, const uint32_t* a, const uint32_t* b) {
    asm volatile(
        "mma.sync.aligned.m16n8k16.row.col.f32.f16.f16.f32 "
        "{%0,%1,%2,%3}, {%4,%5,%6,%7}, {%8,%9}, {%0,%1,%2,%3};"
        : "+f"(c[0]), "+f"(c[1]), "+f"(c[2]), "+f"(c[3])
        : "r"(a[0]), "r"(a[1]), "r"(a[2]), "r"(a[3]), "r"(b[0]), "r"(b[1]));
}
__device__ __forceinline__ uint32_t packh2(float a, float b) {
    __half2 h = __floats2half2_rn(a, b);
    return *(uint32_t*)&h;
}
__device__ __forceinline__ float ex2f(float x) {
    float y;
    asm("ex2.approx.f32 %0, %1;" : "=f"(y) : "f"(x));
    return y;
}
__device__ __forceinline__ void cp16(uint32_t dst, const void* src) {
    asm volatile("cp.async.cg.shared.global [%0], [%1], 16;" :: "r"(dst), "l"(src));
}
#define CP_COMMIT() asm volatile("cp.async.commit_group;" ::: "memory")
#define CP_WAIT(n)  asm volatile("cp.async.wait_group %0;" :: "n"(n) : "memory")

// ---------------------------------------------------------------------------
// Merged prep: x, Wqkv, Wout -> fp16 single. 4 fp32 elements per thread.
// ---------------------------------------------------------------------------
#define NX4  (NT * CD / 4)
#define NWQ4 (3 * CD * CD / 4)
#define NWO4 (CD * CD / 4)
__global__ __launch_bounds__(256)
void prep_kernel(const float* __restrict__ x, const float* __restrict__ Wqkv,
                 const float* __restrict__ Wout,
                 __half* __restrict__ xf,
                 __half* __restrict__ wq, __half* __restrict__ wo)
{
    int i = blockIdx.x * blockDim.x + threadIdx.x;
    if (i < NX4) {
        float4 v = ((const float4*)x)[i];
        ((uint2*)xf)[i] = make_uint2(packh2(v.x, v.y), packh2(v.z, v.w));
    } else if (i < NX4 + NWQ4) {
        int j = i - NX4;
        float4 v = ((const float4*)Wqkv)[j];
        ((uint2*)wq)[j] = make_uint2(packh2(v.x, v.y), packh2(v.z, v.w));
    } else {
        int j = i - NX4 - NWQ4;
        float4 v = ((const float4*)Wout)[j];
        ((uint2*)wo)[j] = make_uint2(packh2(v.x, v.y), packh2(v.z, v.w));
    }
}

// ---------------------------------------------------------------------------
// QKV GEMM with FUSED epilogue: computes qkv = x @ Wqkv^T + bias, then
// per-head RMS norm on q/k (gamma + log2e / 8 folds), per-head ||k|| atomic
// max, and head-major fp16 emit of q,k,v — all from the fp32 accumulators.
// Each warp-half's 64-col span is exactly one (section, head); row norms
// reduce across the 4 quad lanes (2 shuffles), as in post_kernel.
// Mainloop identical to gemm_mma1 (Nc = 3072).
// ---------------------------------------------------------------------------
#define G_ARR  8192
#define G1_STG 16384
__global__ __launch_bounds__(256, 2)
void gemm_qkv(const __half* __restrict__ A, const __half* __restrict__ B,
              const float* __restrict__ bias,
              const float* __restrict__ qg, const float* __restrict__ kg,
              __half* __restrict__ qf, __half* __restrict__ kf,
              __half* __restrict__ vf, float* __restrict__ kmax)
{
    extern __shared__ char smem[];
    const uint32_t sb = smem_u32(smem);
    const int tid = threadIdx.x, lane = tid & 31, w = tid >> 5;
    const int wm = w >> 1, wn = w & 1;
    const int g = lane >> 2, t = lane & 3;
    const int n0 = blockIdx.x * 128, m0 = blockIdx.y * 128;

    float acc[2][8][4];
    #pragma unroll
    for (int i = 0; i < 2; i++)
        #pragma unroll
        for (int j = 0; j < 8; j++)
            acc[i][j][0] = acc[i][j][1] = acc[i][j][2] = acc[i][j][3] = 0.f;

    const __half* srcs[2] = {A, B};

    auto load_tile = [&](int c, int s) {
        int kt = c * 32;
        #pragma unroll
        for (int p = 0; p < 4; p++) {
            int idx = tid + p * 256;
            int arr = idx >> 9;
            int rem = idx & 511;
            int row = rem >> 2, sg = rem & 3;
            int base_row = (arr == 0) ? m0 : n0;
            const __half* src = srcs[arr] + (size_t)(base_row + row) * 1024 + kt + sg * 8;
            cp16(sb + s * G1_STG + arr * G_ARR + row * 64 +
                 ((sg ^ ((row >> 1) & 3)) << 4), src);
        }
    };

    load_tile(0, 0); CP_COMMIT();
    load_tile(1, 1); CP_COMMIT();
    load_tile(2, 2); CP_COMMIT();

    for (int c = 0; c < 32; c++) {
        if (c < 30)      { CP_WAIT(2); }
        else if (c == 30){ CP_WAIT(1); }
        else             { CP_WAIT(0); }
        __syncthreads();
        if (c + 3 < 32) { load_tile(c + 3, (c + 3) & 3); CP_COMMIT(); }

        const uint32_t so = sb + (c & 3) * G1_STG;
        #pragma unroll
        for (int kk = 0; kk < 2; kk++) {
            uint32_t ah[2][4];
            #pragma unroll
            for (int mt = 0; mt < 2; mt++) {
                int ar = wm * 32 + mt * 16 + (lane & 15);
                int ch = 2 * kk + ((lane & 16) >> 4);
                uint32_t off = ar * 64 + (((uint32_t)(ch ^ ((ar >> 1) & 3))) << 4);
                ldsm_x4(ah[mt], so + off);
            }
            #pragma unroll
            for (int u = 0; u < 4; u++) {
                uint32_t bh[4];
                int br = wn * 64 + u * 16 + (lane & 7) + ((lane & 16) >> 1);
                int ch = 2 * kk + ((lane & 8) >> 3);
                uint32_t off = br * 64 + (((uint32_t)(ch ^ ((br >> 1) & 3))) << 4);
                ldsm_x4(bh, so + G_ARR + off);
                #pragma unroll
                for (int mt = 0; mt < 2; mt++) {
                    mma_f16(acc[mt][2 * u],     ah[mt], &bh[0]);
                    mma_f16(acc[mt][2 * u + 1], ah[mt], &bh[2]);
                }
            }
        }
    }

    // ---------------- fused epilogue ----------------
    const int colbase = n0 + wn * 64;          // 64-aligned: one (section, head)
    const int sec  = colbase >> 10;            // 0=q 1=k 2=v
    const int head = (colbase & 1023) >> 6;
    __half* dst = (sec == 0) ? qf : (sec == 1) ? kf : vf;

    // bias add (in place)
    #pragma unroll
    for (int nt = 0; nt < 8; nt++) {
        float2 bv = *(const float2*)&bias[colbase + nt * 8 + t * 2];
        #pragma unroll
        for (int mt = 0; mt < 2; mt++) {
            acc[mt][nt][0] += bv.x; acc[mt][nt][1] += bv.y;
            acc[mt][nt][2] += bv.x; acc[mt][nt][3] += bv.y;
        }
    }

    // gamma for this head (q/k only)
    float gv[16];
    if (sec < 2) {
        const float* gam = (sec == 0) ? qg : kg;
        #pragma unroll
        for (int nt = 0; nt < 8; nt++) {
            float2 gg = *(const float2*)&gam[head * DH + nt * 8 + t * 2];
            gv[2 * nt] = gg.x; gv[2 * nt + 1] = gg.y;
        }
    }

    #pragma unroll
    for (int mt = 0; mt < 2; mt++) {
        #pragma unroll
        for (int which = 0; which < 2; which++) {
            int r = m0 + wm * 32 + mt * 16 + g + which * 8;
            float rv[16];
            #pragma unroll
            for (int nt = 0; nt < 8; nt++) {
                rv[2 * nt]     = acc[mt][nt][2 * which];
                rv[2 * nt + 1] = acc[mt][nt][2 * which + 1];
            }
            if (sec < 2) {
                float ss = 0.f;
                #pragma unroll
                for (int i = 0; i < 16; i++) ss += rv[i] * rv[i];
                ss += __shfl_xor_sync(0xffffffffu, ss, 1);
                ss += __shfl_xor_sync(0xffffffffu, ss, 2);
                float inv = 1.0f / fmaxf(sqrtf(ss), 1e-12f);
                float sc = (sec == 0) ? (inv * LOG2E) : (8.0f * inv);
                #pragma unroll
                for (int i = 0; i < 16; i++) rv[i] *= sc * gv[i];
                if (sec == 1) {
                    float s2 = 0.f;
                    #pragma unroll
                    for (int i = 0; i < 16; i++) s2 += rv[i] * rv[i];
                    s2 += __shfl_xor_sync(0xffffffffu, s2, 1);
                    s2 += __shfl_xor_sync(0xffffffffu, s2, 2);
                    if (t == 0)
                        atomicMax((int*)&kmax[head], __float_as_int(sqrtf(s2)));
                }
            }
            size_t off = (size_t)head * NT * DH + (size_t)r * DH;
            #pragma unroll
            for (int nt = 0; nt < 8; nt++)
                *(uint32_t*)&dst[off + nt * 8 + t * 2] =
                    packh2(rv[2 * nt], rv[2 * nt + 1]);
        }
    }
}

// ---------------------------------------------------------------------------
// MMA GEMM single-product (out-proj): C = A @ B^T + bias. Unchanged.
// ---------------------------------------------------------------------------
__global__ __launch_bounds__(256, 2)
void gemm_mma1(const __half* __restrict__ A, const __half* __restrict__ B,
               const float* __restrict__ bias, float* __restrict__ C, int Nc)
{
    extern __shared__ char smem[];
    const uint32_t sb = smem_u32(smem);
    const int tid = threadIdx.x, lane = tid & 31, w = tid >> 5;
    const int wm = w >> 1, wn = w & 1;
    const int g = lane >> 2, t = lane & 3;
    const int n0 = blockIdx.x * 128, m0 = blockIdx.y * 128;

    float acc[2][8][4];
    #pragma unroll
    for (int i = 0; i < 2; i++)
        #pragma unroll
        for (int j = 0; j < 8; j++)
            acc[i][j][0] = acc[i][j][1] = acc[i][j][2] = acc[i][j][3] = 0.f;

    const __half* srcs[2] = {A, B};

    auto load_tile = [&](int c, int s) {
        int kt = c * 32;
        #pragma unroll
        for (int p = 0; p < 4; p++) {
            int idx = tid + p * 256;
            int arr = idx >> 9;
            int rem = idx & 511;
            int row = rem >> 2, sg = rem & 3;
            int base_row = (arr == 0) ? m0 : n0;
            const __half* src = srcs[arr] + (size_t)(base_row + row) * 1024 + kt + sg * 8;
            cp16(sb + s * G1_STG + arr * G_ARR + row * 64 +
                 ((sg ^ ((row >> 1) & 3)) << 4), src);
        }
    };

    load_tile(0, 0); CP_COMMIT();
    load_tile(1, 1); CP_COMMIT();
    load_tile(2, 2); CP_COMMIT();

    for (int c = 0; c < 32; c++) {
        if (c < 30)      { CP_WAIT(2); }
        else if (c == 30){ CP_WAIT(1); }
        else             { CP_WAIT(0); }
        __syncthreads();
        if (c + 3 < 32) { load_tile(c + 3, (c + 3) & 3); CP_COMMIT(); }

        const uint32_t so = sb + (c & 3) * G1_STG;
        #pragma unroll
        for (int kk = 0; kk < 2; kk++) {
            uint32_t ah[2][4];
            #pragma unroll
            for (int mt = 0; mt < 2; mt++) {
                int ar = wm * 32 + mt * 16 + (lane & 15);
                int ch = 2 * kk + ((lane & 16) >> 4);
                uint32_t off = ar * 64 + (((uint32_t)(ch ^ ((ar >> 1) & 3))) << 4);
                ldsm_x4(ah[mt], so + off);
            }
            #pragma unroll
            for (int u = 0; u < 4; u++) {
                uint32_t bh[4];
                int br = wn * 64 + u * 16 + (lane & 7) + ((lane & 16) >> 1);
                int ch = 2 * kk + ((lane & 8) >> 3);
                uint32_t off = br * 64 + (((uint32_t)(ch ^ ((br >> 1) & 3))) << 4);
                ldsm_x4(bh, so + G_ARR + off);
                #pragma unroll
                for (int mt = 0; mt < 2; mt++) {
                    mma_f16(acc[mt][2 * u],     ah[mt], &bh[0]);
                    mma_f16(acc[mt][2 * u + 1], ah[mt], &bh[2]);
                }
            }
        }
    }

    #pragma unroll
    for (int mt = 0; mt < 2; mt++) {
        int r0 = m0 + wm * 32 + mt * 16 + g;
        #pragma unroll
        for (int nt = 0; nt < 8; nt++) {
            int cc = n0 + wn * 64 + nt * 8 + t * 2;
            float2 bv = *(const float2*)&bias[cc];
            float* a = acc[mt][nt];
            *(float2*)&C[(size_t)r0 * Nc + cc]       = make_float2(a[0] + bv.x, a[1] + bv.y);
            *(float2*)&C[(size_t)(r0 + 8) * Nc + cc] = make_float2(a[2] + bv.x, a[3] + bv.y);
        }
    }
}

// ---------------------------------------------------------------------------
// Flash attention v10 (unchanged from R15): fixed-shift softmax; f32 exp +
// fp16 pack; l via ones-MMA. 128 KV rows per step, two 64-row half-passes.
// 3 stages x 32768 B = 98304 B, 2 CTAs/SM.
// ---------------------------------------------------------------------------
#define A_STG 32768
#define A_VOFF 16384
#define NIT   (NT / 128)
__global__ __launch_bounds__(256, 2)
void flash_mma(const __half* __restrict__ qfg, const __half* __restrict__ kfg,
               const __half* __restrict__ vfg, const float* __restrict__ kmaxp,
               __half* __restrict__ hh)
{
    extern __shared__ char smem[];
    const uint32_t sb = smem_u32(smem);
    const int tid = threadIdx.x, lane = tid & 31, w = tid >> 5;
    const int g = lane >> 2, t = lane & 3;
    const int h = blockIdx.y, q0 = blockIdx.x * 128;
    const size_t hoff = (size_t)h * NT * DH;

    uint32_t qa[4][4];
    {
        const __half* r0 = qfg + hoff + (size_t)(q0 + w * 16 + g) * DH;
        const __half* r1 = r0 + 8 * DH;
        #pragma unroll
        for (int kk = 0; kk < 4; kk++) {
            qa[kk][0] = *(const uint32_t*)(r0 + kk * 16 + 2 * t);
            qa[kk][1] = *(const uint32_t*)(r1 + kk * 16 + 2 * t);
            qa[kk][2] = *(const uint32_t*)(r0 + kk * 16 + 8 + 2 * t);
            qa[kk][3] = *(const uint32_t*)(r1 + kk * 16 + 8 + 2 * t);
        }
    }

    // per-row softmax shift b = ||q_row|| * max||k||
    float qn0 = 0.f, qn1 = 0.f;
    #pragma unroll
    for (int kk = 0; kk < 4; kk++) {
        float2 f;
        f = __half22float2(*(__half2*)&qa[kk][0]); qn0 += f.x * f.x + f.y * f.y;
        f = __half22float2(*(__half2*)&qa[kk][2]); qn0 += f.x * f.x + f.y * f.y;
        f = __half22float2(*(__half2*)&qa[kk][1]); qn1 += f.x * f.x + f.y * f.y;
        f = __half22float2(*(__half2*)&qa[kk][3]); qn1 += f.x * f.x + f.y * f.y;
    }
    qn0 += __shfl_xor_sync(0xffffffffu, qn0, 1);
    qn0 += __shfl_xor_sync(0xffffffffu, qn0, 2);
    qn1 += __shfl_xor_sync(0xffffffffu, qn1, 1);
    qn1 += __shfl_xor_sync(0xffffffffu, qn1, 2);
    float km = kmaxp[h];
    float b0 = sqrtf(qn0) * km, b1 = sqrtf(qn1) * km;

    const __half* kfh = kfg + hoff;
    const __half* vfh = vfg + hoff;

    auto load_tile = [&](int it, int s) {
        int k0 = it * 128;
        #pragma unroll
        for (int p = 0; p < 8; p++) {
            int idx = tid + p * 256;
            int arr = idx >> 10;
            int rem = idx & 1023;
            int row = rem >> 3, sg = rem & 7;
            const __half* src = (arr == 0 ? kfh : vfh) + (size_t)(k0 + row) * DH + sg * 8;
            cp16(sb + s * A_STG + arr * A_VOFF + row * 128 +
                 ((sg ^ (row & 7)) << 4), src);
        }
    };

    const uint32_t ones2[2] = {0x3C003C00u, 0x3C003C00u};
    float lacc[4] = {0.f, 0.f, 0.f, 0.f};
    float oacc[8][4];
    #pragma unroll
    for (int u = 0; u < 8; u++)
        oacc[u][0] = oacc[u][1] = oacc[u][2] = oacc[u][3] = 0.f;

    load_tile(0, 0); CP_COMMIT();
    load_tile(1, 1); CP_COMMIT();

    for (int it = 0; it < NIT; it++) {
        if (it < NIT - 1) { CP_WAIT(1); } else { CP_WAIT(0); }
        __syncthreads();
        if (it + 2 < NIT) { load_tile(it + 2, (it + 2) % 3); CP_COMMIT(); }

        const uint32_t so = sb + (it % 3) * A_STG;

        #pragma unroll
        for (int hp = 0; hp < 2; hp++) {
            const uint32_t soh = so + hp * 8192;

            float s[8][4];
            #pragma unroll
            for (int j = 0; j < 8; j++) {
                s[j][0] = -b0; s[j][1] = -b0;
                s[j][2] = -b1; s[j][3] = -b1;
            }

            #pragma unroll
            for (int kk = 0; kk < 4; kk++) {
                #pragma unroll
                for (int u = 0; u < 4; u++) {
                    uint32_t bh[4];
                    int br = u * 16 + (lane & 7) + ((lane & 16) >> 1);
                    int ch = 2 * kk + ((lane & 8) >> 3);
                    uint32_t off = br * 128 + (((uint32_t)(ch ^ (br & 7))) << 4);
                    ldsm_x4(bh, soh + off);
                    mma_f16(s[2 * u],     qa[kk], &bh[0]);
                    mma_f16(s[2 * u + 1], qa[kk], &bh[2]);
                }
            }

            #pragma unroll
            for (int kv = 0; kv < 4; kv++) {
                float e00 = ex2f(s[2 * kv][0]),     e01 = ex2f(s[2 * kv][1]);
                float e02 = ex2f(s[2 * kv][2]),     e03 = ex2f(s[2 * kv][3]);
                float e10 = ex2f(s[2 * kv + 1][0]), e11 = ex2f(s[2 * kv + 1][1]);
                float e12 = ex2f(s[2 * kv + 1][2]), e13 = ex2f(s[2 * kv + 1][3]);
                uint32_t pa[4];
                pa[0] = packh2(e00, e01);
                pa[1] = packh2(e02, e03);
                pa[2] = packh2(e10, e11);
                pa[3] = packh2(e12, e13);
                mma_f16(lacc, pa, ones2);
                #pragma unroll
                for (int u = 0; u < 4; u++) {
                    uint32_t vh4[4];
                    int vr = kv * 16 + (lane & 15);
                    int ch = 2 * u + ((lane & 16) >> 4);
                    uint32_t off = vr * 128 + (((uint32_t)(ch ^ (vr & 7))) << 4);
                    ldsm_x4_t(vh4, soh + A_VOFF + off);
                    mma_f16(oacc[2 * u],     pa, &vh4[0]);
                    mma_f16(oacc[2 * u + 1], pa, &vh4[2]);
                }
            }
        }
    }

    float inv0 = 1.0f / lacc[0], inv1 = 1.0f / lacc[2];
    int r0 = q0 + w * 16 + g;
    #pragma unroll
    for (int u = 0; u < 8; u++) {
        size_t o0 = (size_t)r0 * CD + h * DH + u * 8 + t * 2;
        *(uint32_t*)&hh[o0] = packh2(oacc[u][0] * inv0, oacc[u][1] * inv0);
        size_t o1 = (size_t)(r0 + 8) * CD + h * DH + u * 8 + t * 2;
        *(uint32_t*)&hh[o1] = packh2(oacc[u][2] * inv1, oacc[u][3] * inv1);
    }
}

// ---------------------------------------------------------------------------
// kernel_launch — graph-capturable, allocation-free.
// Inputs: x, Wqkv, bqkv, q_gamma, k_gamma, Wout, bout
// ---------------------------------------------------------------------------
extern "C" void kernel_launch(void* const* d_in, const int* in_sizes, int n_in,
                              void* d_out, int out_size)
{
    const float* x    = (const float*)d_in[0];
    const float* Wqkv = (const float*)d_in[1];
    const float* bqkv = (const float*)d_in[2];
    const float* qg   = (const float*)d_in[3];
    const float* kg   = (const float*)d_in[4];
    const float* Wout = (const float*)d_in[5];
    const float* bout = (const float*)d_in[6];
    float* out = (float*)d_out;

    void* p;
    cudaGetSymbolAddress(&p, g_xf);   __half* xf   = (__half*)p;
    cudaGetSymbolAddress(&p, g_wq);   __half* wq   = (__half*)p;
    cudaGetSymbolAddress(&p, g_wo);   __half* wo   = (__half*)p;
    cudaGetSymbolAddress(&p, g_hh);   __half* hh   = (__half*)p;
    cudaGetSymbolAddress(&p, g_qf);   __half* qf   = (__half*)p;
    cudaGetSymbolAddress(&p, g_kf);   __half* kf   = (__half*)p;
    cudaGetSymbolAddress(&p, g_vf);   __half* vf   = (__half*)p;
    cudaGetSymbolAddress(&p, g_kmax); float*  kmax = (float*)p;

    cudaFuncSetAttribute(gemm_qkv,
                         cudaFuncAttributeMaxDynamicSharedMemorySize, 65536);
    cudaFuncSetAttribute(gemm_mma1,
                         cudaFuncAttributeMaxDynamicSharedMemorySize, 65536);
    cudaFuncSetAttribute(flash_mma,
                         cudaFuncAttributeMaxDynamicSharedMemorySize, 98304);

    // 0) merged prep + zero per-head kmax
    cudaMemsetAsync(kmax, 0, NH * sizeof(float), 0);
    prep_kernel<<<(NX4 + NWQ4 + NWO4) / 256, 256>>>(x, Wqkv, Wout, xf, wq, wo);

    // 1) fused: qkv GEMM + rms norm + folds + head-major fp16 emit + kmax
    gemm_qkv<<<dim3(3 * CD / 128, NT / 128), 256, 65536>>>(
        xf, wq, bqkv, qg, kg, qf, kf, vf, kmax);

    // 2) flash attention (fixed-shift softmax, f32 exp, ones-MMA l) -> h
    flash_mma<<<dim3(NT / 128, NH), 256, 98304>>>(qf, kf, vf, kmax, hh);

    // 3) out = h @ Wout^T + bout
    gemm_mma1<<<dim3(CD / 128, NT / 128), 256, 65536>>>(hh, wo, bout, out, CD);
}